// round 1
// baseline (speedup 1.0000x reference)
#include <cuda_runtime.h>

#define R_TOT 4096
#define DMODEL 1024
#define N_QKV 3072
#define SEQ 2048
#define NHEAD 16
#define HDIM 64

// Scratch (device globals: allocation-guard safe)
__device__ float g_xn[R_TOT * DMODEL];
__device__ float g_qkv[(size_t)R_TOT * N_QKV];
__device__ float g_u[R_TOT * DMODEL];
__device__ float g_ctx[R_TOT * DMODEL];

// ---------------------------------------------------------------------------
// LayerNorm: one block per row (4096 rows), 256 threads, float4 per thread.
// ---------------------------------------------------------------------------
__global__ __launch_bounds__(256) void ln_kernel(
    const float* __restrict__ x, const float* __restrict__ gamma,
    const float* __restrict__ beta, float* __restrict__ xn)
{
    int row = blockIdx.x;
    int t = threadIdx.x;
    const float4* xr = (const float4*)(x + (size_t)row * DMODEL);
    float4 v = xr[t];
    float s  = v.x + v.y + v.z + v.w;
    float sq = v.x*v.x + v.y*v.y + v.z*v.z + v.w*v.w;
#pragma unroll
    for (int o = 16; o; o >>= 1) {
        s  += __shfl_xor_sync(0xffffffffu, s,  o);
        sq += __shfl_xor_sync(0xffffffffu, sq, o);
    }
    __shared__ float ss[8], sqq[8];
    int w = t >> 5, l = t & 31;
    if (l == 0) { ss[w] = s; sqq[w] = sq; }
    __syncthreads();
    if (w == 0) {
        s  = (l < 8) ? ss[l]  : 0.f;
        sq = (l < 8) ? sqq[l] : 0.f;
#pragma unroll
        for (int o = 4; o; o >>= 1) {
            s  += __shfl_xor_sync(0xffffffffu, s,  o);
            sq += __shfl_xor_sync(0xffffffffu, sq, o);
        }
        if (l == 0) { ss[0] = s; sqq[0] = sq; }
    }
    __syncthreads();
    float mean = ss[0] * (1.f / DMODEL);
    float var  = sqq[0] * (1.f / DMODEL) - mean * mean;
    float rstd = rsqrtf(var + 1e-5f);
    float4 g  = ((const float4*)gamma)[t];
    float4 bb = ((const float4*)beta)[t];
    float4 o;
    o.x = (v.x - mean) * rstd * g.x + bb.x;
    o.y = (v.y - mean) * rstd * g.y + bb.y;
    o.z = (v.z - mean) * rstd * g.z + bb.z;
    o.w = (v.w - mean) * rstd * g.w + bb.w;
    ((float4*)(xn + (size_t)row * DMODEL))[t] = o;
}

// ---------------------------------------------------------------------------
// SGEMM: C[M,N] = act(A @ B + bias) (+ resid).  128x128 tile, BK=8, 8x8/thread.
// MODE 0: plain+bias  MODE 1: bias+SiLU  MODE 2: A=A*A2 elementwise, +bias+resid
// ---------------------------------------------------------------------------
template<int MODE>
__global__ __launch_bounds__(256) void sgemm_kernel(
    const float* __restrict__ A, const float* __restrict__ A2,
    const float* __restrict__ Bm, const float* __restrict__ bias,
    const float* __restrict__ resid, float* __restrict__ C,
    int M, int N, int K)
{
    __shared__ float As[8][128];   // transposed: As[k][m]
    __shared__ float Bs[8][128];   // Bs[k][n]

    int tid = threadIdx.x;
    int tx = tid & 15, ty = tid >> 4;
    int mBase = blockIdx.y * 128, nBase = blockIdx.x * 128;

    float acc[8][8];
#pragma unroll
    for (int i = 0; i < 8; i++)
#pragma unroll
        for (int j = 0; j < 8; j++) acc[i][j] = 0.f;

    int arow = tid >> 1, acol = (tid & 1) * 4;
    int brow = tid >> 5, bcol = (tid & 31) * 4;
    const float* Aptr  = A  + (size_t)(mBase + arow) * K + acol;
    const float* A2ptr = (MODE == 2) ? (A2 + (size_t)(mBase + arow) * K + acol) : A;
    const float* Bptr  = Bm + (size_t)brow * N + nBase + bcol;

    for (int kt = 0; kt < K; kt += 8) {
        float4 av = *(const float4*)(Aptr + kt);
        if (MODE == 2) {
            float4 a2 = *(const float4*)(A2ptr + kt);
            av.x *= a2.x; av.y *= a2.y; av.z *= a2.z; av.w *= a2.w;
        }
        float4 bv = *(const float4*)(Bptr + (size_t)kt * N);
        __syncthreads();
        As[acol + 0][arow] = av.x;
        As[acol + 1][arow] = av.y;
        As[acol + 2][arow] = av.z;
        As[acol + 3][arow] = av.w;
        *(float4*)&Bs[brow][bcol] = bv;
        __syncthreads();
#pragma unroll
        for (int k = 0; k < 8; k++) {
            float4 a0 = *(float4*)&As[k][ty * 4];
            float4 a1 = *(float4*)&As[k][ty * 4 + 64];
            float4 b0 = *(float4*)&Bs[k][tx * 4];
            float4 b1 = *(float4*)&Bs[k][tx * 4 + 64];
            float a[8] = {a0.x, a0.y, a0.z, a0.w, a1.x, a1.y, a1.z, a1.w};
            float b[8] = {b0.x, b0.y, b0.z, b0.w, b1.x, b1.y, b1.z, b1.w};
#pragma unroll
            for (int i = 0; i < 8; i++)
#pragma unroll
                for (int j = 0; j < 8; j++) acc[i][j] += a[i] * b[j];
        }
    }

#pragma unroll
    for (int ih = 0; ih < 2; ih++)
#pragma unroll
        for (int jh = 0; jh < 2; jh++) {
            int cb = nBase + jh * 64 + tx * 4;
            float4 bs4 = *(const float4*)(bias + cb);
#pragma unroll
            for (int i = 0; i < 4; i++) {
                int r = mBase + ih * 64 + ty * 4 + i;
                float4 v;
                v.x = acc[ih * 4 + i][jh * 4 + 0] + bs4.x;
                v.y = acc[ih * 4 + i][jh * 4 + 1] + bs4.y;
                v.z = acc[ih * 4 + i][jh * 4 + 2] + bs4.z;
                v.w = acc[ih * 4 + i][jh * 4 + 3] + bs4.w;
                if (MODE == 1) {
                    v.x = v.x / (1.f + __expf(-v.x));
                    v.y = v.y / (1.f + __expf(-v.y));
                    v.z = v.z / (1.f + __expf(-v.z));
                    v.w = v.w / (1.f + __expf(-v.w));
                }
                if (MODE == 2) {
                    float4 rv = *(const float4*)(resid + (size_t)r * N + cb);
                    v.x += rv.x; v.y += rv.y; v.z += rv.z; v.w += rv.w;
                }
                *(float4*)(C + (size_t)r * N + cb) = v;
            }
        }
}

// ---------------------------------------------------------------------------
// Fused causal sigmoid attention. 64 q-rows per block, loop over 64-key tiles.
// ctx[b,s,h*64+d] = sum_{k<=s} sigmoid(q.k/8 + bias_h) * v[k,d]
// ---------------------------------------------------------------------------
__global__ __launch_bounds__(256) void attn_kernel(
    const float* __restrict__ qkv, const float* __restrict__ rpb,
    float* __restrict__ ctx)
{
    __shared__ float Qt[HDIM * 64];   // [kk][m]
    __shared__ float KtP[64 * 64];    // Kt[kk][n], then reused as Ps[m][n]
    __shared__ float Vs[64 * 64];     // [n][d]

    int qt = 31 - blockIdx.x;         // big tiles first (load balance)
    int bh = blockIdx.y;
    int b = bh >> 4, h = bh & 15;
    float pbias = rpb[h];
    int tid = threadIdx.x;
    int tx = tid & 15, ty = tid >> 4;

    const float* qbase = qkv + (size_t)(b * SEQ) * N_QKV + h * HDIM;
    const float* kbase = qbase + DMODEL;
    const float* vbase = qbase + 2 * DMODEL;

    // Load Q tile transposed (Qt[kk][m])
    {
        int m  = tid >> 2;
        int c0 = (tid & 3) * 16;
        const float* qr = qbase + (size_t)(qt * 64 + m) * N_QKV + c0;
#pragma unroll
        for (int cc = 0; cc < 16; cc += 4) {
            float4 v = *(const float4*)(qr + cc);
            Qt[(c0 + cc + 0) * 64 + m] = v.x;
            Qt[(c0 + cc + 1) * 64 + m] = v.y;
            Qt[(c0 + cc + 2) * 64 + m] = v.z;
            Qt[(c0 + cc + 3) * 64 + m] = v.w;
        }
    }

    float ctxr[4][4];
#pragma unroll
    for (int i = 0; i < 4; i++)
#pragma unroll
        for (int j = 0; j < 4; j++) ctxr[i][j] = 0.f;

    const float scale = 0.125f;   // HD^-0.5 = 1/8

    for (int kt = 0; kt <= qt; kt++) {
        __syncthreads();
        // Load K tile transposed, V tile natural
        {
            int n  = tid >> 2;
            int c0 = (tid & 3) * 16;
            const float* kr = kbase + (size_t)(kt * 64 + n) * N_QKV + c0;
            const float* vr = vbase + (size_t)(kt * 64 + n) * N_QKV + c0;
#pragma unroll
            for (int cc = 0; cc < 16; cc += 4) {
                float4 kv = *(const float4*)(kr + cc);
                KtP[(c0 + cc + 0) * 64 + n] = kv.x;
                KtP[(c0 + cc + 1) * 64 + n] = kv.y;
                KtP[(c0 + cc + 2) * 64 + n] = kv.z;
                KtP[(c0 + cc + 3) * 64 + n] = kv.w;
                *(float4*)&Vs[n * 64 + c0 + cc] = *(const float4*)(vr + cc);
            }
        }
        __syncthreads();

        // Stage A: scores s[i][j] = sum_kk Q[m][kk] * K[n][kk]
        float s[4][4];
#pragma unroll
        for (int i = 0; i < 4; i++)
#pragma unroll
            for (int j = 0; j < 4; j++) s[i][j] = 0.f;
#pragma unroll 16
        for (int kk = 0; kk < 64; kk++) {
            float4 a  = *(float4*)&Qt[kk * 64 + ty * 4];
            float4 bq = *(float4*)&KtP[kk * 64 + tx * 4];
            float av[4] = {a.x, a.y, a.z, a.w};
            float bv[4] = {bq.x, bq.y, bq.z, bq.w};
#pragma unroll
            for (int i = 0; i < 4; i++)
#pragma unroll
                for (int j = 0; j < 4; j++) s[i][j] += av[i] * bv[j];
        }
        __syncthreads();

        // Sigmoid + causal mask on diagonal tile; write Ps[m][n]
        bool diag = (kt == qt);
#pragma unroll
        for (int i = 0; i < 4; i++) {
            int m = ty * 4 + i;
            float pv[4];
#pragma unroll
            for (int j = 0; j < 4; j++) {
                int n = tx * 4 + j;
                float sc = s[i][j] * scale + pbias;
                float pr = 1.f / (1.f + __expf(-sc));
                if (diag && n > m) pr = 0.f;
                pv[j] = pr;
            }
            float4 p = {pv[0], pv[1], pv[2], pv[3]};
            *(float4*)&KtP[m * 64 + tx * 4] = p;
        }
        __syncthreads();

        // Stage B: ctx[i][j] += sum_n Ps[m][n] * Vs[n][d]
#pragma unroll 16
        for (int n = 0; n < 64; n++) {
            float4 vv = *(float4*)&Vs[n * 64 + tx * 4];
            float bv[4] = {vv.x, vv.y, vv.z, vv.w};
#pragma unroll
            for (int i = 0; i < 4; i++) {
                float pa = KtP[(ty * 4 + i) * 64 + n];
#pragma unroll
                for (int j = 0; j < 4; j++) ctxr[i][j] += pa * bv[j];
            }
        }
    }

    // Write ctx in [b, s, h*64+d] layout (ready for the output GEMM)
#pragma unroll
    for (int i = 0; i < 4; i++) {
        int srow = qt * 64 + ty * 4 + i;
        float4 v = {ctxr[i][0], ctxr[i][1], ctxr[i][2], ctxr[i][3]};
        *(float4*)(ctx + (size_t)(b * SEQ + srow) * DMODEL + h * HDIM + tx * 4) = v;
    }
}

// ---------------------------------------------------------------------------
extern "C" void kernel_launch(void* const* d_in, const int* in_sizes, int n_in,
                              void* d_out, int out_size)
{
    const float* x       = (const float*)d_in[0];
    // d_in[1] = attention_mask (causal tril) — applied analytically, unused
    const float* ln_g    = (const float*)d_in[2];
    const float* ln_b    = (const float*)d_in[3];
    const float* w_qkv   = (const float*)d_in[4];
    const float* b_qkv   = (const float*)d_in[5];
    const float* w_gate  = (const float*)d_in[6];
    const float* b_gate  = (const float*)d_in[7];
    const float* w_out   = (const float*)d_in[8];
    const float* b_out   = (const float*)d_in[9];
    const float* rpb     = (const float*)d_in[10];
    float* out = (float*)d_out;

    float *xn, *qkv, *u, *ctx;
    cudaGetSymbolAddress((void**)&xn,  g_xn);
    cudaGetSymbolAddress((void**)&qkv, g_qkv);
    cudaGetSymbolAddress((void**)&u,   g_u);
    cudaGetSymbolAddress((void**)&ctx, g_ctx);

    ln_kernel<<<R_TOT, 256>>>(x, ln_g, ln_b, xn);

    sgemm_kernel<0><<<dim3(N_QKV / 128, R_TOT / 128), 256>>>(
        xn, nullptr, w_qkv, b_qkv, nullptr, qkv, R_TOT, N_QKV, DMODEL);

    sgemm_kernel<1><<<dim3(DMODEL / 128, R_TOT / 128), 256>>>(
        xn, nullptr, w_gate, b_gate, nullptr, u, R_TOT, DMODEL, DMODEL);

    attn_kernel<<<dim3(SEQ / 64, 2 * NHEAD), 256>>>(qkv, rpb, ctx);

    sgemm_kernel<2><<<dim3(DMODEL / 128, R_TOT / 128), 256>>>(
        ctx, u, w_out, b_out, x, out, R_TOT, DMODEL, DMODEL);
}

// round 2
// speedup vs baseline: 1.2295x; 1.2295x over previous
#include <cuda_runtime.h>
#include <cstdint>

#define R_TOT 4096
#define DMODEL 1024
#define N_QKV 3072
#define SEQ 2048
#define NHEAD 16

// Scratch (device globals: allocation-guard safe)
__device__ float g_xn[R_TOT * DMODEL];
__device__ float g_qkv[(size_t)R_TOT * N_QKV];
__device__ float g_u[R_TOT * DMODEL];
__device__ float g_ctx[R_TOT * DMODEL];

// ---------------------------------------------------------------------------
// tf32 helpers: 3xTF32 split for near-fp32 accuracy on tensor cores
// ---------------------------------------------------------------------------
__device__ __forceinline__ uint32_t f2tf32(float x) {
    uint32_t r; asm("cvt.rna.tf32.f32 %0, %1;" : "=r"(r) : "f"(x)); return r;
}
__device__ __forceinline__ void tf32_split(float x, uint32_t& hi, uint32_t& lo) {
    hi = f2tf32(x);
    lo = f2tf32(x - __uint_as_float(hi));
}
__device__ __forceinline__ void mma8(float d[4], const uint32_t a[4], const uint32_t b[2]) {
    asm volatile("mma.sync.aligned.m16n8k8.row.col.f32.tf32.tf32.f32 "
        "{%0,%1,%2,%3},{%4,%5,%6,%7},{%8,%9},{%0,%1,%2,%3};"
        : "+f"(d[0]), "+f"(d[1]), "+f"(d[2]), "+f"(d[3])
        : "r"(a[0]), "r"(a[1]), "r"(a[2]), "r"(a[3]), "r"(b[0]), "r"(b[1]));
}

// ---------------------------------------------------------------------------
// LayerNorm: one block per row, 256 threads, float4 per thread.
// ---------------------------------------------------------------------------
__global__ __launch_bounds__(256) void ln_kernel(
    const float* __restrict__ x, const float* __restrict__ gamma,
    const float* __restrict__ beta, float* __restrict__ xn)
{
    int row = blockIdx.x;
    int t = threadIdx.x;
    const float4* xr = (const float4*)(x + (size_t)row * DMODEL);
    float4 v = xr[t];
    float s  = v.x + v.y + v.z + v.w;
    float sq = v.x*v.x + v.y*v.y + v.z*v.z + v.w*v.w;
#pragma unroll
    for (int o = 16; o; o >>= 1) {
        s  += __shfl_xor_sync(0xffffffffu, s,  o);
        sq += __shfl_xor_sync(0xffffffffu, sq, o);
    }
    __shared__ float ss[8], sqq[8];
    int w = t >> 5, l = t & 31;
    if (l == 0) { ss[w] = s; sqq[w] = sq; }
    __syncthreads();
    if (w == 0) {
        s  = (l < 8) ? ss[l]  : 0.f;
        sq = (l < 8) ? sqq[l] : 0.f;
#pragma unroll
        for (int o = 4; o; o >>= 1) {
            s  += __shfl_xor_sync(0xffffffffu, s,  o);
            sq += __shfl_xor_sync(0xffffffffu, sq, o);
        }
        if (l == 0) { ss[0] = s; sqq[0] = sq; }
    }
    __syncthreads();
    float mean = ss[0] * (1.f / DMODEL);
    float var  = sqq[0] * (1.f / DMODEL) - mean * mean;
    float rstd = rsqrtf(var + 1e-5f);
    float4 g  = ((const float4*)gamma)[t];
    float4 bb = ((const float4*)beta)[t];
    float4 o;
    o.x = (v.x - mean) * rstd * g.x + bb.x;
    o.y = (v.y - mean) * rstd * g.y + bb.y;
    o.z = (v.z - mean) * rstd * g.z + bb.z;
    o.w = (v.w - mean) * rstd * g.w + bb.w;
    ((float4*)(xn + (size_t)row * DMODEL))[t] = o;
}

// ---------------------------------------------------------------------------
// Tensor-core GEMM (3xTF32). C[M,N] = epi(A @ B + bias).
// Block tile 128x128, BK=16, double-buffered smem.
// 8 warps, each computes 32(m) x 64(n) via m16n8k8 fragments.
// MODE 0: +bias   MODE 1: +bias,SiLU   MODE 2: A=A.*A2, +bias,+resid
// ---------------------------------------------------------------------------
template<int MODE>
__global__ __launch_bounds__(256) void tgemm(
    const float* __restrict__ A, const float* __restrict__ A2,
    const float* __restrict__ Bm, const float* __restrict__ bias,
    const float* __restrict__ resid, float* __restrict__ C,
    int M, int N, int K)
{
    __shared__ float As[2][16][136];   // transposed: As[buf][k][m]
    __shared__ float Bs[2][16][136];   // Bs[buf][k][n]

    const int tid  = threadIdx.x;
    const int lane = tid & 31;
    const int gid  = lane >> 2, tig = lane & 3;
    const int wid  = tid >> 5;
    const int wm   = (wid & 3) * 32;
    const int wn   = (wid >> 2) * 64;
    const int mBase = blockIdx.y * 128, nBase = blockIdx.x * 128;

    // global load mapping
    const int am  = tid >> 2;          // 0..63 (and +64)
    const int akq = (tid & 3) * 4;
    const int bk  = tid >> 5;          // 0..7 (and +8)
    const int bnq = (tid & 31) * 4;

    float acc[2][8][4];
#pragma unroll
    for (int i = 0; i < 2; i++)
#pragma unroll
        for (int j = 0; j < 8; j++)
#pragma unroll
            for (int l = 0; l < 4; l++) acc[i][j][l] = 0.f;

    const float* Ap0 = A + (size_t)(mBase + am) * K + akq;
    const float* Ap1 = A + (size_t)(mBase + am + 64) * K + akq;
    const float* A2p0 = (MODE == 2) ? A2 + (size_t)(mBase + am) * K + akq : A;
    const float* A2p1 = (MODE == 2) ? A2 + (size_t)(mBase + am + 64) * K + akq : A;
    const float* Bp0 = Bm + (size_t)bk * N + nBase + bnq;
    const float* Bp1 = Bm + (size_t)(bk + 8) * N + nBase + bnq;

    // prologue: fill buffer 0
    float4 ra0 = *(const float4*)Ap0;
    float4 ra1 = *(const float4*)Ap1;
    float4 rb0 = *(const float4*)Bp0;
    float4 rb1 = *(const float4*)Bp1;
    if (MODE == 2) {
        float4 t0 = *(const float4*)A2p0, t1 = *(const float4*)A2p1;
        ra0.x *= t0.x; ra0.y *= t0.y; ra0.z *= t0.z; ra0.w *= t0.w;
        ra1.x *= t1.x; ra1.y *= t1.y; ra1.z *= t1.z; ra1.w *= t1.w;
    }
    As[0][akq+0][am] = ra0.x; As[0][akq+1][am] = ra0.y;
    As[0][akq+2][am] = ra0.z; As[0][akq+3][am] = ra0.w;
    As[0][akq+0][am+64] = ra1.x; As[0][akq+1][am+64] = ra1.y;
    As[0][akq+2][am+64] = ra1.z; As[0][akq+3][am+64] = ra1.w;
    *(float4*)&Bs[0][bk][bnq]   = rb0;
    *(float4*)&Bs[0][bk+8][bnq] = rb1;
    __syncthreads();

    int buf = 0;
    for (int kt = 0; kt < K; kt += 16) {
        const bool hasNext = (kt + 16 < K);
        if (hasNext) {
            ra0 = *(const float4*)(Ap0 + kt + 16);
            ra1 = *(const float4*)(Ap1 + kt + 16);
            rb0 = *(const float4*)(Bp0 + (size_t)(kt + 16) * N);
            rb1 = *(const float4*)(Bp1 + (size_t)(kt + 16) * N);
            if (MODE == 2) {
                float4 t0 = *(const float4*)(A2p0 + kt + 16);
                float4 t1 = *(const float4*)(A2p1 + kt + 16);
                ra0.x *= t0.x; ra0.y *= t0.y; ra0.z *= t0.z; ra0.w *= t0.w;
                ra1.x *= t1.x; ra1.y *= t1.y; ra1.z *= t1.z; ra1.w *= t1.w;
            }
        }
#pragma unroll
        for (int ks = 0; ks < 2; ks++) {
            uint32_t ah[2][4], al[2][4];
#pragma unroll
            for (int mf = 0; mf < 2; mf++) {
                int m = wm + mf * 16 + gid;
                float x0 = As[buf][ks*8+tig  ][m];
                float x1 = As[buf][ks*8+tig  ][m+8];
                float x2 = As[buf][ks*8+tig+4][m];
                float x3 = As[buf][ks*8+tig+4][m+8];
                tf32_split(x0, ah[mf][0], al[mf][0]);
                tf32_split(x1, ah[mf][1], al[mf][1]);
                tf32_split(x2, ah[mf][2], al[mf][2]);
                tf32_split(x3, ah[mf][3], al[mf][3]);
            }
#pragma unroll
            for (int nf = 0; nf < 8; nf++) {
                int n = wn + nf * 8 + gid;
                float y0 = Bs[buf][ks*8+tig  ][n];
                float y1 = Bs[buf][ks*8+tig+4][n];
                uint32_t bhh[2], bll[2];
                tf32_split(y0, bhh[0], bll[0]);
                tf32_split(y1, bhh[1], bll[1]);
#pragma unroll
                for (int mf = 0; mf < 2; mf++) {
                    mma8(acc[mf][nf], ah[mf], bhh);
                    mma8(acc[mf][nf], al[mf], bhh);
                    mma8(acc[mf][nf], ah[mf], bll);
                }
            }
        }
        if (hasNext) {
            int nb = buf ^ 1;
            As[nb][akq+0][am] = ra0.x; As[nb][akq+1][am] = ra0.y;
            As[nb][akq+2][am] = ra0.z; As[nb][akq+3][am] = ra0.w;
            As[nb][akq+0][am+64] = ra1.x; As[nb][akq+1][am+64] = ra1.y;
            As[nb][akq+2][am+64] = ra1.z; As[nb][akq+3][am+64] = ra1.w;
            *(float4*)&Bs[nb][bk][bnq]   = rb0;
            *(float4*)&Bs[nb][bk+8][bnq] = rb1;
        }
        __syncthreads();
        buf ^= 1;
    }

    // epilogue
#pragma unroll
    for (int mf = 0; mf < 2; mf++) {
#pragma unroll
        for (int nf = 0; nf < 8; nf++) {
            int row0 = mBase + wm + mf * 16 + gid;
            int col  = nBase + wn + nf * 8 + 2 * tig;
            float bx = bias[col], by = bias[col + 1];
            float v0 = acc[mf][nf][0] + bx;
            float v1 = acc[mf][nf][1] + by;
            float v2 = acc[mf][nf][2] + bx;
            float v3 = acc[mf][nf][3] + by;
            if (MODE == 1) {
                v0 = v0 / (1.f + __expf(-v0));
                v1 = v1 / (1.f + __expf(-v1));
                v2 = v2 / (1.f + __expf(-v2));
                v3 = v3 / (1.f + __expf(-v3));
            }
            if (MODE == 2) {
                const float* r0 = resid + (size_t)row0 * N + col;
                const float* r1 = resid + (size_t)(row0 + 8) * N + col;
                v0 += r0[0]; v1 += r0[1]; v2 += r1[0]; v3 += r1[1];
            }
            float2 o0 = {v0, v1}, o1 = {v2, v3};
            *(float2*)(C + (size_t)row0 * N + col) = o0;
            *(float2*)(C + (size_t)(row0 + 8) * N + col) = o1;
        }
    }
}

// ---------------------------------------------------------------------------
// Fused causal sigmoid attention on tensor cores (3xTF32).
// Block = 64 q-rows x one (batch,head). 8 warps: scores/ctx warp tile 16x32.
// smem: Qt[64k][72], Ks[64n][68], Vs[64k][72], Pt[64k][72]  (72.7 KB dynamic)
// ---------------------------------------------------------------------------
#define QP 72
#define KP 68
#define VP 72
#define PP 72

__global__ __launch_bounds__(256) void attn_kernel(
    const float* __restrict__ qkv, const float* __restrict__ rpb,
    float* __restrict__ ctx)
{
    extern __shared__ float smf[];
    float* Qt = smf;                  // Qt[k*QP + m]
    float* Ks = Qt + 64 * QP;         // Ks[n*KP + k]
    float* Vs = Ks + 64 * KP;         // Vs[k*VP + d]
    float* Pt = Vs + 64 * VP;         // Pt[k*PP + m]

    const int qt = 31 - blockIdx.x;   // big tiles first
    const int bh = blockIdx.y;
    const int b = bh >> 4, h = bh & 15;
    const float pbias = rpb[h];
    const int tid  = threadIdx.x;
    const int lane = tid & 31;
    const int gid  = lane >> 2, tig = lane & 3;
    const int wid  = tid >> 5;
    const int m0   = (wid & 3) * 16;
    const int n0   = (wid >> 2) * 32;

    const float* qbase = qkv + (size_t)(b * SEQ) * N_QKV + h * 64;
    const float* kbase = qbase + DMODEL;
    const float* vbase = qbase + 2 * DMODEL;

    const int lrow = tid >> 4;            // 0..15
    const int lcq  = (tid & 15) * 4;      // 0..60

    // load Q tile transposed
#pragma unroll
    for (int i = 0; i < 4; i++) {
        int row = lrow + i * 16;
        float4 v = *(const float4*)(qbase + (size_t)(qt * 64 + row) * N_QKV + lcq);
        Qt[(lcq + 0) * QP + row] = v.x;
        Qt[(lcq + 1) * QP + row] = v.y;
        Qt[(lcq + 2) * QP + row] = v.z;
        Qt[(lcq + 3) * QP + row] = v.w;
    }

    float cacc[4][4];
#pragma unroll
    for (int i = 0; i < 4; i++)
#pragma unroll
        for (int j = 0; j < 4; j++) cacc[i][j] = 0.f;

    for (int kt = 0; kt <= qt; kt++) {
        // prefetch K,V tiles
        float4 kvr[4], vvr[4];
#pragma unroll
        for (int i = 0; i < 4; i++) {
            int row = lrow + i * 16;
            kvr[i] = *(const float4*)(kbase + (size_t)(kt * 64 + row) * N_QKV + lcq);
            vvr[i] = *(const float4*)(vbase + (size_t)(kt * 64 + row) * N_QKV + lcq);
        }
        __syncthreads();   // prev iter's PV done with Vs/Pt
#pragma unroll
        for (int i = 0; i < 4; i++) {
            int row = lrow + i * 16;
            *(float4*)&Ks[row * KP + lcq] = kvr[i];
            *(float4*)&Vs[row * VP + lcq] = vvr[i];
        }
        __syncthreads();

        // S = Q @ K^T   (16x32 per warp)
        float sacc[4][4];
#pragma unroll
        for (int i = 0; i < 4; i++)
#pragma unroll
            for (int j = 0; j < 4; j++) sacc[i][j] = 0.f;
#pragma unroll
        for (int ks = 0; ks < 8; ks++) {
            uint32_t ah[4], al[4];
            {
                float x0 = Qt[(ks*8+tig  ) * QP + m0 + gid];
                float x1 = Qt[(ks*8+tig  ) * QP + m0 + gid + 8];
                float x2 = Qt[(ks*8+tig+4) * QP + m0 + gid];
                float x3 = Qt[(ks*8+tig+4) * QP + m0 + gid + 8];
                tf32_split(x0, ah[0], al[0]);
                tf32_split(x1, ah[1], al[1]);
                tf32_split(x2, ah[2], al[2]);
                tf32_split(x3, ah[3], al[3]);
            }
#pragma unroll
            for (int nf = 0; nf < 4; nf++) {
                int n = n0 + nf * 8 + gid;
                float y0 = Ks[n * KP + ks*8 + tig];
                float y1 = Ks[n * KP + ks*8 + tig + 4];
                uint32_t bhh[2], bll[2];
                tf32_split(y0, bhh[0], bll[0]);
                tf32_split(y1, bhh[1], bll[1]);
                mma8(sacc[nf], ah, bhh);
                mma8(sacc[nf], al, bhh);
                mma8(sacc[nf], ah, bll);
            }
        }

        // sigmoid + causal mask, write P transposed to smem
        const int rowg0 = qt * 64 + m0 + gid;
#pragma unroll
        for (int nf = 0; nf < 4; nf++) {
            int cl = n0 + nf * 8 + 2 * tig;    // local col (even)
            int cg = kt * 64 + cl;             // global col
#pragma unroll
            for (int j = 0; j < 4; j++) {
                int rg = rowg0 + ((j >> 1) ? 8 : 0);
                int cgj = cg + (j & 1);
                float sc = sacc[nf][j] * 0.125f + pbias;
                float p = (cgj <= rg) ? __fdividef(1.f, 1.f + __expf(-sc)) : 0.f;
                int rl = m0 + gid + ((j >> 1) ? 8 : 0);
                Pt[(cl + (j & 1)) * PP + rl] = p;
            }
        }
        __syncthreads();

        // ctx += P @ V
#pragma unroll
        for (int ks = 0; ks < 8; ks++) {
            uint32_t ah[4], al[4];
            {
                float x0 = Pt[(ks*8+tig  ) * PP + m0 + gid];
                float x1 = Pt[(ks*8+tig  ) * PP + m0 + gid + 8];
                float x2 = Pt[(ks*8+tig+4) * PP + m0 + gid];
                float x3 = Pt[(ks*8+tig+4) * PP + m0 + gid + 8];
                tf32_split(x0, ah[0], al[0]);
                tf32_split(x1, ah[1], al[1]);
                tf32_split(x2, ah[2], al[2]);
                tf32_split(x3, ah[3], al[3]);
            }
#pragma unroll
            for (int nf = 0; nf < 4; nf++) {
                int n = n0 + nf * 8 + gid;
                float y0 = Vs[(ks*8+tig  ) * VP + n];
                float y1 = Vs[(ks*8+tig+4) * VP + n];
                uint32_t bhh[2], bll[2];
                tf32_split(y0, bhh[0], bll[0]);
                tf32_split(y1, bhh[1], bll[1]);
                mma8(cacc[nf], ah, bhh);
                mma8(cacc[nf], al, bhh);
                mma8(cacc[nf], ah, bll);
            }
        }
    }

    // write ctx: [b, s, h*64 + d]
#pragma unroll
    for (int nf = 0; nf < 4; nf++) {
        int row = qt * 64 + m0 + gid;
        int col = h * 64 + n0 + nf * 8 + 2 * tig;
        float2 o0 = {cacc[nf][0], cacc[nf][1]};
        float2 o1 = {cacc[nf][2], cacc[nf][3]};
        *(float2*)(ctx + (size_t)(b * SEQ + row) * DMODEL + col) = o0;
        *(float2*)(ctx + (size_t)(b * SEQ + row + 8) * DMODEL + col) = o1;
    }
}

// ---------------------------------------------------------------------------
extern "C" void kernel_launch(void* const* d_in, const int* in_sizes, int n_in,
                              void* d_out, int out_size)
{
    const float* x      = (const float*)d_in[0];
    // d_in[1] = attention_mask (causal tril) — applied analytically, unused
    const float* ln_g   = (const float*)d_in[2];
    const float* ln_b   = (const float*)d_in[3];
    const float* w_qkv  = (const float*)d_in[4];
    const float* b_qkv  = (const float*)d_in[5];
    const float* w_gate = (const float*)d_in[6];
    const float* b_gate = (const float*)d_in[7];
    const float* w_out  = (const float*)d_in[8];
    const float* b_out  = (const float*)d_in[9];
    const float* rpb    = (const float*)d_in[10];
    float* out = (float*)d_out;

    float *xn, *qkv, *u, *ctx;
    cudaGetSymbolAddress((void**)&xn,  g_xn);
    cudaGetSymbolAddress((void**)&qkv, g_qkv);
    cudaGetSymbolAddress((void**)&u,   g_u);
    cudaGetSymbolAddress((void**)&ctx, g_ctx);

    const int ATTN_SMEM = (64 * QP + 64 * KP + 64 * VP + 64 * PP) * 4;
    cudaFuncSetAttribute(attn_kernel, cudaFuncAttributeMaxDynamicSharedMemorySize, ATTN_SMEM);

    ln_kernel<<<R_TOT, 256>>>(x, ln_g, ln_b, xn);

    tgemm<0><<<dim3(N_QKV / 128, R_TOT / 128), 256>>>(
        xn, nullptr, w_qkv, b_qkv, nullptr, qkv, R_TOT, N_QKV, DMODEL);

    tgemm<1><<<dim3(DMODEL / 128, R_TOT / 128), 256>>>(
        xn, nullptr, w_gate, b_gate, nullptr, u, R_TOT, DMODEL, DMODEL);

    attn_kernel<<<dim3(SEQ / 64, 2 * NHEAD), 256, ATTN_SMEM>>>(qkv, rpb, ctx);

    tgemm<2><<<dim3(DMODEL / 128, R_TOT / 128), 256>>>(
        ctx, u, w_out, b_out, x, out, R_TOT, DMODEL, DMODEL);
}

// round 3
// speedup vs baseline: 1.9223x; 1.5636x over previous
#include <cuda_runtime.h>
#include <cuda_bf16.h>
#include <cstdint>

#define R_TOT 4096
#define DMODEL 1024
#define N_QKV 3072
#define SEQ 2048
#define NHEAD 16

// ------------------------------ scratch (device globals) -------------------
__device__ __nv_bfloat16 g_xnh[R_TOT * DMODEL], g_xnl[R_TOT * DMODEL];
__device__ __nv_bfloat16 g_wqh[N_QKV * DMODEL], g_wql[N_QKV * DMODEL];
__device__ __nv_bfloat16 g_wgh[DMODEL * DMODEL], g_wgl[DMODEL * DMODEL];
__device__ __nv_bfloat16 g_woh[DMODEL * DMODEL], g_wol[DMODEL * DMODEL];
__device__ uint32_t g_qkvh[(size_t)R_TOT * N_QKV], g_qkvl[(size_t)R_TOT * N_QKV];
__device__ float g_u[R_TOT * DMODEL];
__device__ float g_ctx[R_TOT * DMODEL];
__device__ __nv_bfloat16 g_ah[R_TOT * DMODEL], g_al[R_TOT * DMODEL];

// ------------------------------ helpers ------------------------------------
__device__ __forceinline__ uint32_t f2tf32(float x) {
    uint32_t r; asm("cvt.rna.tf32.f32 %0, %1;" : "=r"(r) : "f"(x)); return r;
}
__device__ __forceinline__ void bf_split(float x, __nv_bfloat16& h, __nv_bfloat16& l) {
    h = __float2bfloat16_rn(x);
    l = __float2bfloat16_rn(x - __bfloat162float(h));
}
__device__ __forceinline__ void mma16(float d[4], const uint32_t a[4], const uint32_t b[2]) {
    asm volatile("mma.sync.aligned.m16n8k16.row.col.f32.bf16.bf16.f32 "
        "{%0,%1,%2,%3},{%4,%5,%6,%7},{%8,%9},{%0,%1,%2,%3};"
        : "+f"(d[0]), "+f"(d[1]), "+f"(d[2]), "+f"(d[3])
        : "r"(a[0]), "r"(a[1]), "r"(a[2]), "r"(a[3]), "r"(b[0]), "r"(b[1]));
}
__device__ __forceinline__ void mma8(float d[4], const uint32_t a[4], const uint32_t b[2]) {
    asm volatile("mma.sync.aligned.m16n8k8.row.col.f32.tf32.tf32.f32 "
        "{%0,%1,%2,%3},{%4,%5,%6,%7},{%8,%9},{%0,%1,%2,%3};"
        : "+f"(d[0]), "+f"(d[1]), "+f"(d[2]), "+f"(d[3])
        : "r"(a[0]), "r"(a[1]), "r"(a[2]), "r"(a[3]), "r"(b[0]), "r"(b[1]));
}

// ------------------------------ LayerNorm + bf16 split ---------------------
__global__ __launch_bounds__(256) void ln_split_kernel(
    const float* __restrict__ x, const float* __restrict__ gamma,
    const float* __restrict__ beta,
    __nv_bfloat16* __restrict__ xh, __nv_bfloat16* __restrict__ xl)
{
    int row = blockIdx.x;
    int t = threadIdx.x;
    const float4* xr = (const float4*)(x + (size_t)row * DMODEL);
    float4 v = xr[t];
    float s  = v.x + v.y + v.z + v.w;
    float sq = v.x*v.x + v.y*v.y + v.z*v.z + v.w*v.w;
#pragma unroll
    for (int o = 16; o; o >>= 1) {
        s  += __shfl_xor_sync(0xffffffffu, s,  o);
        sq += __shfl_xor_sync(0xffffffffu, sq, o);
    }
    __shared__ float ss[8], sqq[8];
    int w = t >> 5, l = t & 31;
    if (l == 0) { ss[w] = s; sqq[w] = sq; }
    __syncthreads();
    if (w == 0) {
        s  = (l < 8) ? ss[l]  : 0.f;
        sq = (l < 8) ? sqq[l] : 0.f;
#pragma unroll
        for (int o = 4; o; o >>= 1) {
            s  += __shfl_xor_sync(0xffffffffu, s,  o);
            sq += __shfl_xor_sync(0xffffffffu, sq, o);
        }
        if (l == 0) { ss[0] = s; sqq[0] = sq; }
    }
    __syncthreads();
    float mean = ss[0] * (1.f / DMODEL);
    float var  = sqq[0] * (1.f / DMODEL) - mean * mean;
    float rstd = rsqrtf(var + 1e-5f);
    float4 g  = ((const float4*)gamma)[t];
    float4 bb = ((const float4*)beta)[t];
    float o0 = (v.x - mean) * rstd * g.x + bb.x;
    float o1 = (v.y - mean) * rstd * g.y + bb.y;
    float o2 = (v.z - mean) * rstd * g.z + bb.z;
    float o3 = (v.w - mean) * rstd * g.w + bb.w;
    __nv_bfloat16 h0, l0, h1, l1, h2, l2, h3, l3;
    bf_split(o0, h0, l0); bf_split(o1, h1, l1);
    bf_split(o2, h2, l2); bf_split(o3, h3, l3);
    __nv_bfloat162* dh = (__nv_bfloat162*)(xh + (size_t)row * DMODEL + t * 4);
    __nv_bfloat162* dl = (__nv_bfloat162*)(xl + (size_t)row * DMODEL + t * 4);
    __nv_bfloat162 p;
    p.x = h0; p.y = h1; dh[0] = p;
    p.x = h2; p.y = h3; dh[1] = p;
    p.x = l0; p.y = l1; dl[0] = p;
    p.x = l2; p.y = l3; dl[1] = p;
}

// --------------------- weight transpose + bf16 split ------------------------
// in: w[K][N] fp32, out: wt_h/wt_l [N][K] bf16
__global__ void wsplit_kernel(const float* __restrict__ w,
                              __nv_bfloat16* __restrict__ th,
                              __nv_bfloat16* __restrict__ tl, int K, int N)
{
    __shared__ float t[32][33];
    int n0 = blockIdx.x * 32, k0 = blockIdx.y * 32;
    int tx = threadIdx.x, ty = threadIdx.y;
#pragma unroll
    for (int j = ty; j < 32; j += 8)
        t[j][tx] = w[(size_t)(k0 + j) * N + n0 + tx];
    __syncthreads();
#pragma unroll
    for (int j = ty; j < 32; j += 8) {
        float v = t[tx][j];                   // = w[k0+tx][n0+j]
        __nv_bfloat16 h, l;
        bf_split(v, h, l);
        th[(size_t)(n0 + j) * K + k0 + tx] = h;
        tl[(size_t)(n0 + j) * K + k0 + tx] = l;
    }
}

// --------------------- elementwise ctx*u -> bf16 split ----------------------
__global__ __launch_bounds__(256) void mulsplit_kernel(
    const float* __restrict__ ctx, const float* __restrict__ u,
    __nv_bfloat16* __restrict__ ah, __nv_bfloat16* __restrict__ al)
{
    size_t i = ((size_t)blockIdx.x * 256 + threadIdx.x) * 4;
    float4 c = *(const float4*)(ctx + i);
    float4 g = *(const float4*)(u + i);
    float v0 = c.x * g.x, v1 = c.y * g.y, v2 = c.z * g.z, v3 = c.w * g.w;
    __nv_bfloat16 h0, l0, h1, l1, h2, l2, h3, l3;
    bf_split(v0, h0, l0); bf_split(v1, h1, l1);
    bf_split(v2, h2, l2); bf_split(v3, h3, l3);
    __nv_bfloat162 p;
    __nv_bfloat162* dh = (__nv_bfloat162*)(ah + i);
    __nv_bfloat162* dl = (__nv_bfloat162*)(al + i);
    p.x = h0; p.y = h1; dh[0] = p;
    p.x = h2; p.y = h3; dh[1] = p;
    p.x = l0; p.y = l1; dl[0] = p;
    p.x = l2; p.y = l3; dl[1] = p;
}

// ---------------------------------------------------------------------------
// bf16 2-split tensor-core GEMM. C = epi(A @ B^T + bias), B pre-transposed [N][K].
// Block 128x128, BK=16 (one m16n8k16 k-chunk), double-buffered.
// MODE 0: write tf32 hi/lo (qkv)   MODE 1: SiLU -> fp32   MODE 2: +resid -> fp32
// ---------------------------------------------------------------------------
template<int MODE>
__global__ __launch_bounds__(256) void tgemm(
    const __nv_bfloat16* __restrict__ Ah, const __nv_bfloat16* __restrict__ Al,
    const __nv_bfloat16* __restrict__ Bh, const __nv_bfloat16* __restrict__ Bl,
    const float* __restrict__ bias, const float* __restrict__ resid,
    float* __restrict__ Cf, uint32_t* __restrict__ Ch, uint32_t* __restrict__ Cl,
    int M, int N, int K)
{
    __shared__ __nv_bfloat16 Ash[2][128][24];
    __shared__ __nv_bfloat16 Asl[2][128][24];
    __shared__ __nv_bfloat16 Bsh[2][128][24];
    __shared__ __nv_bfloat16 Bsl[2][128][24];

    const int tid  = threadIdx.x;
    const int lane = tid & 31;
    const int gid  = lane >> 2, tig = lane & 3;
    const int wid  = tid >> 5;
    const int wm   = (wid & 3) * 32;
    const int wn   = (wid >> 2) * 64;
    const int mBase = blockIdx.y * 128, nBase = blockIdx.x * 128;

    const int row = tid >> 1;            // 0..127
    const int kq  = (tid & 1) * 8;       // 0 or 8

    const __nv_bfloat16* Aph = Ah + (size_t)(mBase + row) * K + kq;
    const __nv_bfloat16* Apl = Al + (size_t)(mBase + row) * K + kq;
    const __nv_bfloat16* Bph = Bh + (size_t)(nBase + row) * K + kq;
    const __nv_bfloat16* Bpl = Bl + (size_t)(nBase + row) * K + kq;

    float acc[2][8][4];
#pragma unroll
    for (int i = 0; i < 2; i++)
#pragma unroll
        for (int j = 0; j < 8; j++)
#pragma unroll
            for (int l = 0; l < 4; l++) acc[i][j][l] = 0.f;

    uint4 rah = *(const uint4*)Aph;
    uint4 ral = *(const uint4*)Apl;
    uint4 rbh = *(const uint4*)Bph;
    uint4 rbl = *(const uint4*)Bpl;
    *(uint4*)&Ash[0][row][kq] = rah;
    *(uint4*)&Asl[0][row][kq] = ral;
    *(uint4*)&Bsh[0][row][kq] = rbh;
    *(uint4*)&Bsl[0][row][kq] = rbl;
    __syncthreads();

    int buf = 0;
    for (int kt = 0; kt < K; kt += 16) {
        const bool hasNext = (kt + 16 < K);
        if (hasNext) {
            rah = *(const uint4*)(Aph + kt + 16);
            ral = *(const uint4*)(Apl + kt + 16);
            rbh = *(const uint4*)(Bph + kt + 16);
            rbl = *(const uint4*)(Bpl + kt + 16);
        }

        uint32_t ahr[2][4], alr[2][4], bhr[8][2], blr[8][2];
#pragma unroll
        for (int mf = 0; mf < 2; mf++) {
            int m = wm + mf * 16 + gid;
            ahr[mf][0] = *(const uint32_t*)&Ash[buf][m    ][2*tig];
            ahr[mf][1] = *(const uint32_t*)&Ash[buf][m + 8][2*tig];
            ahr[mf][2] = *(const uint32_t*)&Ash[buf][m    ][2*tig + 8];
            ahr[mf][3] = *(const uint32_t*)&Ash[buf][m + 8][2*tig + 8];
            alr[mf][0] = *(const uint32_t*)&Asl[buf][m    ][2*tig];
            alr[mf][1] = *(const uint32_t*)&Asl[buf][m + 8][2*tig];
            alr[mf][2] = *(const uint32_t*)&Asl[buf][m    ][2*tig + 8];
            alr[mf][3] = *(const uint32_t*)&Asl[buf][m + 8][2*tig + 8];
        }
#pragma unroll
        for (int nf = 0; nf < 8; nf++) {
            int n = wn + nf * 8 + gid;
            bhr[nf][0] = *(const uint32_t*)&Bsh[buf][n][2*tig];
            bhr[nf][1] = *(const uint32_t*)&Bsh[buf][n][2*tig + 8];
            blr[nf][0] = *(const uint32_t*)&Bsl[buf][n][2*tig];
            blr[nf][1] = *(const uint32_t*)&Bsl[buf][n][2*tig + 8];
        }
        // three passes; 16 independent accumulators between same-acc reuse
#pragma unroll
        for (int nf = 0; nf < 8; nf++)
#pragma unroll
            for (int mf = 0; mf < 2; mf++) mma16(acc[mf][nf], ahr[mf], bhr[nf]);
#pragma unroll
        for (int nf = 0; nf < 8; nf++)
#pragma unroll
            for (int mf = 0; mf < 2; mf++) mma16(acc[mf][nf], alr[mf], bhr[nf]);
#pragma unroll
        for (int nf = 0; nf < 8; nf++)
#pragma unroll
            for (int mf = 0; mf < 2; mf++) mma16(acc[mf][nf], ahr[mf], blr[nf]);

        if (hasNext) {
            int nb = buf ^ 1;
            *(uint4*)&Ash[nb][row][kq] = rah;
            *(uint4*)&Asl[nb][row][kq] = ral;
            *(uint4*)&Bsh[nb][row][kq] = rbh;
            *(uint4*)&Bsl[nb][row][kq] = rbl;
        }
        __syncthreads();
        buf ^= 1;
    }

    // epilogue
#pragma unroll
    for (int mf = 0; mf < 2; mf++) {
#pragma unroll
        for (int nf = 0; nf < 8; nf++) {
            int row0 = mBase + wm + mf * 16 + gid;
            int col  = nBase + wn + nf * 8 + 2 * tig;
            float bx = bias[col], by = bias[col + 1];
            float v0 = acc[mf][nf][0] + bx;
            float v1 = acc[mf][nf][1] + by;
            float v2 = acc[mf][nf][2] + bx;
            float v3 = acc[mf][nf][3] + by;
            if (MODE == 0) {
                uint32_t h0 = f2tf32(v0), h1 = f2tf32(v1);
                uint32_t h2 = f2tf32(v2), h3 = f2tf32(v3);
                uint32_t l0 = f2tf32(v0 - __uint_as_float(h0));
                uint32_t l1 = f2tf32(v1 - __uint_as_float(h1));
                uint32_t l2 = f2tf32(v2 - __uint_as_float(h2));
                uint32_t l3 = f2tf32(v3 - __uint_as_float(h3));
                uint2 u0 = {h0, h1}, u1 = {h2, h3};
                uint2 w0 = {l0, l1}, w1 = {l2, l3};
                *(uint2*)(Ch + (size_t)row0 * N + col) = u0;
                *(uint2*)(Ch + (size_t)(row0 + 8) * N + col) = u1;
                *(uint2*)(Cl + (size_t)row0 * N + col) = w0;
                *(uint2*)(Cl + (size_t)(row0 + 8) * N + col) = w1;
            } else {
                if (MODE == 1) {
                    v0 = v0 / (1.f + __expf(-v0));
                    v1 = v1 / (1.f + __expf(-v1));
                    v2 = v2 / (1.f + __expf(-v2));
                    v3 = v3 / (1.f + __expf(-v3));
                }
                if (MODE == 2) {
                    const float* r0 = resid + (size_t)row0 * N + col;
                    const float* r1 = resid + (size_t)(row0 + 8) * N + col;
                    v0 += r0[0]; v1 += r0[1]; v2 += r1[0]; v3 += r1[1];
                }
                float2 o0 = {v0, v1}, o1 = {v2, v3};
                *(float2*)(Cf + (size_t)row0 * N + col) = o0;
                *(float2*)(Cf + (size_t)(row0 + 8) * N + col) = o1;
            }
        }
    }
}

// ---------------------------------------------------------------------------
// Fused causal sigmoid attention, tf32, pre-split operands, 4 mma / tile-step.
// S = (qh+ql)@kh^T ; P = tf32(sigmoid) ; ctx += P@(vh+vl)
// smem (u32): Qh,Ql [64k][72m]  Kh [64n][68k]  Vh,Vl [64k][72d]  Pt [64k][72m]
// ---------------------------------------------------------------------------
__global__ __launch_bounds__(256) void attn_kernel(
    const uint32_t* __restrict__ qkvh, const uint32_t* __restrict__ qkvl,
    const float* __restrict__ rpb, float* __restrict__ ctx)
{
    extern __shared__ uint32_t smu[];
    uint32_t* Qh = smu;
    uint32_t* Ql = Qh + 64 * 72;
    uint32_t* Kh = Ql + 64 * 72;
    uint32_t* Vh = Kh + 64 * 68;
    uint32_t* Vl = Vh + 64 * 72;
    uint32_t* Pt = Vl + 64 * 72;

    const int qt = 31 - blockIdx.x;
    const int bh = blockIdx.y;
    const int b = bh >> 4, h = bh & 15;
    const float pbias = rpb[h];
    const int tid  = threadIdx.x;
    const int lane = tid & 31;
    const int gid  = lane >> 2, tig = lane & 3;
    const int wid  = tid >> 5;
    const int m0   = (wid & 3) * 16;
    const int n0   = (wid >> 2) * 32;

    const size_t base = (size_t)(b * SEQ) * N_QKV + h * 64;
    const uint32_t* qbh = qkvh + base;
    const uint32_t* qbl = qkvl + base;
    const uint32_t* kbh = qbh + DMODEL;
    const uint32_t* vbh = qbh + 2 * DMODEL;
    const uint32_t* vbl = qbl + 2 * DMODEL;

    const int lrow = tid >> 4;            // 0..15
    const int lcq  = (tid & 15) * 4;      // 0..60

    // load Q tile (hi+lo) transposed
#pragma unroll
    for (int i = 0; i < 4; i++) {
        int row = lrow + i * 16;
        uint4 vh = *(const uint4*)(qbh + (size_t)(qt * 64 + row) * N_QKV + lcq);
        uint4 vl = *(const uint4*)(qbl + (size_t)(qt * 64 + row) * N_QKV + lcq);
        Qh[(lcq + 0) * 72 + row] = vh.x;
        Qh[(lcq + 1) * 72 + row] = vh.y;
        Qh[(lcq + 2) * 72 + row] = vh.z;
        Qh[(lcq + 3) * 72 + row] = vh.w;
        Ql[(lcq + 0) * 72 + row] = vl.x;
        Ql[(lcq + 1) * 72 + row] = vl.y;
        Ql[(lcq + 2) * 72 + row] = vl.z;
        Ql[(lcq + 3) * 72 + row] = vl.w;
    }

    float cacc[4][4];
#pragma unroll
    for (int i = 0; i < 4; i++)
#pragma unroll
        for (int j = 0; j < 4; j++) cacc[i][j] = 0.f;

    for (int kt = 0; kt <= qt; kt++) {
        uint4 kr[4], vrh[4], vrl[4];
#pragma unroll
        for (int i = 0; i < 4; i++) {
            int row = lrow + i * 16;
            size_t off = (size_t)(kt * 64 + row) * N_QKV + lcq;
            kr[i]  = *(const uint4*)(kbh + off);
            vrh[i] = *(const uint4*)(vbh + off);
            vrl[i] = *(const uint4*)(vbl + off);
        }
        __syncthreads();   // prev PV done with Vh/Vl/Pt
#pragma unroll
        for (int i = 0; i < 4; i++) {
            int row = lrow + i * 16;
            *(uint4*)&Kh[row * 68 + lcq] = kr[i];
            *(uint4*)&Vh[row * 72 + lcq] = vrh[i];
            *(uint4*)&Vl[row * 72 + lcq] = vrl[i];
        }
        __syncthreads();

        // S = Q @ K^T  (16x32 per warp), 2 mma per (ks,nf)
        float sacc[4][4];
#pragma unroll
        for (int i = 0; i < 4; i++)
#pragma unroll
            for (int j = 0; j < 4; j++) sacc[i][j] = 0.f;
#pragma unroll
        for (int ks = 0; ks < 8; ks++) {
            uint32_t ah[4], al[4], bk[4][2];
            ah[0] = Qh[(ks*8+tig  ) * 72 + m0 + gid];
            ah[1] = Qh[(ks*8+tig  ) * 72 + m0 + gid + 8];
            ah[2] = Qh[(ks*8+tig+4) * 72 + m0 + gid];
            ah[3] = Qh[(ks*8+tig+4) * 72 + m0 + gid + 8];
            al[0] = Ql[(ks*8+tig  ) * 72 + m0 + gid];
            al[1] = Ql[(ks*8+tig  ) * 72 + m0 + gid + 8];
            al[2] = Ql[(ks*8+tig+4) * 72 + m0 + gid];
            al[3] = Ql[(ks*8+tig+4) * 72 + m0 + gid + 8];
#pragma unroll
            for (int nf = 0; nf < 4; nf++) {
                int n = n0 + nf * 8 + gid;
                bk[nf][0] = Kh[n * 68 + ks*8 + tig];
                bk[nf][1] = Kh[n * 68 + ks*8 + tig + 4];
            }
#pragma unroll
            for (int nf = 0; nf < 4; nf++) mma8(sacc[nf], ah, bk[nf]);
#pragma unroll
            for (int nf = 0; nf < 4; nf++) mma8(sacc[nf], al, bk[nf]);
        }

        // sigmoid + causal mask -> Pt (tf32, transposed [k][m])
        const int rowg0 = qt * 64 + m0 + gid;
        const bool diag = (kt == qt);
#pragma unroll
        for (int nf = 0; nf < 4; nf++) {
            int cl = n0 + nf * 8 + 2 * tig;
            int cg = kt * 64 + cl;
#pragma unroll
            for (int j = 0; j < 4; j++) {
                int rg = rowg0 + ((j >> 1) ? 8 : 0);
                int cgj = cg + (j & 1);
                float sc = sacc[nf][j] * 0.125f + pbias;
                float p = (!diag || cgj <= rg) ? __fdividef(1.f, 1.f + __expf(-sc)) : 0.f;
                int rl = m0 + gid + ((j >> 1) ? 8 : 0);
                Pt[(cl + (j & 1)) * 72 + rl] = f2tf32(p);
            }
        }
        __syncthreads();

        // ctx += P @ V, 2 mma per (ks,nf)
#pragma unroll
        for (int ks = 0; ks < 8; ks++) {
            uint32_t ap[4], bvh[4][2], bvl[4][2];
            ap[0] = Pt[(ks*8+tig  ) * 72 + m0 + gid];
            ap[1] = Pt[(ks*8+tig  ) * 72 + m0 + gid + 8];
            ap[2] = Pt[(ks*8+tig+4) * 72 + m0 + gid];
            ap[3] = Pt[(ks*8+tig+4) * 72 + m0 + gid + 8];
#pragma unroll
            for (int nf = 0; nf < 4; nf++) {
                int n = n0 + nf * 8 + gid;
                bvh[nf][0] = Vh[(ks*8+tig  ) * 72 + n];
                bvh[nf][1] = Vh[(ks*8+tig+4) * 72 + n];
                bvl[nf][0] = Vl[(ks*8+tig  ) * 72 + n];
                bvl[nf][1] = Vl[(ks*8+tig+4) * 72 + n];
            }
#pragma unroll
            for (int nf = 0; nf < 4; nf++) mma8(cacc[nf], ap, bvh[nf]);
#pragma unroll
            for (int nf = 0; nf < 4; nf++) mma8(cacc[nf], ap, bvl[nf]);
        }
    }

    // write ctx: [b, s, h*64 + d]
#pragma unroll
    for (int nf = 0; nf < 4; nf++) {
        int row = qt * 64 + m0 + gid;
        int col = h * 64 + n0 + nf * 8 + 2 * tig;
        float2 o0 = {cacc[nf][0], cacc[nf][1]};
        float2 o1 = {cacc[nf][2], cacc[nf][3]};
        *(float2*)(ctx + (size_t)(b * SEQ + row) * DMODEL + col) = o0;
        *(float2*)(ctx + (size_t)(b * SEQ + row + 8) * DMODEL + col) = o1;
    }
}

// ---------------------------------------------------------------------------
extern "C" void kernel_launch(void* const* d_in, const int* in_sizes, int n_in,
                              void* d_out, int out_size)
{
    const float* x      = (const float*)d_in[0];
    // d_in[1] = attention_mask (causal tril) — applied analytically, unused
    const float* ln_g   = (const float*)d_in[2];
    const float* ln_b   = (const float*)d_in[3];
    const float* w_qkv  = (const float*)d_in[4];
    const float* b_qkv  = (const float*)d_in[5];
    const float* w_gate = (const float*)d_in[6];
    const float* b_gate = (const float*)d_in[7];
    const float* w_out  = (const float*)d_in[8];
    const float* b_out  = (const float*)d_in[9];
    const float* rpb    = (const float*)d_in[10];
    float* out = (float*)d_out;

    __nv_bfloat16 *xnh, *xnl, *wqh, *wql, *wgh, *wgl, *woh, *wol, *ah, *al;
    uint32_t *qkvh, *qkvl;
    float *u, *ctx;
    cudaGetSymbolAddress((void**)&xnh, g_xnh);
    cudaGetSymbolAddress((void**)&xnl, g_xnl);
    cudaGetSymbolAddress((void**)&wqh, g_wqh);
    cudaGetSymbolAddress((void**)&wql, g_wql);
    cudaGetSymbolAddress((void**)&wgh, g_wgh);
    cudaGetSymbolAddress((void**)&wgl, g_wgl);
    cudaGetSymbolAddress((void**)&woh, g_woh);
    cudaGetSymbolAddress((void**)&wol, g_wol);
    cudaGetSymbolAddress((void**)&qkvh, g_qkvh);
    cudaGetSymbolAddress((void**)&qkvl, g_qkvl);
    cudaGetSymbolAddress((void**)&u,   g_u);
    cudaGetSymbolAddress((void**)&ctx, g_ctx);
    cudaGetSymbolAddress((void**)&ah,  g_ah);
    cudaGetSymbolAddress((void**)&al,  g_al);

    const int ATTN_SMEM = 64 * (72 * 5 + 68) * 4;   // ~107 KB
    static bool attr_done = false;
    if (!attr_done) {
        cudaFuncSetAttribute(attn_kernel, cudaFuncAttributeMaxDynamicSharedMemorySize, ATTN_SMEM);
        attr_done = true;
    }

    // weight prep (constants re-derived every launch: deterministic)
    wsplit_kernel<<<dim3(N_QKV / 32, DMODEL / 32), dim3(32, 8)>>>(w_qkv, wqh, wql, DMODEL, N_QKV);
    wsplit_kernel<<<dim3(DMODEL / 32, DMODEL / 32), dim3(32, 8)>>>(w_gate, wgh, wgl, DMODEL, DMODEL);
    wsplit_kernel<<<dim3(DMODEL / 32, DMODEL / 32), dim3(32, 8)>>>(w_out, woh, wol, DMODEL, DMODEL);

    ln_split_kernel<<<R_TOT, 256>>>(x, ln_g, ln_b, xnh, xnl);

    tgemm<0><<<dim3(N_QKV / 128, R_TOT / 128), 256>>>(
        xnh, xnl, wqh, wql, b_qkv, nullptr, nullptr, qkvh, qkvl, R_TOT, N_QKV, DMODEL);

    tgemm<1><<<dim3(DMODEL / 128, R_TOT / 128), 256>>>(
        xnh, xnl, wgh, wgl, b_gate, nullptr, u, nullptr, nullptr, R_TOT, DMODEL, DMODEL);

    attn_kernel<<<dim3(SEQ / 64, 2 * NHEAD), 256, ATTN_SMEM>>>(qkvh, qkvl, rpb, ctx);

    mulsplit_kernel<<<(R_TOT * DMODEL) / (256 * 4), 256>>>(ctx, u, ah, al);

    tgemm<2><<<dim3(DMODEL / 128, R_TOT / 128), 256>>>(
        ah, al, woh, wol, b_out, x, out, nullptr, nullptr, R_TOT, DMODEL, DMODEL);
}

// round 5
// speedup vs baseline: 2.0463x; 1.0645x over previous
#include <cuda_runtime.h>
#include <cuda_bf16.h>
#include <cstdint>

#define R_TOT 4096
#define DMODEL 1024
#define N_QKV 3072
#define SEQ 2048
#define NHEAD 16

// ------------------------------ scratch (device globals) -------------------
__device__ __nv_bfloat16 g_xnh[R_TOT * DMODEL], g_xnl[R_TOT * DMODEL];
__device__ __nv_bfloat16 g_wqh[N_QKV * DMODEL], g_wql[N_QKV * DMODEL];
__device__ __nv_bfloat16 g_wgh[DMODEL * DMODEL], g_wgl[DMODEL * DMODEL];
__device__ __nv_bfloat16 g_woh[DMODEL * DMODEL], g_wol[DMODEL * DMODEL];
__device__ __nv_bfloat16 g_qkvh[(size_t)R_TOT * N_QKV], g_qkvl[(size_t)R_TOT * N_QKV];
__device__ float g_u[R_TOT * DMODEL];
__device__ float g_ctx[R_TOT * DMODEL];
__device__ __nv_bfloat16 g_ah[R_TOT * DMODEL], g_al[R_TOT * DMODEL];

// ------------------------------ helpers ------------------------------------
__device__ __forceinline__ void bf_split(float x, __nv_bfloat16& h, __nv_bfloat16& l) {
    h = __float2bfloat16_rn(x);
    l = __float2bfloat16_rn(x - __bfloat162float(h));
}
__device__ __forceinline__ void mma16(float d[4], const uint32_t a[4], uint32_t b0, uint32_t b1) {
    asm volatile("mma.sync.aligned.m16n8k16.row.col.f32.bf16.bf16.f32 "
        "{%0,%1,%2,%3},{%4,%5,%6,%7},{%8,%9},{%0,%1,%2,%3};"
        : "+f"(d[0]), "+f"(d[1]), "+f"(d[2]), "+f"(d[3])
        : "r"(a[0]), "r"(a[1]), "r"(a[2]), "r"(a[3]), "r"(b0), "r"(b1));
}
__device__ __forceinline__ void ldm_x4(uint32_t r[4], uint32_t addr) {
    asm volatile("ldmatrix.sync.aligned.m8n8.x4.shared.b16 {%0,%1,%2,%3}, [%4];"
        : "=r"(r[0]), "=r"(r[1]), "=r"(r[2]), "=r"(r[3]) : "r"(addr));
}
__device__ __forceinline__ uint32_t smem_u32(const void* p) {
    return (uint32_t)__cvta_generic_to_shared(p);
}

// ------------------------------ LayerNorm + bf16 split ---------------------
__global__ __launch_bounds__(256) void ln_split_kernel(
    const float* __restrict__ x, const float* __restrict__ gamma,
    const float* __restrict__ beta,
    __nv_bfloat16* __restrict__ xh, __nv_bfloat16* __restrict__ xl)
{
    int row = blockIdx.x;
    int t = threadIdx.x;
    const float4* xr = (const float4*)(x + (size_t)row * DMODEL);
    float4 v = xr[t];
    float s  = v.x + v.y + v.z + v.w;
    float sq = v.x*v.x + v.y*v.y + v.z*v.z + v.w*v.w;
#pragma unroll
    for (int o = 16; o; o >>= 1) {
        s  += __shfl_xor_sync(0xffffffffu, s,  o);
        sq += __shfl_xor_sync(0xffffffffu, sq, o);
    }
    __shared__ float ss[8], sqq[8];
    int w = t >> 5, l = t & 31;
    if (l == 0) { ss[w] = s; sqq[w] = sq; }
    __syncthreads();
    if (w == 0) {
        s  = (l < 8) ? ss[l]  : 0.f;
        sq = (l < 8) ? sqq[l] : 0.f;
#pragma unroll
        for (int o = 4; o; o >>= 1) {
            s  += __shfl_xor_sync(0xffffffffu, s,  o);
            sq += __shfl_xor_sync(0xffffffffu, sq, o);
        }
        if (l == 0) { ss[0] = s; sqq[0] = sq; }
    }
    __syncthreads();
    float mean = ss[0] * (1.f / DMODEL);
    float var  = sqq[0] * (1.f / DMODEL) - mean * mean;
    float rstd = rsqrtf(var + 1e-5f);
    float4 g  = ((const float4*)gamma)[t];
    float4 bb = ((const float4*)beta)[t];
    float o0 = (v.x - mean) * rstd * g.x + bb.x;
    float o1 = (v.y - mean) * rstd * g.y + bb.y;
    float o2 = (v.z - mean) * rstd * g.z + bb.z;
    float o3 = (v.w - mean) * rstd * g.w + bb.w;
    __nv_bfloat16 h0, l0, h1, l1, h2, l2, h3, l3;
    bf_split(o0, h0, l0); bf_split(o1, h1, l1);
    bf_split(o2, h2, l2); bf_split(o3, h3, l3);
    uint2 ph, pl;
    __nv_bfloat162 a;
    a.x = h0; a.y = h1; ph.x = *(uint32_t*)&a;
    a.x = h2; a.y = h3; ph.y = *(uint32_t*)&a;
    a.x = l0; a.y = l1; pl.x = *(uint32_t*)&a;
    a.x = l2; a.y = l3; pl.y = *(uint32_t*)&a;
    *(uint2*)(xh + (size_t)row * DMODEL + t * 4) = ph;
    *(uint2*)(xl + (size_t)row * DMODEL + t * 4) = pl;
}

// --------------------- weight transpose + bf16 split ------------------------
__global__ void wsplit_kernel(const float* __restrict__ w,
                              __nv_bfloat16* __restrict__ th,
                              __nv_bfloat16* __restrict__ tl, int K, int N)
{
    __shared__ float t[32][33];
    int n0 = blockIdx.x * 32, k0 = blockIdx.y * 32;
    int tx = threadIdx.x, ty = threadIdx.y;
#pragma unroll
    for (int j = ty; j < 32; j += 8)
        t[j][tx] = w[(size_t)(k0 + j) * N + n0 + tx];
    __syncthreads();
#pragma unroll
    for (int j = ty; j < 32; j += 8) {
        float v = t[tx][j];
        __nv_bfloat16 h, l;
        bf_split(v, h, l);
        th[(size_t)(n0 + j) * K + k0 + tx] = h;
        tl[(size_t)(n0 + j) * K + k0 + tx] = l;
    }
}

// --------------------- elementwise ctx*u -> bf16 split ----------------------
__global__ __launch_bounds__(256) void mulsplit_kernel(
    const float* __restrict__ ctx, const float* __restrict__ u,
    __nv_bfloat16* __restrict__ ah, __nv_bfloat16* __restrict__ al)
{
    size_t i = ((size_t)blockIdx.x * 256 + threadIdx.x) * 4;
    float4 c = *(const float4*)(ctx + i);
    float4 g = *(const float4*)(u + i);
    float v0 = c.x * g.x, v1 = c.y * g.y, v2 = c.z * g.z, v3 = c.w * g.w;
    __nv_bfloat16 h0, l0, h1, l1, h2, l2, h3, l3;
    bf_split(v0, h0, l0); bf_split(v1, h1, l1);
    bf_split(v2, h2, l2); bf_split(v3, h3, l3);
    uint2 ph, pl;
    __nv_bfloat162 a;
    a.x = h0; a.y = h1; ph.x = *(uint32_t*)&a;
    a.x = h2; a.y = h3; ph.y = *(uint32_t*)&a;
    a.x = l0; a.y = l1; pl.x = *(uint32_t*)&a;
    a.x = l2; a.y = l3; pl.y = *(uint32_t*)&a;
    *(uint2*)(ah + i) = ph;
    *(uint2*)(al + i) = pl;
}

// ---------------------------------------------------------------------------
// bf16 2-split GEMM, ldmatrix fragments. C = epi(A @ B^T + bias).
// Block 128x128, BK=16, double-buffered. 8 warps, warp tile 32x64.
// MODE 0: write bf16 hi/lo   MODE 1: SiLU -> fp32   MODE 2: +resid -> fp32
// ---------------------------------------------------------------------------
template<int MODE>
__global__ __launch_bounds__(256) void tgemm(
    const __nv_bfloat16* __restrict__ Ah, const __nv_bfloat16* __restrict__ Al,
    const __nv_bfloat16* __restrict__ Bh, const __nv_bfloat16* __restrict__ Bl,
    const float* __restrict__ bias, const float* __restrict__ resid,
    float* __restrict__ Cf, __nv_bfloat16* __restrict__ Chh,
    __nv_bfloat16* __restrict__ Cll, int M, int N, int K)
{
    __shared__ __nv_bfloat16 Ash[2][128][24];
    __shared__ __nv_bfloat16 Asl[2][128][24];
    __shared__ __nv_bfloat16 Bsh[2][128][24];
    __shared__ __nv_bfloat16 Bsl[2][128][24];

    const int tid  = threadIdx.x;
    const int lane = tid & 31;
    const int gid  = lane >> 2, tig = lane & 3;
    const int wid  = tid >> 5;
    const int wm   = (wid & 3) * 32;
    const int wn   = (wid >> 2) * 64;
    const int mBase = blockIdx.y * 128, nBase = blockIdx.x * 128;
    const int lrow = lane & 15;
    const int lkb  = (lane >> 4) * 16;

    const int row = tid >> 1;
    const int kq  = (tid & 1) * 8;

    const __nv_bfloat16* Aph = Ah + (size_t)(mBase + row) * K + kq;
    const __nv_bfloat16* Apl = Al + (size_t)(mBase + row) * K + kq;
    const __nv_bfloat16* Bph = Bh + (size_t)(nBase + row) * K + kq;
    const __nv_bfloat16* Bpl = Bl + (size_t)(nBase + row) * K + kq;

    uint32_t uAh[2], uAl[2], uBh[2], uBl[2];
#pragma unroll
    for (int b = 0; b < 2; b++) {
        uAh[b] = smem_u32(&Ash[b][0][0]);
        uAl[b] = smem_u32(&Asl[b][0][0]);
        uBh[b] = smem_u32(&Bsh[b][0][0]);
        uBl[b] = smem_u32(&Bsl[b][0][0]);
    }

    float acc[2][8][4];
#pragma unroll
    for (int i = 0; i < 2; i++)
#pragma unroll
        for (int j = 0; j < 8; j++)
#pragma unroll
            for (int l = 0; l < 4; l++) acc[i][j][l] = 0.f;

    uint4 rah = *(const uint4*)Aph;
    uint4 ral = *(const uint4*)Apl;
    uint4 rbh = *(const uint4*)Bph;
    uint4 rbl = *(const uint4*)Bpl;
    *(uint4*)&Ash[0][row][kq] = rah;
    *(uint4*)&Asl[0][row][kq] = ral;
    *(uint4*)&Bsh[0][row][kq] = rbh;
    *(uint4*)&Bsl[0][row][kq] = rbl;
    __syncthreads();

    int buf = 0;
    for (int kt = 0; kt < K; kt += 16) {
        const bool hasNext = (kt + 16 < K);
        if (hasNext) {
            rah = *(const uint4*)(Aph + kt + 16);
            ral = *(const uint4*)(Apl + kt + 16);
            rbh = *(const uint4*)(Bph + kt + 16);
            rbl = *(const uint4*)(Bpl + kt + 16);
        }

        uint32_t ah[2][4], al[2][4], bh[4][4], bl[4][4];
#pragma unroll
        for (int mf = 0; mf < 2; mf++) {
            ldm_x4(ah[mf], uAh[buf] + (wm + mf * 16 + lrow) * 48 + lkb);
            ldm_x4(al[mf], uAl[buf] + (wm + mf * 16 + lrow) * 48 + lkb);
        }
#pragma unroll
        for (int p = 0; p < 4; p++) {
            ldm_x4(bh[p], uBh[buf] + (wn + p * 16 + lrow) * 48 + lkb);
            ldm_x4(bl[p], uBl[buf] + (wn + p * 16 + lrow) * 48 + lkb);
        }
#pragma unroll
        for (int nf = 0; nf < 8; nf++)
#pragma unroll
            for (int mf = 0; mf < 2; mf++)
                mma16(acc[mf][nf], ah[mf], bh[nf >> 1][nf & 1], bh[nf >> 1][(nf & 1) + 2]);
#pragma unroll
        for (int nf = 0; nf < 8; nf++)
#pragma unroll
            for (int mf = 0; mf < 2; mf++)
                mma16(acc[mf][nf], al[mf], bh[nf >> 1][nf & 1], bh[nf >> 1][(nf & 1) + 2]);
#pragma unroll
        for (int nf = 0; nf < 8; nf++)
#pragma unroll
            for (int mf = 0; mf < 2; mf++)
                mma16(acc[mf][nf], ah[mf], bl[nf >> 1][nf & 1], bl[nf >> 1][(nf & 1) + 2]);

        if (hasNext) {
            int nb = buf ^ 1;
            *(uint4*)&Ash[nb][row][kq] = rah;
            *(uint4*)&Asl[nb][row][kq] = ral;
            *(uint4*)&Bsh[nb][row][kq] = rbh;
            *(uint4*)&Bsl[nb][row][kq] = rbl;
        }
        __syncthreads();
        buf ^= 1;
    }

    // epilogue
#pragma unroll
    for (int mf = 0; mf < 2; mf++) {
#pragma unroll
        for (int nf = 0; nf < 8; nf++) {
            int row0 = mBase + wm + mf * 16 + gid;
            int col  = nBase + wn + nf * 8 + 2 * tig;
            float bx = bias[col], by = bias[col + 1];
            float v0 = acc[mf][nf][0] + bx;
            float v1 = acc[mf][nf][1] + by;
            float v2 = acc[mf][nf][2] + bx;
            float v3 = acc[mf][nf][3] + by;
            if (MODE == 0) {
                __nv_bfloat16 h0, l0, h1, l1, h2, l2, h3, l3;
                bf_split(v0, h0, l0); bf_split(v1, h1, l1);
                bf_split(v2, h2, l2); bf_split(v3, h3, l3);
                __nv_bfloat162 a;
                a.x = h0; a.y = h1;
                *(__nv_bfloat162*)(Chh + (size_t)row0 * N + col) = a;
                a.x = h2; a.y = h3;
                *(__nv_bfloat162*)(Chh + (size_t)(row0 + 8) * N + col) = a;
                a.x = l0; a.y = l1;
                *(__nv_bfloat162*)(Cll + (size_t)row0 * N + col) = a;
                a.x = l2; a.y = l3;
                *(__nv_bfloat162*)(Cll + (size_t)(row0 + 8) * N + col) = a;
            } else {
                if (MODE == 1) {
                    v0 = v0 / (1.f + __expf(-v0));
                    v1 = v1 / (1.f + __expf(-v1));
                    v2 = v2 / (1.f + __expf(-v2));
                    v3 = v3 / (1.f + __expf(-v3));
                }
                if (MODE == 2) {
                    const float* r0 = resid + (size_t)row0 * N + col;
                    const float* r1 = resid + (size_t)(row0 + 8) * N + col;
                    v0 += r0[0]; v1 += r0[1]; v2 += r1[0]; v3 += r1[1];
                }
                float2 o0 = {v0, v1}, o1 = {v2, v3};
                *(float2*)(Cf + (size_t)row0 * N + col) = o0;
                *(float2*)(Cf + (size_t)(row0 + 8) * N + col) = o1;
            }
        }
    }
}

// ---------------------------------------------------------------------------
// Fused causal sigmoid attention, bf16 m16n8k16, ldmatrix fragments.
// smem regions (each 64 x 72 bf16): Qh Ql Kh Kl Vh Vl Ph Pl  => 72 KB
// ---------------------------------------------------------------------------
#define ATT_STRIDE 72
#define ATT_REGION (64 * ATT_STRIDE)

__global__ __launch_bounds__(256) void attn_kernel(
    const __nv_bfloat16* __restrict__ qkvh, const __nv_bfloat16* __restrict__ qkvl,
    const float* __restrict__ rpb, float* __restrict__ ctx)
{
    extern __shared__ __nv_bfloat16 smb[];
    __nv_bfloat16* Qh = smb;
    __nv_bfloat16* Ql = Qh + ATT_REGION;
    __nv_bfloat16* Kh = Ql + ATT_REGION;
    __nv_bfloat16* Kl = Kh + ATT_REGION;
    __nv_bfloat16* Vh = Kl + ATT_REGION;
    __nv_bfloat16* Vl = Vh + ATT_REGION;
    __nv_bfloat16* Ph = Vl + ATT_REGION;
    __nv_bfloat16* Pl = Ph + ATT_REGION;
    const uint32_t uQh = smem_u32(Qh), uQl = smem_u32(Ql);
    const uint32_t uKh = smem_u32(Kh), uKl = smem_u32(Kl);
    const uint32_t uVh = smem_u32(Vh), uVl = smem_u32(Vl);
    const uint32_t uPh = smem_u32(Ph), uPl = smem_u32(Pl);

    const int qt = 31 - blockIdx.x;
    const int bh = blockIdx.y;
    const int b = bh >> 4, h = bh & 15;
    const float pbias = rpb[h];
    const int tid  = threadIdx.x;
    const int lane = tid & 31;
    const int gid  = lane >> 2, tig = lane & 3;
    const int wid  = tid >> 5;
    const int m0   = (wid & 3) * 16;
    const int n0   = (wid >> 2) * 32;
    const int lrow = lane & 15;
    const int lkb  = (lane >> 4) * 16;

    const size_t base = (size_t)(b * SEQ) * N_QKV + h * 64;
    const __nv_bfloat16* qbh = qkvh + base;
    const __nv_bfloat16* qbl = qkvl + base;
    const __nv_bfloat16* kbh = qbh + DMODEL;
    const __nv_bfloat16* kbl = qbl + DMODEL;
    const __nv_bfloat16* vbh = qbh + 2 * DMODEL;
    const __nv_bfloat16* vbl = qbl + 2 * DMODEL;

    const int krow = tid >> 2;
    const int kc16 = (tid & 3) * 16;
    const int vkp = tid & 31;
    const int vd0 = (tid >> 5) * 8;

    // load Q tile (row-major, straight copy)
    {
        size_t off = (size_t)(qt * 64 + krow) * N_QKV + kc16;
        uint4 a0 = *(const uint4*)(qbh + off);
        uint4 a1 = *(const uint4*)(qbh + off + 8);
        uint4 b0 = *(const uint4*)(qbl + off);
        uint4 b1 = *(const uint4*)(qbl + off + 8);
        *(uint4*)&Qh[krow * ATT_STRIDE + kc16]     = a0;
        *(uint4*)&Qh[krow * ATT_STRIDE + kc16 + 8] = a1;
        *(uint4*)&Ql[krow * ATT_STRIDE + kc16]     = b0;
        *(uint4*)&Ql[krow * ATT_STRIDE + kc16 + 8] = b1;
    }

    float cacc[4][4];
#pragma unroll
    for (int i = 0; i < 4; i++)
#pragma unroll
        for (int j = 0; j < 4; j++) cacc[i][j] = 0.f;

    for (int kt = 0; kt <= qt; kt++) {
        uint4 kh0, kh1, kl0, kl1, va0, va1, vb0, vb1;
        {
            size_t off = (size_t)(kt * 64 + krow) * N_QKV + kc16;
            kh0 = *(const uint4*)(kbh + off);
            kh1 = *(const uint4*)(kbh + off + 8);
            kl0 = *(const uint4*)(kbl + off);
            kl1 = *(const uint4*)(kbl + off + 8);
            size_t voff0 = (size_t)(kt * 64 + 2 * vkp) * N_QKV + vd0;
            size_t voff1 = voff0 + N_QKV;
            va0 = *(const uint4*)(vbh + voff0);
            va1 = *(const uint4*)(vbh + voff1);
            vb0 = *(const uint4*)(vbl + voff0);
            vb1 = *(const uint4*)(vbl + voff1);
        }
        __syncthreads();   // prev PV done with V/P; prev QK done with K
        {
            *(uint4*)&Kh[krow * ATT_STRIDE + kc16]     = kh0;
            *(uint4*)&Kh[krow * ATT_STRIDE + kc16 + 8] = kh1;
            *(uint4*)&Kl[krow * ATT_STRIDE + kc16]     = kl0;
            *(uint4*)&Kl[krow * ATT_STRIDE + kc16 + 8] = kl1;
            const uint32_t* a0w = (const uint32_t*)&va0;
            const uint32_t* a1w = (const uint32_t*)&va1;
            const uint32_t* b0w = (const uint32_t*)&vb0;
            const uint32_t* b1w = (const uint32_t*)&vb1;
#pragma unroll
            for (int i = 0; i < 4; i++) {
                uint32_t h_lo = __byte_perm(a0w[i], a1w[i], 0x5410);
                uint32_t h_hi = __byte_perm(a0w[i], a1w[i], 0x7632);
                uint32_t l_lo = __byte_perm(b0w[i], b1w[i], 0x5410);
                uint32_t l_hi = __byte_perm(b0w[i], b1w[i], 0x7632);
                int d = vd0 + 2 * i;
                *(uint32_t*)&Vh[d * ATT_STRIDE + 2 * vkp]       = h_lo;
                *(uint32_t*)&Vh[(d + 1) * ATT_STRIDE + 2 * vkp] = h_hi;
                *(uint32_t*)&Vl[d * ATT_STRIDE + 2 * vkp]       = l_lo;
                *(uint32_t*)&Vl[(d + 1) * ATT_STRIDE + 2 * vkp] = l_hi;
            }
        }
        __syncthreads();

        // S = Q @ K^T : 3-term bf16
        float sacc[4][4];
#pragma unroll
        for (int i = 0; i < 4; i++)
#pragma unroll
            for (int j = 0; j < 4; j++) sacc[i][j] = 0.f;
#pragma unroll
        for (int ks = 0; ks < 4; ks++) {
            const int kb = ks * 32 + lkb;
            uint32_t qh[4], ql[4], k0h[4], k1h[4], k0l[4], k1l[4];
            ldm_x4(qh, uQh + (m0 + lrow) * (ATT_STRIDE * 2) + kb);
            ldm_x4(ql, uQl + (m0 + lrow) * (ATT_STRIDE * 2) + kb);
            ldm_x4(k0h, uKh + (n0 + lrow) * (ATT_STRIDE * 2) + kb);
            ldm_x4(k1h, uKh + (n0 + 16 + lrow) * (ATT_STRIDE * 2) + kb);
            ldm_x4(k0l, uKl + (n0 + lrow) * (ATT_STRIDE * 2) + kb);
            ldm_x4(k1l, uKl + (n0 + 16 + lrow) * (ATT_STRIDE * 2) + kb);
            mma16(sacc[0], qh, k0h[0], k0h[2]);
            mma16(sacc[1], qh, k0h[1], k0h[3]);
            mma16(sacc[2], qh, k1h[0], k1h[2]);
            mma16(sacc[3], qh, k1h[1], k1h[3]);
            mma16(sacc[0], ql, k0h[0], k0h[2]);
            mma16(sacc[1], ql, k0h[1], k0h[3]);
            mma16(sacc[2], ql, k1h[0], k1h[2]);
            mma16(sacc[3], ql, k1h[1], k1h[3]);
            mma16(sacc[0], qh, k0l[0], k0l[2]);
            mma16(sacc[1], qh, k0l[1], k0l[3]);
            mma16(sacc[2], qh, k1l[0], k1l[2]);
            mma16(sacc[3], qh, k1l[1], k1l[3]);
        }

        // sigmoid + causal mask -> P (bf16 hi/lo, row-major [m][kseq])
        const int rowg0 = qt * 64 + m0 + gid;
        const bool diag = (kt == qt);
#pragma unroll
        for (int nf = 0; nf < 4; nf++) {
            int cl = n0 + nf * 8 + 2 * tig;
            int cg = kt * 64 + cl;
            float p0, p1, p2, p3;
            {
                float s0 = sacc[nf][0] * 0.125f + pbias;
                float s1 = sacc[nf][1] * 0.125f + pbias;
                float s2 = sacc[nf][2] * 0.125f + pbias;
                float s3 = sacc[nf][3] * 0.125f + pbias;
                p0 = __fdividef(1.f, 1.f + __expf(-s0));
                p1 = __fdividef(1.f, 1.f + __expf(-s1));
                p2 = __fdividef(1.f, 1.f + __expf(-s2));
                p3 = __fdividef(1.f, 1.f + __expf(-s3));
                if (diag) {
                    if (cg > rowg0)     p0 = 0.f;
                    if (cg + 1 > rowg0) p1 = 0.f;
                    if (cg > rowg0 + 8)     p2 = 0.f;
                    if (cg + 1 > rowg0 + 8) p3 = 0.f;
                }
            }
            __nv_bfloat16 h0, l0, h1, l1, h2, l2, h3, l3;
            bf_split(p0, h0, l0); bf_split(p1, h1, l1);
            bf_split(p2, h2, l2); bf_split(p3, h3, l3);
            __nv_bfloat162 a;
            int r0 = m0 + gid, r1 = m0 + gid + 8;
            a.x = h0; a.y = h1; *(__nv_bfloat162*)&Ph[r0 * ATT_STRIDE + cl] = a;
            a.x = h2; a.y = h3; *(__nv_bfloat162*)&Ph[r1 * ATT_STRIDE + cl] = a;
            a.x = l0; a.y = l1; *(__nv_bfloat162*)&Pl[r0 * ATT_STRIDE + cl] = a;
            a.x = l2; a.y = l3; *(__nv_bfloat162*)&Pl[r1 * ATT_STRIDE + cl] = a;
        }
        __syncthreads();

        // ctx += P @ V : 3-term bf16
#pragma unroll
        for (int ks = 0; ks < 4; ks++) {
            const int kb = ks * 32 + lkb;
            uint32_t ph[4], pl[4], v0h[4], v1h[4], v0l[4], v1l[4];
            ldm_x4(ph, uPh + (m0 + lrow) * (ATT_STRIDE * 2) + kb);
            ldm_x4(pl, uPl + (m0 + lrow) * (ATT_STRIDE * 2) + kb);
            ldm_x4(v0h, uVh + (n0 + lrow) * (ATT_STRIDE * 2) + kb);
            ldm_x4(v1h, uVh + (n0 + 16 + lrow) * (ATT_STRIDE * 2) + kb);
            ldm_x4(v0l, uVl + (n0 + lrow) * (ATT_STRIDE * 2) + kb);
            ldm_x4(v1l, uVl + (n0 + 16 + lrow) * (ATT_STRIDE * 2) + kb);
            mma16(cacc[0], ph, v0h[0], v0h[2]);
            mma16(cacc[1], ph, v0h[1], v0h[3]);
            mma16(cacc[2], ph, v1h[0], v1h[2]);
            mma16(cacc[3], ph, v1h[1], v1h[3]);
            mma16(cacc[0], pl, v0h[0], v0h[2]);
            mma16(cacc[1], pl, v0h[1], v0h[3]);
            mma16(cacc[2], pl, v1h[0], v1h[2]);
            mma16(cacc[3], pl, v1h[1], v1h[3]);
            mma16(cacc[0], ph, v0l[0], v0l[2]);
            mma16(cacc[1], ph, v0l[1], v0l[3]);
            mma16(cacc[2], ph, v1l[0], v1l[2]);
            mma16(cacc[3], ph, v1l[1], v1l[3]);
        }
    }

    // write ctx: [b, s, h*64 + d]
#pragma unroll
    for (int nf = 0; nf < 4; nf++) {
        int row = qt * 64 + m0 + gid;
        int col = h * 64 + n0 + nf * 8 + 2 * tig;
        float2 o0 = {cacc[nf][0], cacc[nf][1]};
        float2 o1 = {cacc[nf][2], cacc[nf][3]};
        *(float2*)(ctx + (size_t)(b * SEQ + row) * DMODEL + col) = o0;
        *(float2*)(ctx + (size_t)(b * SEQ + row + 8) * DMODEL + col) = o1;
    }
}

// ---------------------------------------------------------------------------
extern "C" void kernel_launch(void* const* d_in, const int* in_sizes, int n_in,
                              void* d_out, int out_size)
{
    const float* x      = (const float*)d_in[0];
    // d_in[1] = attention_mask (causal tril) — applied analytically, unused
    const float* ln_g   = (const float*)d_in[2];
    const float* ln_b   = (const float*)d_in[3];
    const float* w_qkv  = (const float*)d_in[4];
    const float* b_qkv  = (const float*)d_in[5];
    const float* w_gate = (const float*)d_in[6];
    const float* b_gate = (const float*)d_in[7];
    const float* w_out  = (const float*)d_in[8];
    const float* b_out  = (const float*)d_in[9];
    const float* rpb    = (const float*)d_in[10];
    float* out = (float*)d_out;

    __nv_bfloat16 *xnh, *xnl, *wqh, *wql, *wgh, *wgl, *woh, *wol, *ah, *al;
    __nv_bfloat16 *qkvh, *qkvl;
    float *u, *ctx;
    cudaGetSymbolAddress((void**)&xnh, g_xnh);
    cudaGetSymbolAddress((void**)&xnl, g_xnl);
    cudaGetSymbolAddress((void**)&wqh, g_wqh);
    cudaGetSymbolAddress((void**)&wql, g_wql);
    cudaGetSymbolAddress((void**)&wgh, g_wgh);
    cudaGetSymbolAddress((void**)&wgl, g_wgl);
    cudaGetSymbolAddress((void**)&woh, g_woh);
    cudaGetSymbolAddress((void**)&wol, g_wol);
    cudaGetSymbolAddress((void**)&qkvh, g_qkvh);
    cudaGetSymbolAddress((void**)&qkvl, g_qkvl);
    cudaGetSymbolAddress((void**)&u,   g_u);
    cudaGetSymbolAddress((void**)&ctx, g_ctx);
    cudaGetSymbolAddress((void**)&ah,  g_ah);
    cudaGetSymbolAddress((void**)&al,  g_al);

    const int ATTN_SMEM = 8 * ATT_REGION * 2;   // 73728 B
    cudaFuncSetAttribute(attn_kernel, cudaFuncAttributeMaxDynamicSharedMemorySize, ATTN_SMEM);

    wsplit_kernel<<<dim3(N_QKV / 32, DMODEL / 32), dim3(32, 8)>>>(w_qkv, wqh, wql, DMODEL, N_QKV);
    wsplit_kernel<<<dim3(DMODEL / 32, DMODEL / 32), dim3(32, 8)>>>(w_gate, wgh, wgl, DMODEL, DMODEL);
    wsplit_kernel<<<dim3(DMODEL / 32, DMODEL / 32), dim3(32, 8)>>>(w_out, woh, wol, DMODEL, DMODEL);

    ln_split_kernel<<<R_TOT, 256>>>(x, ln_g, ln_b, xnh, xnl);

    tgemm<0><<<dim3(N_QKV / 128, R_TOT / 128), 256>>>(
        xnh, xnl, wqh, wql, b_qkv, nullptr, nullptr, qkvh, qkvl, R_TOT, N_QKV, DMODEL);

    tgemm<1><<<dim3(DMODEL / 128, R_TOT / 128), 256>>>(
        xnh, xnl, wgh, wgl, b_gate, nullptr, u, nullptr, nullptr, R_TOT, DMODEL, DMODEL);

    attn_kernel<<<dim3(SEQ / 64, 2 * NHEAD), 256, ATTN_SMEM>>>(qkvh, qkvl, rpb, ctx);

    mulsplit_kernel<<<(R_TOT * DMODEL) / (256 * 4), 256>>>(ctx, u, ah, al);

    tgemm<2><<<dim3(DMODEL / 128, R_TOT / 128), 256>>>(
        ah, al, woh, wol, b_out, x, out, nullptr, nullptr, R_TOT, DMODEL, DMODEL);
}

// round 7
// speedup vs baseline: 2.0732x; 1.0131x over previous
#include <cuda_runtime.h>
#include <cuda_bf16.h>
#include <cstdint>

#define R_TOT 4096
#define DMODEL 1024
#define N_QKV 3072
#define SEQ 2048
#define NHEAD 16

// ------------------------------ scratch (device globals) -------------------
__device__ __nv_bfloat16 g_xnh[R_TOT * DMODEL], g_xnl[R_TOT * DMODEL];
__device__ __nv_bfloat16 g_wqh[N_QKV * DMODEL], g_wql[N_QKV * DMODEL];
__device__ __nv_bfloat16 g_wgh[DMODEL * DMODEL], g_wgl[DMODEL * DMODEL];
__device__ __nv_bfloat16 g_woh[DMODEL * DMODEL], g_wol[DMODEL * DMODEL];
__device__ __nv_bfloat16 g_qkvh[(size_t)R_TOT * N_QKV], g_qkvl[(size_t)R_TOT * N_QKV];
__device__ float g_u[R_TOT * DMODEL];
__device__ float g_ctx[R_TOT * DMODEL];
__device__ __nv_bfloat16 g_ah[R_TOT * DMODEL], g_al[R_TOT * DMODEL];

// ------------------------------ helpers ------------------------------------
__device__ __forceinline__ void bf_split(float x, __nv_bfloat16& h, __nv_bfloat16& l) {
    h = __float2bfloat16_rn(x);
    l = __float2bfloat16_rn(x - __bfloat162float(h));
}
__device__ __forceinline__ void mma16(float d[4], const uint32_t a[4], uint32_t b0, uint32_t b1) {
    asm volatile("mma.sync.aligned.m16n8k16.row.col.f32.bf16.bf16.f32 "
        "{%0,%1,%2,%3},{%4,%5,%6,%7},{%8,%9},{%0,%1,%2,%3};"
        : "+f"(d[0]), "+f"(d[1]), "+f"(d[2]), "+f"(d[3])
        : "r"(a[0]), "r"(a[1]), "r"(a[2]), "r"(a[3]), "r"(b0), "r"(b1));
}
__device__ __forceinline__ void ldm_x4(uint32_t r[4], uint32_t addr) {
    asm volatile("ldmatrix.sync.aligned.m8n8.x4.shared.b16 {%0,%1,%2,%3}, [%4];"
        : "=r"(r[0]), "=r"(r[1]), "=r"(r[2]), "=r"(r[3]) : "r"(addr));
}
__device__ __forceinline__ uint32_t smem_u32(const void* p) {
    return (uint32_t)__cvta_generic_to_shared(p);
}
#define CP16(dst, src) \
    asm volatile("cp.async.cg.shared.global [%0], [%1], 16;" \
        :: "r"(dst), "l"(__cvta_generic_to_global(src)) : "memory")
#define CP_COMMIT() asm volatile("cp.async.commit_group;" ::: "memory")
#define CP_WAIT0()  asm volatile("cp.async.wait_group 0;" ::: "memory")

// ------------------------------ LayerNorm + bf16 split ---------------------
__global__ __launch_bounds__(256) void ln_split_kernel(
    const float* __restrict__ x, const float* __restrict__ gamma,
    const float* __restrict__ beta,
    __nv_bfloat16* __restrict__ xh, __nv_bfloat16* __restrict__ xl)
{
    int row = blockIdx.x;
    int t = threadIdx.x;
    const float4* xr = (const float4*)(x + (size_t)row * DMODEL);
    float4 v = xr[t];
    float s  = v.x + v.y + v.z + v.w;
    float sq = v.x*v.x + v.y*v.y + v.z*v.z + v.w*v.w;
#pragma unroll
    for (int o = 16; o; o >>= 1) {
        s  += __shfl_xor_sync(0xffffffffu, s,  o);
        sq += __shfl_xor_sync(0xffffffffu, sq, o);
    }
    __shared__ float ss[8], sqq[8];
    int w = t >> 5, l = t & 31;
    if (l == 0) { ss[w] = s; sqq[w] = sq; }
    __syncthreads();
    if (w == 0) {
        s  = (l < 8) ? ss[l]  : 0.f;
        sq = (l < 8) ? sqq[l] : 0.f;
#pragma unroll
        for (int o = 4; o; o >>= 1) {
            s  += __shfl_xor_sync(0xffffffffu, s,  o);
            sq += __shfl_xor_sync(0xffffffffu, sq, o);
        }
        if (l == 0) { ss[0] = s; sqq[0] = sq; }
    }
    __syncthreads();
    float mean = ss[0] * (1.f / DMODEL);
    float var  = sqq[0] * (1.f / DMODEL) - mean * mean;
    float rstd = rsqrtf(var + 1e-5f);
    float4 g  = ((const float4*)gamma)[t];
    float4 bb = ((const float4*)beta)[t];
    float o0 = (v.x - mean) * rstd * g.x + bb.x;
    float o1 = (v.y - mean) * rstd * g.y + bb.y;
    float o2 = (v.z - mean) * rstd * g.z + bb.z;
    float o3 = (v.w - mean) * rstd * g.w + bb.w;
    __nv_bfloat16 h0, l0, h1, l1, h2, l2, h3, l3;
    bf_split(o0, h0, l0); bf_split(o1, h1, l1);
    bf_split(o2, h2, l2); bf_split(o3, h3, l3);
    uint2 ph, pl;
    __nv_bfloat162 a;
    a.x = h0; a.y = h1; ph.x = *(uint32_t*)&a;
    a.x = h2; a.y = h3; ph.y = *(uint32_t*)&a;
    a.x = l0; a.y = l1; pl.x = *(uint32_t*)&a;
    a.x = l2; a.y = l3; pl.y = *(uint32_t*)&a;
    *(uint2*)(xh + (size_t)row * DMODEL + t * 4) = ph;
    *(uint2*)(xl + (size_t)row * DMODEL + t * 4) = pl;
}

// --------------------- weight transpose + bf16 split ------------------------
__global__ void wsplit_kernel(const float* __restrict__ w,
                              __nv_bfloat16* __restrict__ th,
                              __nv_bfloat16* __restrict__ tl, int K, int N)
{
    __shared__ float t[32][33];
    int n0 = blockIdx.x * 32, k0 = blockIdx.y * 32;
    int tx = threadIdx.x, ty = threadIdx.y;
#pragma unroll
    for (int j = ty; j < 32; j += 8)
        t[j][tx] = w[(size_t)(k0 + j) * N + n0 + tx];
    __syncthreads();
#pragma unroll
    for (int j = ty; j < 32; j += 8) {
        float v = t[tx][j];
        __nv_bfloat16 h, l;
        bf_split(v, h, l);
        th[(size_t)(n0 + j) * K + k0 + tx] = h;
        tl[(size_t)(n0 + j) * K + k0 + tx] = l;
    }
}

// --------------------- elementwise ctx*u -> bf16 split ----------------------
__global__ __launch_bounds__(256) void mulsplit_kernel(
    const float* __restrict__ ctx, const float* __restrict__ u,
    __nv_bfloat16* __restrict__ ah, __nv_bfloat16* __restrict__ al)
{
    size_t i = ((size_t)blockIdx.x * 256 + threadIdx.x) * 4;
    float4 c = *(const float4*)(ctx + i);
    float4 g = *(const float4*)(u + i);
    float v0 = c.x * g.x, v1 = c.y * g.y, v2 = c.z * g.z, v3 = c.w * g.w;
    __nv_bfloat16 h0, l0, h1, l1, h2, l2, h3, l3;
    bf_split(v0, h0, l0); bf_split(v1, h1, l1);
    bf_split(v2, h2, l2); bf_split(v3, h3, l3);
    uint2 ph, pl;
    __nv_bfloat162 a;
    a.x = h0; a.y = h1; ph.x = *(uint32_t*)&a;
    a.x = h2; a.y = h3; ph.y = *(uint32_t*)&a;
    a.x = l0; a.y = l1; pl.x = *(uint32_t*)&a;
    a.x = l2; a.y = l3; pl.y = *(uint32_t*)&a;
    *(uint2*)(ah + i) = ph;
    *(uint2*)(al + i) = pl;
}

// ---------------------------------------------------------------------------
// bf16 2-split GEMM, cp.async double-buffered, BK=32, ldmatrix fragments.
// Block 128x128, 8 warps, warp tile 32x64.
// MODE 0: write bf16 hi/lo   MODE 1: SiLU -> fp32   MODE 2: +resid -> fp32
// smem: stage = Ah(10240) Al(10240) Bh(10240) Bl(10240) = 40960 B, x2 stages
// ---------------------------------------------------------------------------
#define G_STAGE 40960u
#define G_SMEM  (2 * 40960)

template<int MODE>
__global__ __launch_bounds__(256) void tgemm(
    const __nv_bfloat16* __restrict__ Ah, const __nv_bfloat16* __restrict__ Al,
    const __nv_bfloat16* __restrict__ Bh, const __nv_bfloat16* __restrict__ Bl,
    const float* __restrict__ bias, const float* __restrict__ resid,
    float* __restrict__ Cf, __nv_bfloat16* __restrict__ Chh,
    __nv_bfloat16* __restrict__ Cll, int M, int N, int K)
{
    extern __shared__ char gsm[];
    const uint32_t base = smem_u32(gsm);

    const int tid  = threadIdx.x;
    const int lane = tid & 31;
    const int gid  = lane >> 2, tig = lane & 3;
    const int wid  = tid >> 5;
    const int wm   = (wid & 3) * 32;
    const int wn   = (wid >> 2) * 64;
    const int mBase = blockIdx.y * 128, nBase = blockIdx.x * 128;
    const int lrow = lane & 15;
    const uint32_t lkb = (lane >> 4) * 16;

    float acc[2][8][4];
#pragma unroll
    for (int i = 0; i < 2; i++)
#pragma unroll
        for (int j = 0; j < 8; j++)
#pragma unroll
            for (int l = 0; l < 4; l++) acc[i][j][l] = 0.f;

    auto ld_stage = [&](int c, int s) {
        const uint32_t sb = base + (uint32_t)s * G_STAGE;
        const int kt = c * 32;
#pragma unroll
        for (int it = 0; it < 2; it++) {
            int idx = it * 256 + tid;
            int row = idx >> 2, seg = idx & 3;
            uint32_t d = sb + row * 80 + seg * 16;
            size_t aoff = (size_t)(mBase + row) * K + kt + seg * 8;
            size_t boff = (size_t)(nBase + row) * K + kt + seg * 8;
            CP16(d,          Ah + aoff);
            CP16(d + 10240,  Al + aoff);
            CP16(d + 20480,  Bh + boff);
            CP16(d + 30720,  Bl + boff);
        }
    };

    ld_stage(0, 0); CP_COMMIT();
    const int NC = K / 32;
    for (int c = 0; c < NC; c++) {
        CP_WAIT0(); __syncthreads();
        if (c + 1 < NC) { ld_stage(c + 1, (c + 1) & 1); CP_COMMIT(); }
        const uint32_t sb = base + (uint32_t)(c & 1) * G_STAGE;
#pragma unroll
        for (int ks = 0; ks < 2; ks++) {
            const uint32_t kb = ks * 32 + lkb;
            uint32_t ah[2][4], al[2][4], bh[4][4], bl[4][4];
#pragma unroll
            for (int mf = 0; mf < 2; mf++) {
                uint32_t ra = sb + (wm + mf * 16 + lrow) * 80 + kb;
                ldm_x4(ah[mf], ra);
                ldm_x4(al[mf], ra + 10240);
            }
#pragma unroll
            for (int p = 0; p < 4; p++) {
                uint32_t rb = sb + 20480 + (wn + p * 16 + lrow) * 80 + kb;
                ldm_x4(bh[p], rb);
                ldm_x4(bl[p], rb + 10240);
            }
#pragma unroll
            for (int nf = 0; nf < 8; nf++)
#pragma unroll
                for (int mf = 0; mf < 2; mf++)
                    mma16(acc[mf][nf], ah[mf], bh[nf >> 1][nf & 1], bh[nf >> 1][(nf & 1) + 2]);
#pragma unroll
            for (int nf = 0; nf < 8; nf++)
#pragma unroll
                for (int mf = 0; mf < 2; mf++)
                    mma16(acc[mf][nf], al[mf], bh[nf >> 1][nf & 1], bh[nf >> 1][(nf & 1) + 2]);
#pragma unroll
            for (int nf = 0; nf < 8; nf++)
#pragma unroll
                for (int mf = 0; mf < 2; mf++)
                    mma16(acc[mf][nf], ah[mf], bl[nf >> 1][nf & 1], bl[nf >> 1][(nf & 1) + 2]);
        }
    }

    // epilogue
#pragma unroll
    for (int mf = 0; mf < 2; mf++) {
#pragma unroll
        for (int nf = 0; nf < 8; nf++) {
            int row0 = mBase + wm + mf * 16 + gid;
            int col  = nBase + wn + nf * 8 + 2 * tig;
            float bx = bias[col], by = bias[col + 1];
            float v0 = acc[mf][nf][0] + bx;
            float v1 = acc[mf][nf][1] + by;
            float v2 = acc[mf][nf][2] + bx;
            float v3 = acc[mf][nf][3] + by;
            if (MODE == 0) {
                __nv_bfloat16 h0, l0, h1, l1, h2, l2, h3, l3;
                bf_split(v0, h0, l0); bf_split(v1, h1, l1);
                bf_split(v2, h2, l2); bf_split(v3, h3, l3);
                __nv_bfloat162 a;
                a.x = h0; a.y = h1;
                *(__nv_bfloat162*)(Chh + (size_t)row0 * N + col) = a;
                a.x = h2; a.y = h3;
                *(__nv_bfloat162*)(Chh + (size_t)(row0 + 8) * N + col) = a;
                a.x = l0; a.y = l1;
                *(__nv_bfloat162*)(Cll + (size_t)row0 * N + col) = a;
                a.x = l2; a.y = l3;
                *(__nv_bfloat162*)(Cll + (size_t)(row0 + 8) * N + col) = a;
            } else {
                if (MODE == 1) {
                    v0 = v0 / (1.f + __expf(-v0));
                    v1 = v1 / (1.f + __expf(-v1));
                    v2 = v2 / (1.f + __expf(-v2));
                    v3 = v3 / (1.f + __expf(-v3));
                }
                if (MODE == 2) {
                    const float* r0 = resid + (size_t)row0 * N + col;
                    const float* r1 = resid + (size_t)(row0 + 8) * N + col;
                    v0 += r0[0]; v1 += r0[1]; v2 += r1[0]; v3 += r1[1];
                }
                float2 o0 = {v0, v1}, o1 = {v2, v3};
                *(float2*)(Cf + (size_t)row0 * N + col) = o0;
                *(float2*)(Cf + (size_t)(row0 + 8) * N + col) = o1;
            }
        }
    }
}

// ---------------------------------------------------------------------------
// Fused causal sigmoid attention, bf16 m16n8k16, 128-q-row tiles.
// 8 warps: warp tile 32(m) x 32(n). smem 110592 B.
// ---------------------------------------------------------------------------
#define AST 72
#define ATTN_SMEM_B ((4 * 128 + 4 * 64) * AST * 2)

__global__ __launch_bounds__(256) void attn_kernel(
    const __nv_bfloat16* __restrict__ qkvh, const __nv_bfloat16* __restrict__ qkvl,
    const float* __restrict__ rpb, float* __restrict__ ctx)
{
    extern __shared__ __nv_bfloat16 smb[];
    __nv_bfloat16* Qh = smb;
    __nv_bfloat16* Ql = Qh + 128 * AST;
    __nv_bfloat16* Ph = Ql + 128 * AST;
    __nv_bfloat16* Pl = Ph + 128 * AST;
    __nv_bfloat16* Kh = Pl + 128 * AST;
    __nv_bfloat16* Kl = Kh + 64 * AST;
    __nv_bfloat16* Vh = Kl + 64 * AST;
    __nv_bfloat16* Vl = Vh + 64 * AST;
    const uint32_t uQh = smem_u32(Qh), uQl = smem_u32(Ql);
    const uint32_t uPh = smem_u32(Ph), uPl = smem_u32(Pl);
    const uint32_t uKh = smem_u32(Kh), uKl = smem_u32(Kl);
    const uint32_t uVh = smem_u32(Vh), uVl = smem_u32(Vl);

    const int qt = 15 - (int)blockIdx.x;     // big tiles first
    const int bh = blockIdx.y;
    const int b = bh >> 4, h = bh & 15;
    const float pbias = rpb[h];
    const int tid  = threadIdx.x;
    const int lane = tid & 31;
    const int gid  = lane >> 2, tig = lane & 3;
    const int wid  = tid >> 5;
    const int m0   = (wid & 3) * 32;
    const int n0   = (wid >> 2) * 32;
    const int lrow = lane & 15;
    const uint32_t lkb = (lane >> 4) * 16;

    const size_t base = (size_t)(b * SEQ) * N_QKV + h * 64;
    const __nv_bfloat16* qbh = qkvh + base;
    const __nv_bfloat16* qbl = qkvl + base;
    const __nv_bfloat16* kbh = qbh + DMODEL;
    const __nv_bfloat16* kbl = qbl + DMODEL;
    const __nv_bfloat16* vbh = qbh + 2 * DMODEL;
    const __nv_bfloat16* vbl = qbl + 2 * DMODEL;

    // Q load: 128 rows x 64 cols (hi+lo)
#pragma unroll
    for (int it = 0; it < 4; it++) {
        int idx = it * 256 + tid;
        int row = idx >> 3, seg = idx & 7;
        size_t off = (size_t)(qt * 128 + row) * N_QKV + seg * 8;
        *(uint4*)&Qh[row * AST + seg * 8] = *(const uint4*)(qbh + off);
        *(uint4*)&Ql[row * AST + seg * 8] = *(const uint4*)(qbl + off);
    }

    float cacc[2][4][4];
#pragma unroll
    for (int i = 0; i < 2; i++)
#pragma unroll
        for (int j = 0; j < 4; j++)
#pragma unroll
            for (int l = 0; l < 4; l++) cacc[i][j][l] = 0.f;

    const int krow = tid >> 2;
    const int kc16 = (tid & 3) * 16;
    const int vkp = tid & 31;
    const int vd0 = (tid >> 5) * 8;

    const int nkt = 2 * qt + 2;
    for (int kt = 0; kt < nkt; kt++) {
        // prefetch K/V tile (64 rows)
        uint4 kh0, kh1, kl0, kl1, va0, va1, vb0, vb1;
        {
            size_t off = (size_t)(kt * 64 + krow) * N_QKV + kc16;
            kh0 = *(const uint4*)(kbh + off);
            kh1 = *(const uint4*)(kbh + off + 8);
            kl0 = *(const uint4*)(kbl + off);
            kl1 = *(const uint4*)(kbl + off + 8);
            size_t voff0 = (size_t)(kt * 64 + 2 * vkp) * N_QKV + vd0;
            size_t voff1 = voff0 + N_QKV;
            va0 = *(const uint4*)(vbh + voff0);
            va1 = *(const uint4*)(vbh + voff1);
            vb0 = *(const uint4*)(vbl + voff0);
            vb1 = *(const uint4*)(vbl + voff1);
        }
        __syncthreads();   // prev iter's reads of K/V/P done
        {
            *(uint4*)&Kh[krow * AST + kc16]     = kh0;
            *(uint4*)&Kh[krow * AST + kc16 + 8] = kh1;
            *(uint4*)&Kl[krow * AST + kc16]     = kl0;
            *(uint4*)&Kl[krow * AST + kc16 + 8] = kl1;
            const uint32_t* a0w = (const uint32_t*)&va0;
            const uint32_t* a1w = (const uint32_t*)&va1;
            const uint32_t* b0w = (const uint32_t*)&vb0;
            const uint32_t* b1w = (const uint32_t*)&vb1;
#pragma unroll
            for (int i = 0; i < 4; i++) {
                uint32_t h_lo = __byte_perm(a0w[i], a1w[i], 0x5410);
                uint32_t h_hi = __byte_perm(a0w[i], a1w[i], 0x7632);
                uint32_t l_lo = __byte_perm(b0w[i], b1w[i], 0x5410);
                uint32_t l_hi = __byte_perm(b0w[i], b1w[i], 0x7632);
                int d = vd0 + 2 * i;
                *(uint32_t*)&Vh[d * AST + 2 * vkp]       = h_lo;
                *(uint32_t*)&Vh[(d + 1) * AST + 2 * vkp] = h_hi;
                *(uint32_t*)&Vl[d * AST + 2 * vkp]       = l_lo;
                *(uint32_t*)&Vl[(d + 1) * AST + 2 * vkp] = l_hi;
            }
        }
        __syncthreads();

        // S = Q @ K^T : 3-term bf16, per-warp 32x32
        float sacc[2][4][4];
#pragma unroll
        for (int i = 0; i < 2; i++)
#pragma unroll
            for (int j = 0; j < 4; j++)
#pragma unroll
                for (int l = 0; l < 4; l++) sacc[i][j][l] = 0.f;
#pragma unroll
        for (int ks = 0; ks < 4; ks++) {
            const uint32_t kb = ks * 32 + lkb;
            uint32_t k0h[4], k1h[4], k0l[4], k1l[4];
            ldm_x4(k0h, uKh + (n0 + lrow) * (AST * 2) + kb);
            ldm_x4(k1h, uKh + (n0 + 16 + lrow) * (AST * 2) + kb);
            ldm_x4(k0l, uKl + (n0 + lrow) * (AST * 2) + kb);
            ldm_x4(k1l, uKl + (n0 + 16 + lrow) * (AST * 2) + kb);
#pragma unroll
            for (int mf = 0; mf < 2; mf++) {
                uint32_t qh[4], ql[4];
                ldm_x4(qh, uQh + (m0 + mf * 16 + lrow) * (AST * 2) + kb);
                ldm_x4(ql, uQl + (m0 + mf * 16 + lrow) * (AST * 2) + kb);
                mma16(sacc[mf][0], qh, k0h[0], k0h[2]);
                mma16(sacc[mf][1], qh, k0h[1], k0h[3]);
                mma16(sacc[mf][2], qh, k1h[0], k1h[2]);
                mma16(sacc[mf][3], qh, k1h[1], k1h[3]);
                mma16(sacc[mf][0], ql, k0h[0], k0h[2]);
                mma16(sacc[mf][1], ql, k0h[1], k0h[3]);
                mma16(sacc[mf][2], ql, k1h[0], k1h[2]);
                mma16(sacc[mf][3], ql, k1h[1], k1h[3]);
                mma16(sacc[mf][0], qh, k0l[0], k0l[2]);
                mma16(sacc[mf][1], qh, k0l[1], k0l[3]);
                mma16(sacc[mf][2], qh, k1l[0], k1l[2]);
                mma16(sacc[mf][3], qh, k1l[1], k1l[3]);
            }
        }

        // sigmoid + causal mask -> P (bf16 hi/lo, [m][kseq])
        const bool diag = (kt >= 2 * qt);
#pragma unroll
        for (int mf = 0; mf < 2; mf++) {
            int rl0 = m0 + mf * 16 + gid;
            int rg0 = qt * 128 + rl0;
#pragma unroll
            for (int nf = 0; nf < 4; nf++) {
                int cl = n0 + nf * 8 + 2 * tig;
                int cg = kt * 64 + cl;
                float s0 = sacc[mf][nf][0] * 0.125f + pbias;
                float s1 = sacc[mf][nf][1] * 0.125f + pbias;
                float s2 = sacc[mf][nf][2] * 0.125f + pbias;
                float s3 = sacc[mf][nf][3] * 0.125f + pbias;
                float p0 = __fdividef(1.f, 1.f + __expf(-s0));
                float p1 = __fdividef(1.f, 1.f + __expf(-s1));
                float p2 = __fdividef(1.f, 1.f + __expf(-s2));
                float p3 = __fdividef(1.f, 1.f + __expf(-s3));
                if (diag) {
                    if (cg > rg0)         p0 = 0.f;
                    if (cg + 1 > rg0)     p1 = 0.f;
                    if (cg > rg0 + 8)     p2 = 0.f;
                    if (cg + 1 > rg0 + 8) p3 = 0.f;
                }
                __nv_bfloat16 h0, l0, h1, l1, h2, l2, h3, l3;
                bf_split(p0, h0, l0); bf_split(p1, h1, l1);
                bf_split(p2, h2, l2); bf_split(p3, h3, l3);
                __nv_bfloat162 a;
                a.x = h0; a.y = h1; *(__nv_bfloat162*)&Ph[rl0 * AST + cl] = a;
                a.x = h2; a.y = h3; *(__nv_bfloat162*)&Ph[(rl0 + 8) * AST + cl] = a;
                a.x = l0; a.y = l1; *(__nv_bfloat162*)&Pl[rl0 * AST + cl] = a;
                a.x = l2; a.y = l3; *(__nv_bfloat162*)&Pl[(rl0 + 8) * AST + cl] = a;
            }
        }
        __syncthreads();

        // ctx += P @ V : 3-term bf16
#pragma unroll
        for (int ks = 0; ks < 4; ks++) {
            const uint32_t kb = ks * 32 + lkb;
            uint32_t v0h[4], v1h[4], v0l[4], v1l[4];
            ldm_x4(v0h, uVh + (n0 + lrow) * (AST * 2) + kb);
            ldm_x4(v1h, uVh + (n0 + 16 + lrow) * (AST * 2) + kb);
            ldm_x4(v0l, uVl + (n0 + lrow) * (AST * 2) + kb);
            ldm_x4(v1l, uVl + (n0 + 16 + lrow) * (AST * 2) + kb);
#pragma unroll
            for (int mf = 0; mf < 2; mf++) {
                uint32_t ph[4], pl[4];
                ldm_x4(ph, uPh + (m0 + mf * 16 + lrow) * (AST * 2) + kb);
                ldm_x4(pl, uPl + (m0 + mf * 16 + lrow) * (AST * 2) + kb);
                mma16(cacc[mf][0], ph, v0h[0], v0h[2]);
                mma16(cacc[mf][1], ph, v0h[1], v0h[3]);
                mma16(cacc[mf][2], ph, v1h[0], v1h[2]);
                mma16(cacc[mf][3], ph, v1h[1], v1h[3]);
                mma16(cacc[mf][0], pl, v0h[0], v0h[2]);
                mma16(cacc[mf][1], pl, v0h[1], v0h[3]);
                mma16(cacc[mf][2], pl, v1h[0], v1h[2]);
                mma16(cacc[mf][3], pl, v1h[1], v1h[3]);
                mma16(cacc[mf][0], ph, v0l[0], v0l[2]);
                mma16(cacc[mf][1], ph, v0l[1], v0l[3]);
                mma16(cacc[mf][2], ph, v1l[0], v1l[2]);
                mma16(cacc[mf][3], ph, v1l[1], v1l[3]);
            }
        }
    }

    // write ctx: [b, s, h*64 + d]
#pragma unroll
    for (int mf = 0; mf < 2; mf++) {
#pragma unroll
        for (int nf = 0; nf < 4; nf++) {
            int row = qt * 128 + m0 + mf * 16 + gid;
            int col = h * 64 + n0 + nf * 8 + 2 * tig;
            float2 o0 = {cacc[mf][nf][0], cacc[mf][nf][1]};
            float2 o1 = {cacc[mf][nf][2], cacc[mf][nf][3]};
            *(float2*)(ctx + (size_t)(b * SEQ + row) * DMODEL + col) = o0;
            *(float2*)(ctx + (size_t)(b * SEQ + row + 8) * DMODEL + col) = o1;
        }
    }
}

// ---------------------------------------------------------------------------
extern "C" void kernel_launch(void* const* d_in, const int* in_sizes, int n_in,
                              void* d_out, int out_size)
{
    const float* x      = (const float*)d_in[0];
    // d_in[1] = attention_mask (causal tril) — applied analytically, unused
    const float* ln_g   = (const float*)d_in[2];
    const float* ln_b   = (const float*)d_in[3];
    const float* w_qkv  = (const float*)d_in[4];
    const float* b_qkv  = (const float*)d_in[5];
    const float* w_gate = (const float*)d_in[6];
    const float* b_gate = (const float*)d_in[7];
    const float* w_out  = (const float*)d_in[8];
    const float* b_out  = (const float*)d_in[9];
    const float* rpb    = (const float*)d_in[10];
    float* out = (float*)d_out;

    __nv_bfloat16 *xnh, *xnl, *wqh, *wql, *wgh, *wgl, *woh, *wol, *ah, *al;
    __nv_bfloat16 *qkvh, *qkvl;
    float *u, *ctx;
    cudaGetSymbolAddress((void**)&xnh, g_xnh);
    cudaGetSymbolAddress((void**)&xnl, g_xnl);
    cudaGetSymbolAddress((void**)&wqh, g_wqh);
    cudaGetSymbolAddress((void**)&wql, g_wql);
    cudaGetSymbolAddress((void**)&wgh, g_wgh);
    cudaGetSymbolAddress((void**)&wgl, g_wgl);
    cudaGetSymbolAddress((void**)&woh, g_woh);
    cudaGetSymbolAddress((void**)&wol, g_wol);
    cudaGetSymbolAddress((void**)&qkvh, g_qkvh);
    cudaGetSymbolAddress((void**)&qkvl, g_qkvl);
    cudaGetSymbolAddress((void**)&u,   g_u);
    cudaGetSymbolAddress((void**)&ctx, g_ctx);
    cudaGetSymbolAddress((void**)&ah,  g_ah);
    cudaGetSymbolAddress((void**)&al,  g_al);

    cudaFuncSetAttribute(attn_kernel, cudaFuncAttributeMaxDynamicSharedMemorySize, ATTN_SMEM_B);
    cudaFuncSetAttribute(tgemm<0>, cudaFuncAttributeMaxDynamicSharedMemorySize, G_SMEM);
    cudaFuncSetAttribute(tgemm<1>, cudaFuncAttributeMaxDynamicSharedMemorySize, G_SMEM);
    cudaFuncSetAttribute(tgemm<2>, cudaFuncAttributeMaxDynamicSharedMemorySize, G_SMEM);

    wsplit_kernel<<<dim3(N_QKV / 32, DMODEL / 32), dim3(32, 8)>>>(w_qkv, wqh, wql, DMODEL, N_QKV);
    wsplit_kernel<<<dim3(DMODEL / 32, DMODEL / 32), dim3(32, 8)>>>(w_gate, wgh, wgl, DMODEL, DMODEL);
    wsplit_kernel<<<dim3(DMODEL / 32, DMODEL / 32), dim3(32, 8)>>>(w_out, woh, wol, DMODEL, DMODEL);

    ln_split_kernel<<<R_TOT, 256>>>(x, ln_g, ln_b, xnh, xnl);

    tgemm<0><<<dim3(N_QKV / 128, R_TOT / 128), 256, G_SMEM>>>(
        xnh, xnl, wqh, wql, b_qkv, nullptr, nullptr, qkvh, qkvl, R_TOT, N_QKV, DMODEL);

    tgemm<1><<<dim3(DMODEL / 128, R_TOT / 128), 256, G_SMEM>>>(
        xnh, xnl, wgh, wgl, b_gate, nullptr, u, nullptr, nullptr, R_TOT, DMODEL, DMODEL);

    attn_kernel<<<dim3(SEQ / 128, 2 * NHEAD), 256, ATTN_SMEM_B>>>(qkvh, qkvl, rpb, ctx);

    mulsplit_kernel<<<(R_TOT * DMODEL) / (256 * 4), 256>>>(ctx, u, ah, al);

    tgemm<2><<<dim3(DMODEL / 128, R_TOT / 128), 256, G_SMEM>>>(
        ah, al, woh, wol, b_out, x, out, nullptr, nullptr, R_TOT, DMODEL, DMODEL);
}

// round 8
// speedup vs baseline: 2.9568x; 1.4262x over previous
#include <cuda_runtime.h>
#include <cuda_fp16.h>
#include <cstdint>

#define R_TOT 4096
#define DMODEL 1024
#define N_QKV 3072
#define SEQ 2048
#define NHEAD 16

// ------------------------------ scratch (device globals) -------------------
__device__ __half g_xn[R_TOT * DMODEL];                       // activations, single fp16
__device__ __half g_wqh[N_QKV * DMODEL], g_wql[N_QKV * DMODEL];
__device__ __half g_wgh[DMODEL * DMODEL], g_wgl[DMODEL * DMODEL];
__device__ __half g_woh[DMODEL * DMODEL], g_wol[DMODEL * DMODEL];
__device__ __half g_qkvh[(size_t)R_TOT * N_QKV], g_qkvl[(size_t)R_TOT * N_QKV];
__device__ float g_u[R_TOT * DMODEL];
__device__ float g_ctx[R_TOT * DMODEL];
__device__ __half g_a[R_TOT * DMODEL];                        // ctx*u, single fp16

// ------------------------------ helpers ------------------------------------
__device__ __forceinline__ void h_split(float x, __half& h, __half& l) {
    h = __float2half_rn(x);
    l = __float2half_rn(x - __half2float(h));
}
__device__ __forceinline__ void mma16(float d[4], const uint32_t a[4], uint32_t b0, uint32_t b1) {
    asm volatile("mma.sync.aligned.m16n8k16.row.col.f32.f16.f16.f32 "
        "{%0,%1,%2,%3},{%4,%5,%6,%7},{%8,%9},{%0,%1,%2,%3};"
        : "+f"(d[0]), "+f"(d[1]), "+f"(d[2]), "+f"(d[3])
        : "r"(a[0]), "r"(a[1]), "r"(a[2]), "r"(a[3]), "r"(b0), "r"(b1));
}
__device__ __forceinline__ void ldm_x4(uint32_t r[4], uint32_t addr) {
    asm volatile("ldmatrix.sync.aligned.m8n8.x4.shared.b16 {%0,%1,%2,%3}, [%4];"
        : "=r"(r[0]), "=r"(r[1]), "=r"(r[2]), "=r"(r[3]) : "r"(addr));
}
__device__ __forceinline__ uint32_t smem_u32(const void* p) {
    return (uint32_t)__cvta_generic_to_shared(p);
}
#define CP16(dst, src) \
    asm volatile("cp.async.cg.shared.global [%0], [%1], 16;" \
        :: "r"(dst), "l"(__cvta_generic_to_global(src)) : "memory")
#define CP_COMMIT() asm volatile("cp.async.commit_group;" ::: "memory")
#define CP_WAIT0()  asm volatile("cp.async.wait_group 0;" ::: "memory")

// ------------------------------ LayerNorm -> single fp16 -------------------
__global__ __launch_bounds__(256) void ln_half_kernel(
    const float* __restrict__ x, const float* __restrict__ gamma,
    const float* __restrict__ beta, __half* __restrict__ xn)
{
    int row = blockIdx.x;
    int t = threadIdx.x;
    const float4* xr = (const float4*)(x + (size_t)row * DMODEL);
    float4 v = xr[t];
    float s  = v.x + v.y + v.z + v.w;
    float sq = v.x*v.x + v.y*v.y + v.z*v.z + v.w*v.w;
#pragma unroll
    for (int o = 16; o; o >>= 1) {
        s  += __shfl_xor_sync(0xffffffffu, s,  o);
        sq += __shfl_xor_sync(0xffffffffu, sq, o);
    }
    __shared__ float ss[8], sqq[8];
    int w = t >> 5, l = t & 31;
    if (l == 0) { ss[w] = s; sqq[w] = sq; }
    __syncthreads();
    if (w == 0) {
        s  = (l < 8) ? ss[l]  : 0.f;
        sq = (l < 8) ? sqq[l] : 0.f;
#pragma unroll
        for (int o = 4; o; o >>= 1) {
            s  += __shfl_xor_sync(0xffffffffu, s,  o);
            sq += __shfl_xor_sync(0xffffffffu, sq, o);
        }
        if (l == 0) { ss[0] = s; sqq[0] = sq; }
    }
    __syncthreads();
    float mean = ss[0] * (1.f / DMODEL);
    float var  = sqq[0] * (1.f / DMODEL) - mean * mean;
    float rstd = rsqrtf(var + 1e-5f);
    float4 g  = ((const float4*)gamma)[t];
    float4 bb = ((const float4*)beta)[t];
    __half2 p0, p1;
    p0.x = __float2half_rn((v.x - mean) * rstd * g.x + bb.x);
    p0.y = __float2half_rn((v.y - mean) * rstd * g.y + bb.y);
    p1.x = __float2half_rn((v.z - mean) * rstd * g.z + bb.z);
    p1.y = __float2half_rn((v.w - mean) * rstd * g.w + bb.w);
    uint2 o;
    o.x = *(uint32_t*)&p0; o.y = *(uint32_t*)&p1;
    *(uint2*)(xn + (size_t)row * DMODEL + t * 4) = o;
}

// --------------------- weight transpose + fp16 split ------------------------
__global__ void wsplit_kernel(const float* __restrict__ w,
                              __half* __restrict__ th,
                              __half* __restrict__ tl, int K, int N)
{
    __shared__ float t[32][33];
    int n0 = blockIdx.x * 32, k0 = blockIdx.y * 32;
    int tx = threadIdx.x, ty = threadIdx.y;
#pragma unroll
    for (int j = ty; j < 32; j += 8)
        t[j][tx] = w[(size_t)(k0 + j) * N + n0 + tx];
    __syncthreads();
#pragma unroll
    for (int j = ty; j < 32; j += 8) {
        float v = t[tx][j];
        __half h, l;
        h_split(v, h, l);
        th[(size_t)(n0 + j) * K + k0 + tx] = h;
        tl[(size_t)(n0 + j) * K + k0 + tx] = l;
    }
}

// --------------------- elementwise ctx*u -> single fp16 ---------------------
__global__ __launch_bounds__(256) void mulhalf_kernel(
    const float* __restrict__ ctx, const float* __restrict__ u,
    __half* __restrict__ a)
{
    size_t i = ((size_t)blockIdx.x * 256 + threadIdx.x) * 4;
    float4 c = *(const float4*)(ctx + i);
    float4 g = *(const float4*)(u + i);
    __half2 p0, p1;
    p0.x = __float2half_rn(c.x * g.x);
    p0.y = __float2half_rn(c.y * g.y);
    p1.x = __float2half_rn(c.z * g.z);
    p1.y = __float2half_rn(c.w * g.w);
    uint2 o;
    o.x = *(uint32_t*)&p0; o.y = *(uint32_t*)&p1;
    *(uint2*)(a + i) = o;
}

// ---------------------------------------------------------------------------
// fp16 GEMM, A single / B 2-split, 2 mma passes. cp.async double-buffer, BK=32.
// Block 128x128, 8 warps, warp tile 32x64.
// MODE 0: write fp16 hi/lo   MODE 1: SiLU -> fp32   MODE 2: +resid -> fp32
// stage = A(10240) Bh(10240) Bl(10240) = 30720 B, x2 stages
// ---------------------------------------------------------------------------
#define G_STAGE 30720u
#define G_SMEM  (2 * 30720)

template<int MODE>
__global__ __launch_bounds__(256) void tgemm(
    const __half* __restrict__ A,
    const __half* __restrict__ Bh, const __half* __restrict__ Bl,
    const float* __restrict__ bias, const float* __restrict__ resid,
    float* __restrict__ Cf, __half* __restrict__ Chh,
    __half* __restrict__ Cll, int M, int N, int K)
{
    extern __shared__ char gsm[];
    const uint32_t base = smem_u32(gsm);

    const int tid  = threadIdx.x;
    const int lane = tid & 31;
    const int gid  = lane >> 2, tig = lane & 3;
    const int wid  = tid >> 5;
    const int wm   = (wid & 3) * 32;
    const int wn   = (wid >> 2) * 64;
    const int mBase = blockIdx.y * 128, nBase = blockIdx.x * 128;
    const int lrow = lane & 15;
    const uint32_t lkb = (lane >> 4) * 16;

    float acc[2][8][4];
#pragma unroll
    for (int i = 0; i < 2; i++)
#pragma unroll
        for (int j = 0; j < 8; j++)
#pragma unroll
            for (int l = 0; l < 4; l++) acc[i][j][l] = 0.f;

    auto ld_stage = [&](int c, int s) {
        const uint32_t sb = base + (uint32_t)s * G_STAGE;
        const int kt = c * 32;
#pragma unroll
        for (int it = 0; it < 2; it++) {
            int idx = it * 256 + tid;
            int row = idx >> 2, seg = idx & 3;
            uint32_t d = sb + row * 80 + seg * 16;
            size_t aoff = (size_t)(mBase + row) * K + kt + seg * 8;
            size_t boff = (size_t)(nBase + row) * K + kt + seg * 8;
            CP16(d,          A  + aoff);
            CP16(d + 10240,  Bh + boff);
            CP16(d + 20480,  Bl + boff);
        }
    };

    ld_stage(0, 0); CP_COMMIT();
    const int NC = K / 32;
    for (int c = 0; c < NC; c++) {
        CP_WAIT0(); __syncthreads();
        if (c + 1 < NC) { ld_stage(c + 1, (c + 1) & 1); CP_COMMIT(); }
        const uint32_t sb = base + (uint32_t)(c & 1) * G_STAGE;
#pragma unroll
        for (int ks = 0; ks < 2; ks++) {
            const uint32_t kb = ks * 32 + lkb;
            uint32_t ar[2][4], bh[4][4], bl[4][4];
#pragma unroll
            for (int mf = 0; mf < 2; mf++)
                ldm_x4(ar[mf], sb + (wm + mf * 16 + lrow) * 80 + kb);
#pragma unroll
            for (int p = 0; p < 4; p++) {
                uint32_t rb = sb + 10240 + (wn + p * 16 + lrow) * 80 + kb;
                ldm_x4(bh[p], rb);
                ldm_x4(bl[p], rb + 10240);
            }
#pragma unroll
            for (int nf = 0; nf < 8; nf++)
#pragma unroll
                for (int mf = 0; mf < 2; mf++)
                    mma16(acc[mf][nf], ar[mf], bh[nf >> 1][nf & 1], bh[nf >> 1][(nf & 1) + 2]);
#pragma unroll
            for (int nf = 0; nf < 8; nf++)
#pragma unroll
                for (int mf = 0; mf < 2; mf++)
                    mma16(acc[mf][nf], ar[mf], bl[nf >> 1][nf & 1], bl[nf >> 1][(nf & 1) + 2]);
        }
    }

    // epilogue
#pragma unroll
    for (int mf = 0; mf < 2; mf++) {
#pragma unroll
        for (int nf = 0; nf < 8; nf++) {
            int row0 = mBase + wm + mf * 16 + gid;
            int col  = nBase + wn + nf * 8 + 2 * tig;
            float bx = bias[col], by = bias[col + 1];
            float v0 = acc[mf][nf][0] + bx;
            float v1 = acc[mf][nf][1] + by;
            float v2 = acc[mf][nf][2] + bx;
            float v3 = acc[mf][nf][3] + by;
            if (MODE == 0) {
                __half h0, l0, h1, l1, h2, l2, h3, l3;
                h_split(v0, h0, l0); h_split(v1, h1, l1);
                h_split(v2, h2, l2); h_split(v3, h3, l3);
                __half2 a;
                a.x = h0; a.y = h1;
                *(__half2*)(Chh + (size_t)row0 * N + col) = a;
                a.x = h2; a.y = h3;
                *(__half2*)(Chh + (size_t)(row0 + 8) * N + col) = a;
                a.x = l0; a.y = l1;
                *(__half2*)(Cll + (size_t)row0 * N + col) = a;
                a.x = l2; a.y = l3;
                *(__half2*)(Cll + (size_t)(row0 + 8) * N + col) = a;
            } else {
                if (MODE == 1) {
                    v0 = v0 / (1.f + __expf(-v0));
                    v1 = v1 / (1.f + __expf(-v1));
                    v2 = v2 / (1.f + __expf(-v2));
                    v3 = v3 / (1.f + __expf(-v3));
                }
                if (MODE == 2) {
                    const float* r0 = resid + (size_t)row0 * N + col;
                    const float* r1 = resid + (size_t)(row0 + 8) * N + col;
                    v0 += r0[0]; v1 += r0[1]; v2 += r1[0]; v3 += r1[1];
                }
                float2 o0 = {v0, v1}, o1 = {v2, v3};
                *(float2*)(Cf + (size_t)row0 * N + col) = o0;
                *(float2*)(Cf + (size_t)(row0 + 8) * N + col) = o1;
            }
        }
    }
}

// ---------------------------------------------------------------------------
// Fused causal sigmoid attention, fp16 A-single/B-split, 128-q-row tiles.
// Q single, K hi/lo, P single, V hi/lo. 8 warps, warp tile 32x32. smem 72 KB.
// ---------------------------------------------------------------------------
#define AST 72
#define ATTN_SMEM_B ((2 * 128 + 4 * 64) * AST * 2)

__global__ __launch_bounds__(256) void attn_kernel(
    const __half* __restrict__ qkvh, const __half* __restrict__ qkvl,
    const float* __restrict__ rpb, float* __restrict__ ctx)
{
    extern __shared__ __half smb[];
    __half* Qs = smb;
    __half* Ps = Qs + 128 * AST;
    __half* Kh = Ps + 128 * AST;
    __half* Kl = Kh + 64 * AST;
    __half* Vh = Kl + 64 * AST;
    __half* Vl = Vh + 64 * AST;
    const uint32_t uQ = smem_u32(Qs), uP = smem_u32(Ps);
    const uint32_t uKh = smem_u32(Kh), uKl = smem_u32(Kl);
    const uint32_t uVh = smem_u32(Vh), uVl = smem_u32(Vl);

    const int qt = 15 - (int)blockIdx.x;     // big tiles first
    const int bh = blockIdx.y;
    const int b = bh >> 4, h = bh & 15;
    const float pbias = rpb[h];
    const int tid  = threadIdx.x;
    const int lane = tid & 31;
    const int gid  = lane >> 2, tig = lane & 3;
    const int wid  = tid >> 5;
    const int m0   = (wid & 3) * 32;
    const int n0   = (wid >> 2) * 32;
    const int lrow = lane & 15;
    const uint32_t lkb = (lane >> 4) * 16;

    const size_t base = (size_t)(b * SEQ) * N_QKV + h * 64;
    const __half* qb  = qkvh + base;                 // Q single (hi part)
    const __half* kbh = qkvh + base + DMODEL;
    const __half* kbl = qkvl + base + DMODEL;
    const __half* vbh = qkvh + base + 2 * DMODEL;
    const __half* vbl = qkvl + base + 2 * DMODEL;

    // Q load: 128 rows x 64 cols, single
#pragma unroll
    for (int it = 0; it < 4; it++) {
        int idx = it * 256 + tid;
        int row = idx >> 3, seg = idx & 7;
        if (it < 4) {
            size_t off = (size_t)(qt * 128 + row) * N_QKV + seg * 8;
            *(uint4*)&Qs[row * AST + seg * 8] = *(const uint4*)(qb + off);
        }
    }

    float cacc[2][4][4];
#pragma unroll
    for (int i = 0; i < 2; i++)
#pragma unroll
        for (int j = 0; j < 4; j++)
#pragma unroll
            for (int l = 0; l < 4; l++) cacc[i][j][l] = 0.f;

    const int krow = tid >> 2;
    const int kc16 = (tid & 3) * 16;
    const int vkp = tid & 31;
    const int vd0 = (tid >> 5) * 8;

    const int nkt = 2 * qt + 2;
    for (int kt = 0; kt < nkt; kt++) {
        uint4 kh0, kh1, kl0, kl1, va0, va1, vb0, vb1;
        {
            size_t off = (size_t)(kt * 64 + krow) * N_QKV + kc16;
            kh0 = *(const uint4*)(kbh + off);
            kh1 = *(const uint4*)(kbh + off + 8);
            kl0 = *(const uint4*)(kbl + off);
            kl1 = *(const uint4*)(kbl + off + 8);
            size_t voff0 = (size_t)(kt * 64 + 2 * vkp) * N_QKV + vd0;
            size_t voff1 = voff0 + N_QKV;
            va0 = *(const uint4*)(vbh + voff0);
            va1 = *(const uint4*)(vbh + voff1);
            vb0 = *(const uint4*)(vbl + voff0);
            vb1 = *(const uint4*)(vbl + voff1);
        }
        __syncthreads();   // prev iter's reads of K/V/P done
        {
            *(uint4*)&Kh[krow * AST + kc16]     = kh0;
            *(uint4*)&Kh[krow * AST + kc16 + 8] = kh1;
            *(uint4*)&Kl[krow * AST + kc16]     = kl0;
            *(uint4*)&Kl[krow * AST + kc16 + 8] = kl1;
            const uint32_t* a0w = (const uint32_t*)&va0;
            const uint32_t* a1w = (const uint32_t*)&va1;
            const uint32_t* b0w = (const uint32_t*)&vb0;
            const uint32_t* b1w = (const uint32_t*)&vb1;
#pragma unroll
            for (int i = 0; i < 4; i++) {
                uint32_t h_lo = __byte_perm(a0w[i], a1w[i], 0x5410);
                uint32_t h_hi = __byte_perm(a0w[i], a1w[i], 0x7632);
                uint32_t l_lo = __byte_perm(b0w[i], b1w[i], 0x5410);
                uint32_t l_hi = __byte_perm(b0w[i], b1w[i], 0x7632);
                int d = vd0 + 2 * i;
                *(uint32_t*)&Vh[d * AST + 2 * vkp]       = h_lo;
                *(uint32_t*)&Vh[(d + 1) * AST + 2 * vkp] = h_hi;
                *(uint32_t*)&Vl[d * AST + 2 * vkp]       = l_lo;
                *(uint32_t*)&Vl[(d + 1) * AST + 2 * vkp] = l_hi;
            }
        }
        __syncthreads();

        // S = Q @ K^T : q single, k hi/lo (2 passes)
        float sacc[2][4][4];
#pragma unroll
        for (int i = 0; i < 2; i++)
#pragma unroll
            for (int j = 0; j < 4; j++)
#pragma unroll
                for (int l = 0; l < 4; l++) sacc[i][j][l] = 0.f;
#pragma unroll
        for (int ks = 0; ks < 4; ks++) {
            const uint32_t kb = ks * 32 + lkb;
            uint32_t k0h[4], k1h[4], k0l[4], k1l[4];
            ldm_x4(k0h, uKh + (n0 + lrow) * (AST * 2) + kb);
            ldm_x4(k1h, uKh + (n0 + 16 + lrow) * (AST * 2) + kb);
            ldm_x4(k0l, uKl + (n0 + lrow) * (AST * 2) + kb);
            ldm_x4(k1l, uKl + (n0 + 16 + lrow) * (AST * 2) + kb);
#pragma unroll
            for (int mf = 0; mf < 2; mf++) {
                uint32_t qh[4];
                ldm_x4(qh, uQ + (m0 + mf * 16 + lrow) * (AST * 2) + kb);
                mma16(sacc[mf][0], qh, k0h[0], k0h[2]);
                mma16(sacc[mf][1], qh, k0h[1], k0h[3]);
                mma16(sacc[mf][2], qh, k1h[0], k1h[2]);
                mma16(sacc[mf][3], qh, k1h[1], k1h[3]);
                mma16(sacc[mf][0], qh, k0l[0], k0l[2]);
                mma16(sacc[mf][1], qh, k0l[1], k0l[3]);
                mma16(sacc[mf][2], qh, k1l[0], k1l[2]);
                mma16(sacc[mf][3], qh, k1l[1], k1l[3]);
            }
        }

        // sigmoid + causal mask -> P (single fp16, [m][kseq])
        const bool diag = (kt >= 2 * qt);
#pragma unroll
        for (int mf = 0; mf < 2; mf++) {
            int rl0 = m0 + mf * 16 + gid;
            int rg0 = qt * 128 + rl0;
#pragma unroll
            for (int nf = 0; nf < 4; nf++) {
                int cl = n0 + nf * 8 + 2 * tig;
                int cg = kt * 64 + cl;
                float s0 = sacc[mf][nf][0] * 0.125f + pbias;
                float s1 = sacc[mf][nf][1] * 0.125f + pbias;
                float s2 = sacc[mf][nf][2] * 0.125f + pbias;
                float s3 = sacc[mf][nf][3] * 0.125f + pbias;
                float p0 = __fdividef(1.f, 1.f + __expf(-s0));
                float p1 = __fdividef(1.f, 1.f + __expf(-s1));
                float p2 = __fdividef(1.f, 1.f + __expf(-s2));
                float p3 = __fdividef(1.f, 1.f + __expf(-s3));
                if (diag) {
                    if (cg > rg0)         p0 = 0.f;
                    if (cg + 1 > rg0)     p1 = 0.f;
                    if (cg > rg0 + 8)     p2 = 0.f;
                    if (cg + 1 > rg0 + 8) p3 = 0.f;
                }
                __half2 a;
                a.x = __float2half_rn(p0); a.y = __float2half_rn(p1);
                *(__half2*)&Ps[rl0 * AST + cl] = a;
                a.x = __float2half_rn(p2); a.y = __float2half_rn(p3);
                *(__half2*)&Ps[(rl0 + 8) * AST + cl] = a;
            }
        }
        __syncthreads();

        // ctx += P @ V : p single, v hi/lo (2 passes)
#pragma unroll
        for (int ks = 0; ks < 4; ks++) {
            const uint32_t kb = ks * 32 + lkb;
            uint32_t v0h[4], v1h[4], v0l[4], v1l[4];
            ldm_x4(v0h, uVh + (n0 + lrow) * (AST * 2) + kb);
            ldm_x4(v1h, uVh + (n0 + 16 + lrow) * (AST * 2) + kb);
            ldm_x4(v0l, uVl + (n0 + lrow) * (AST * 2) + kb);
            ldm_x4(v1l, uVl + (n0 + 16 + lrow) * (AST * 2) + kb);
#pragma unroll
            for (int mf = 0; mf < 2; mf++) {
                uint32_t ph[4];
                ldm_x4(ph, uP + (m0 + mf * 16 + lrow) * (AST * 2) + kb);
                mma16(cacc[mf][0], ph, v0h[0], v0h[2]);
                mma16(cacc[mf][1], ph, v0h[1], v0h[3]);
                mma16(cacc[mf][2], ph, v1h[0], v1h[2]);
                mma16(cacc[mf][3], ph, v1h[1], v1h[3]);
                mma16(cacc[mf][0], ph, v0l[0], v0l[2]);
                mma16(cacc[mf][1], ph, v0l[1], v0l[3]);
                mma16(cacc[mf][2], ph, v1l[0], v1l[2]);
                mma16(cacc[mf][3], ph, v1l[1], v1l[3]);
            }
        }
    }

    // write ctx: [b, s, h*64 + d]
#pragma unroll
    for (int mf = 0; mf < 2; mf++) {
#pragma unroll
        for (int nf = 0; nf < 4; nf++) {
            int row = qt * 128 + m0 + mf * 16 + gid;
            int col = h * 64 + n0 + nf * 8 + 2 * tig;
            float2 o0 = {cacc[mf][nf][0], cacc[mf][nf][1]};
            float2 o1 = {cacc[mf][nf][2], cacc[mf][nf][3]};
            *(float2*)(ctx + (size_t)(b * SEQ + row) * DMODEL + col) = o0;
            *(float2*)(ctx + (size_t)(b * SEQ + row + 8) * DMODEL + col) = o1;
        }
    }
}

// ---------------------------------------------------------------------------
extern "C" void kernel_launch(void* const* d_in, const int* in_sizes, int n_in,
                              void* d_out, int out_size)
{
    const float* x      = (const float*)d_in[0];
    // d_in[1] = attention_mask (causal tril) — applied analytically, unused
    const float* ln_g   = (const float*)d_in[2];
    const float* ln_b   = (const float*)d_in[3];
    const float* w_qkv  = (const float*)d_in[4];
    const float* b_qkv  = (const float*)d_in[5];
    const float* w_gate = (const float*)d_in[6];
    const float* b_gate = (const float*)d_in[7];
    const float* w_out  = (const float*)d_in[8];
    const float* b_out  = (const float*)d_in[9];
    const float* rpb    = (const float*)d_in[10];
    float* out = (float*)d_out;

    __half *xn, *wqh, *wql, *wgh, *wgl, *woh, *wol, *a;
    __half *qkvh, *qkvl;
    float *u, *ctx;
    cudaGetSymbolAddress((void**)&xn,  g_xn);
    cudaGetSymbolAddress((void**)&wqh, g_wqh);
    cudaGetSymbolAddress((void**)&wql, g_wql);
    cudaGetSymbolAddress((void**)&wgh, g_wgh);
    cudaGetSymbolAddress((void**)&wgl, g_wgl);
    cudaGetSymbolAddress((void**)&woh, g_woh);
    cudaGetSymbolAddress((void**)&wol, g_wol);
    cudaGetSymbolAddress((void**)&qkvh, g_qkvh);
    cudaGetSymbolAddress((void**)&qkvl, g_qkvl);
    cudaGetSymbolAddress((void**)&u,   g_u);
    cudaGetSymbolAddress((void**)&ctx, g_ctx);
    cudaGetSymbolAddress((void**)&a,   g_a);

    cudaFuncSetAttribute(attn_kernel, cudaFuncAttributeMaxDynamicSharedMemorySize, ATTN_SMEM_B);
    cudaFuncSetAttribute(tgemm<0>, cudaFuncAttributeMaxDynamicSharedMemorySize, G_SMEM);
    cudaFuncSetAttribute(tgemm<1>, cudaFuncAttributeMaxDynamicSharedMemorySize, G_SMEM);
    cudaFuncSetAttribute(tgemm<2>, cudaFuncAttributeMaxDynamicSharedMemorySize, G_SMEM);

    wsplit_kernel<<<dim3(N_QKV / 32, DMODEL / 32), dim3(32, 8)>>>(w_qkv, wqh, wql, DMODEL, N_QKV);
    wsplit_kernel<<<dim3(DMODEL / 32, DMODEL / 32), dim3(32, 8)>>>(w_gate, wgh, wgl, DMODEL, DMODEL);
    wsplit_kernel<<<dim3(DMODEL / 32, DMODEL / 32), dim3(32, 8)>>>(w_out, woh, wol, DMODEL, DMODEL);

    ln_half_kernel<<<R_TOT, 256>>>(x, ln_g, ln_b, xn);

    tgemm<0><<<dim3(N_QKV / 128, R_TOT / 128), 256, G_SMEM>>>(
        xn, wqh, wql, b_qkv, nullptr, nullptr, qkvh, qkvl, R_TOT, N_QKV, DMODEL);

    tgemm<1><<<dim3(DMODEL / 128, R_TOT / 128), 256, G_SMEM>>>(
        xn, wgh, wgl, b_gate, nullptr, u, nullptr, nullptr, R_TOT, DMODEL, DMODEL);

    attn_kernel<<<dim3(SEQ / 128, 2 * NHEAD), 256, ATTN_SMEM_B>>>(qkvh, qkvl, rpb, ctx);

    mulhalf_kernel<<<(R_TOT * DMODEL) / (256 * 4), 256>>>(ctx, u, a);

    tgemm<2><<<dim3(DMODEL / 128, R_TOT / 128), 256, G_SMEM>>>(
        a, woh, wol, b_out, x, out, nullptr, nullptr, R_TOT, DMODEL, DMODEL);
}

// round 9
// speedup vs baseline: 3.5541x; 1.2020x over previous
#include <cuda_runtime.h>
#include <cuda_fp16.h>
#include <cstdint>

#define R_TOT 4096
#define DMODEL 1024
#define N_QKV 3072
#define SEQ 2048
#define NHEAD 16

// ------------------------------ scratch (device globals) -------------------
__device__ __half g_xn[R_TOT * DMODEL];                       // activations, single fp16
__device__ __half g_wqh[N_QKV * DMODEL], g_wql[N_QKV * DMODEL];
__device__ __half g_wgh[DMODEL * DMODEL], g_wgl[DMODEL * DMODEL];
__device__ __half g_woh[DMODEL * DMODEL], g_wol[DMODEL * DMODEL];
__device__ __half g_qkvh[(size_t)R_TOT * N_QKV], g_qkvl[(size_t)R_TOT * N_QKV];
__device__ float g_u[R_TOT * DMODEL];
__device__ __half g_a[R_TOT * DMODEL];                        // ctx*u, single fp16

// ------------------------------ helpers ------------------------------------
__device__ __forceinline__ void h_split(float x, __half& h, __half& l) {
    h = __float2half_rn(x);
    l = __float2half_rn(x - __half2float(h));
}
__device__ __forceinline__ void mma16(float d[4], const uint32_t a[4], uint32_t b0, uint32_t b1) {
    asm volatile("mma.sync.aligned.m16n8k16.row.col.f32.f16.f16.f32 "
        "{%0,%1,%2,%3},{%4,%5,%6,%7},{%8,%9},{%0,%1,%2,%3};"
        : "+f"(d[0]), "+f"(d[1]), "+f"(d[2]), "+f"(d[3])
        : "r"(a[0]), "r"(a[1]), "r"(a[2]), "r"(a[3]), "r"(b0), "r"(b1));
}
__device__ __forceinline__ void ldm_x4(uint32_t r[4], uint32_t addr) {
    asm volatile("ldmatrix.sync.aligned.m8n8.x4.shared.b16 {%0,%1,%2,%3}, [%4];"
        : "=r"(r[0]), "=r"(r[1]), "=r"(r[2]), "=r"(r[3]) : "r"(addr));
}
__device__ __forceinline__ uint32_t smem_u32(const void* p) {
    return (uint32_t)__cvta_generic_to_shared(p);
}
#define CP16(dst, src) \
    asm volatile("cp.async.cg.shared.global [%0], [%1], 16;" \
        :: "r"(dst), "l"(__cvta_generic_to_global(src)) : "memory")
#define CP_COMMIT() asm volatile("cp.async.commit_group;" ::: "memory")
#define CP_WAIT0()  asm volatile("cp.async.wait_group 0;" ::: "memory")

// ------------------------------ LayerNorm -> single fp16 -------------------
__global__ __launch_bounds__(256) void ln_half_kernel(
    const float* __restrict__ x, const float* __restrict__ gamma,
    const float* __restrict__ beta, __half* __restrict__ xn)
{
    int row = blockIdx.x;
    int t = threadIdx.x;
    const float4* xr = (const float4*)(x + (size_t)row * DMODEL);
    float4 v = xr[t];
    float s  = v.x + v.y + v.z + v.w;
    float sq = v.x*v.x + v.y*v.y + v.z*v.z + v.w*v.w;
#pragma unroll
    for (int o = 16; o; o >>= 1) {
        s  += __shfl_xor_sync(0xffffffffu, s,  o);
        sq += __shfl_xor_sync(0xffffffffu, sq, o);
    }
    __shared__ float ss[8], sqq[8];
    int w = t >> 5, l = t & 31;
    if (l == 0) { ss[w] = s; sqq[w] = sq; }
    __syncthreads();
    if (w == 0) {
        s  = (l < 8) ? ss[l]  : 0.f;
        sq = (l < 8) ? sqq[l] : 0.f;
#pragma unroll
        for (int o = 4; o; o >>= 1) {
            s  += __shfl_xor_sync(0xffffffffu, s,  o);
            sq += __shfl_xor_sync(0xffffffffu, sq, o);
        }
        if (l == 0) { ss[0] = s; sqq[0] = sq; }
    }
    __syncthreads();
    float mean = ss[0] * (1.f / DMODEL);
    float var  = sqq[0] * (1.f / DMODEL) - mean * mean;
    float rstd = rsqrtf(var + 1e-5f);
    float4 g  = ((const float4*)gamma)[t];
    float4 bb = ((const float4*)beta)[t];
    __half2 p0, p1;
    p0.x = __float2half_rn((v.x - mean) * rstd * g.x + bb.x);
    p0.y = __float2half_rn((v.y - mean) * rstd * g.y + bb.y);
    p1.x = __float2half_rn((v.z - mean) * rstd * g.z + bb.z);
    p1.y = __float2half_rn((v.w - mean) * rstd * g.w + bb.w);
    uint2 o;
    o.x = *(uint32_t*)&p0; o.y = *(uint32_t*)&p1;
    *(uint2*)(xn + (size_t)row * DMODEL + t * 4) = o;
}

// --------------------- weight transpose + fp16 split ------------------------
__global__ void wsplit_kernel(const float* __restrict__ w,
                              __half* __restrict__ th,
                              __half* __restrict__ tl, int K, int N)
{
    __shared__ float t[32][33];
    int n0 = blockIdx.x * 32, k0 = blockIdx.y * 32;
    int tx = threadIdx.x, ty = threadIdx.y;
#pragma unroll
    for (int j = ty; j < 32; j += 8)
        t[j][tx] = w[(size_t)(k0 + j) * N + n0 + tx];
    __syncthreads();
#pragma unroll
    for (int j = ty; j < 32; j += 8) {
        float v = t[tx][j];
        __half h, l;
        h_split(v, h, l);
        th[(size_t)(n0 + j) * K + k0 + tx] = h;
        tl[(size_t)(n0 + j) * K + k0 + tx] = l;
    }
}

// ---------------------------------------------------------------------------
// fp16 GEMM core: A single / B 2-split, cp.async double-buffer, BK=32.
// Block 128x128, 8 warps, warp tile 32x64. K = 1024 fixed.
// FUSED=1: qkv+gate merged (nBase<3072 -> fp16 hi/lo qkv; else SiLU -> u fp32)
// FUSED=0: out-proj (+resid -> fp32 out)
// stage = A(10240) Bh(10240) Bl(10240) = 30720 B, x2 stages
// ---------------------------------------------------------------------------
#define G_STAGE 30720u
#define G_SMEM  (2 * 30720)

template<int FUSED>
__global__ __launch_bounds__(256) void tgemm(
    const __half* __restrict__ A,
    const __half* __restrict__ BqH, const __half* __restrict__ BqL,
    const __half* __restrict__ BgH, const __half* __restrict__ BgL,
    const float* __restrict__ bias_q, const float* __restrict__ bias_g,
    const float* __restrict__ resid,
    float* __restrict__ Cf, __half* __restrict__ Chh, __half* __restrict__ Cll)
{
    extern __shared__ char gsm[];
    const uint32_t base = smem_u32(gsm);
    const int K = DMODEL;

    const int tid  = threadIdx.x;
    const int lane = tid & 31;
    const int gid  = lane >> 2, tig = lane & 3;
    const int wid  = tid >> 5;
    const int wm   = (wid & 3) * 32;
    const int wn   = (wid >> 2) * 64;
    const int mBase = blockIdx.y * 128, nBase = blockIdx.x * 128;
    const int lrow = lane & 15;
    const uint32_t lkb = (lane >> 4) * 16;

    // select B source / epilogue region (uniform per block)
    const bool isQ = (!FUSED) || (nBase < N_QKV);
    const __half* Bh = FUSED ? (isQ ? BqH + (size_t)nBase * K
                                    : BgH + (size_t)(nBase - N_QKV) * K)
                             : BqH + (size_t)nBase * K;
    const __half* Bl = FUSED ? (isQ ? BqL + (size_t)nBase * K
                                    : BgL + (size_t)(nBase - N_QKV) * K)
                             : BqL + (size_t)nBase * K;
    const float* bias = (FUSED && !isQ) ? bias_g : bias_q;
    const int biasOff = (FUSED) ? (isQ ? nBase : nBase - N_QKV) : nBase;

    float acc[2][8][4];
#pragma unroll
    for (int i = 0; i < 2; i++)
#pragma unroll
        for (int j = 0; j < 8; j++)
#pragma unroll
            for (int l = 0; l < 4; l++) acc[i][j][l] = 0.f;

    auto ld_stage = [&](int c, int s) {
        const uint32_t sb = base + (uint32_t)s * G_STAGE;
        const int kt = c * 32;
#pragma unroll
        for (int it = 0; it < 2; it++) {
            int idx = it * 256 + tid;
            int row = idx >> 2, seg = idx & 3;
            uint32_t d = sb + row * 80 + seg * 16;
            size_t aoff = (size_t)(mBase + row) * K + kt + seg * 8;
            size_t boff = (size_t)row * K + kt + seg * 8;
            CP16(d,          A  + aoff);
            CP16(d + 10240,  Bh + boff);
            CP16(d + 20480,  Bl + boff);
        }
    };

    ld_stage(0, 0); CP_COMMIT();
    const int NC = K / 32;
    for (int c = 0; c < NC; c++) {
        CP_WAIT0(); __syncthreads();
        if (c + 1 < NC) { ld_stage(c + 1, (c + 1) & 1); CP_COMMIT(); }
        const uint32_t sb = base + (uint32_t)(c & 1) * G_STAGE;
#pragma unroll
        for (int ks = 0; ks < 2; ks++) {
            const uint32_t kb = ks * 32 + lkb;
            uint32_t ar[2][4], bh[4][4], bl[4][4];
#pragma unroll
            for (int mf = 0; mf < 2; mf++)
                ldm_x4(ar[mf], sb + (wm + mf * 16 + lrow) * 80 + kb);
#pragma unroll
            for (int p = 0; p < 4; p++) {
                uint32_t rb = sb + 10240 + (wn + p * 16 + lrow) * 80 + kb;
                ldm_x4(bh[p], rb);
                ldm_x4(bl[p], rb + 10240);
            }
#pragma unroll
            for (int nf = 0; nf < 8; nf++)
#pragma unroll
                for (int mf = 0; mf < 2; mf++)
                    mma16(acc[mf][nf], ar[mf], bh[nf >> 1][nf & 1], bh[nf >> 1][(nf & 1) + 2]);
#pragma unroll
            for (int nf = 0; nf < 8; nf++)
#pragma unroll
                for (int mf = 0; mf < 2; mf++)
                    mma16(acc[mf][nf], ar[mf], bl[nf >> 1][nf & 1], bl[nf >> 1][(nf & 1) + 2]);
        }
    }

    // epilogue
#pragma unroll
    for (int mf = 0; mf < 2; mf++) {
#pragma unroll
        for (int nf = 0; nf < 8; nf++) {
            int row0 = mBase + wm + mf * 16 + gid;
            int colL = biasOff + wn + nf * 8 + 2 * tig;   // col in local output
            float bx = bias[colL], by = bias[colL + 1];
            float v0 = acc[mf][nf][0] + bx;
            float v1 = acc[mf][nf][1] + by;
            float v2 = acc[mf][nf][2] + bx;
            float v3 = acc[mf][nf][3] + by;
            if (FUSED && isQ) {
                __half h0, l0, h1, l1, h2, l2, h3, l3;
                h_split(v0, h0, l0); h_split(v1, h1, l1);
                h_split(v2, h2, l2); h_split(v3, h3, l3);
                __half2 a;
                a.x = h0; a.y = h1;
                *(__half2*)(Chh + (size_t)row0 * N_QKV + colL) = a;
                a.x = h2; a.y = h3;
                *(__half2*)(Chh + (size_t)(row0 + 8) * N_QKV + colL) = a;
                a.x = l0; a.y = l1;
                *(__half2*)(Cll + (size_t)row0 * N_QKV + colL) = a;
                a.x = l2; a.y = l3;
                *(__half2*)(Cll + (size_t)(row0 + 8) * N_QKV + colL) = a;
            } else if (FUSED) {   // gate region: SiLU -> u fp32
                v0 = v0 / (1.f + __expf(-v0));
                v1 = v1 / (1.f + __expf(-v1));
                v2 = v2 / (1.f + __expf(-v2));
                v3 = v3 / (1.f + __expf(-v3));
                float2 o0 = {v0, v1}, o1 = {v2, v3};
                *(float2*)(Cf + (size_t)row0 * DMODEL + colL) = o0;
                *(float2*)(Cf + (size_t)(row0 + 8) * DMODEL + colL) = o1;
            } else {              // out-proj: +resid -> fp32
                const float* r0 = resid + (size_t)row0 * DMODEL + colL;
                const float* r1 = resid + (size_t)(row0 + 8) * DMODEL + colL;
                v0 += r0[0]; v1 += r0[1]; v2 += r1[0]; v3 += r1[1];
                float2 o0 = {v0, v1}, o1 = {v2, v3};
                *(float2*)(Cf + (size_t)row0 * DMODEL + colL) = o0;
                *(float2*)(Cf + (size_t)(row0 + 8) * DMODEL + colL) = o1;
            }
        }
    }
}

// ---------------------------------------------------------------------------
// Fused causal sigmoid attention, fp16, 128-q-row tiles.
// Q single, K hi/lo (2-pass QK), P single, V single (1-pass PV).
// Epilogue: ctx * u -> fp16 `a` directly. 8 warps, warp tile 32x32.
// smem: Q 128 + P 128 + Kh 64 + Kl 64 + Vh 64 rows of AST halfs = 64512 B
// ---------------------------------------------------------------------------
#define AST 72
#define ATTN_SMEM_B ((2 * 128 + 3 * 64) * AST * 2)

__global__ __launch_bounds__(256) void attn_kernel(
    const __half* __restrict__ qkvh, const __half* __restrict__ qkvl,
    const float* __restrict__ rpb, const float* __restrict__ u,
    __half* __restrict__ aout)
{
    extern __shared__ __half smb[];
    __half* Qs = smb;
    __half* Ps = Qs + 128 * AST;
    __half* Kh = Ps + 128 * AST;
    __half* Kl = Kh + 64 * AST;
    __half* Vh = Kl + 64 * AST;
    const uint32_t uQ = smem_u32(Qs), uP = smem_u32(Ps);
    const uint32_t uKh = smem_u32(Kh), uKl = smem_u32(Kl);
    const uint32_t uVh = smem_u32(Vh);

    const int qt = 15 - (int)blockIdx.x;     // big tiles first
    const int bh = blockIdx.y;
    const int b = bh >> 4, h = bh & 15;
    const float pbias = rpb[h];
    const int tid  = threadIdx.x;
    const int lane = tid & 31;
    const int gid  = lane >> 2, tig = lane & 3;
    const int wid  = tid >> 5;
    const int m0   = (wid & 3) * 32;
    const int n0   = (wid >> 2) * 32;
    const int lrow = lane & 15;
    const uint32_t lkb = (lane >> 4) * 16;

    const size_t base = (size_t)(b * SEQ) * N_QKV + h * 64;
    const __half* qb  = qkvh + base;
    const __half* kbh = qkvh + base + DMODEL;
    const __half* kbl = qkvl + base + DMODEL;
    const __half* vbh = qkvh + base + 2 * DMODEL;

    // Q load: 128 rows x 64 cols, single
#pragma unroll
    for (int it = 0; it < 4; it++) {
        int idx = it * 256 + tid;
        int row = idx >> 3, seg = idx & 7;
        size_t off = (size_t)(qt * 128 + row) * N_QKV + seg * 8;
        *(uint4*)&Qs[row * AST + seg * 8] = *(const uint4*)(qb + off);
    }

    float cacc[2][4][4];
#pragma unroll
    for (int i = 0; i < 2; i++)
#pragma unroll
        for (int j = 0; j < 4; j++)
#pragma unroll
            for (int l = 0; l < 4; l++) cacc[i][j][l] = 0.f;

    const int krow = tid >> 2;
    const int kc16 = (tid & 3) * 16;
    const int vkp = tid & 31;
    const int vd0 = (tid >> 5) * 8;

    const int nkt = 2 * qt + 2;
    for (int kt = 0; kt < nkt; kt++) {
        uint4 kh0, kh1, kl0, kl1, va0, va1;
        {
            size_t off = (size_t)(kt * 64 + krow) * N_QKV + kc16;
            kh0 = *(const uint4*)(kbh + off);
            kh1 = *(const uint4*)(kbh + off + 8);
            kl0 = *(const uint4*)(kbl + off);
            kl1 = *(const uint4*)(kbl + off + 8);
            size_t voff0 = (size_t)(kt * 64 + 2 * vkp) * N_QKV + vd0;
            va0 = *(const uint4*)(vbh + voff0);
            va1 = *(const uint4*)(vbh + voff0 + N_QKV);
        }
        __syncthreads();   // prev iter's reads of K/V/P done
        {
            *(uint4*)&Kh[krow * AST + kc16]     = kh0;
            *(uint4*)&Kh[krow * AST + kc16 + 8] = kh1;
            *(uint4*)&Kl[krow * AST + kc16]     = kl0;
            *(uint4*)&Kl[krow * AST + kc16 + 8] = kl1;
            const uint32_t* a0w = (const uint32_t*)&va0;
            const uint32_t* a1w = (const uint32_t*)&va1;
#pragma unroll
            for (int i = 0; i < 4; i++) {
                uint32_t h_lo = __byte_perm(a0w[i], a1w[i], 0x5410);
                uint32_t h_hi = __byte_perm(a0w[i], a1w[i], 0x7632);
                int d = vd0 + 2 * i;
                *(uint32_t*)&Vh[d * AST + 2 * vkp]       = h_lo;
                *(uint32_t*)&Vh[(d + 1) * AST + 2 * vkp] = h_hi;
            }
        }
        __syncthreads();

        // S = Q @ K^T : q single, k hi/lo (2 passes)
        float sacc[2][4][4];
#pragma unroll
        for (int i = 0; i < 2; i++)
#pragma unroll
            for (int j = 0; j < 4; j++)
#pragma unroll
                for (int l = 0; l < 4; l++) sacc[i][j][l] = 0.f;
#pragma unroll
        for (int ks = 0; ks < 4; ks++) {
            const uint32_t kb = ks * 32 + lkb;
            uint32_t k0h[4], k1h[4], k0l[4], k1l[4];
            ldm_x4(k0h, uKh + (n0 + lrow) * (AST * 2) + kb);
            ldm_x4(k1h, uKh + (n0 + 16 + lrow) * (AST * 2) + kb);
            ldm_x4(k0l, uKl + (n0 + lrow) * (AST * 2) + kb);
            ldm_x4(k1l, uKl + (n0 + 16 + lrow) * (AST * 2) + kb);
#pragma unroll
            for (int mf = 0; mf < 2; mf++) {
                uint32_t qh[4];
                ldm_x4(qh, uQ + (m0 + mf * 16 + lrow) * (AST * 2) + kb);
                mma16(sacc[mf][0], qh, k0h[0], k0h[2]);
                mma16(sacc[mf][1], qh, k0h[1], k0h[3]);
                mma16(sacc[mf][2], qh, k1h[0], k1h[2]);
                mma16(sacc[mf][3], qh, k1h[1], k1h[3]);
                mma16(sacc[mf][0], qh, k0l[0], k0l[2]);
                mma16(sacc[mf][1], qh, k0l[1], k0l[3]);
                mma16(sacc[mf][2], qh, k1l[0], k1l[2]);
                mma16(sacc[mf][3], qh, k1l[1], k1l[3]);
            }
        }

        // sigmoid + causal mask -> P (single fp16, [m][kseq])
        const bool diag = (kt >= 2 * qt);
#pragma unroll
        for (int mf = 0; mf < 2; mf++) {
            int rl0 = m0 + mf * 16 + gid;
            int rg0 = qt * 128 + rl0;
#pragma unroll
            for (int nf = 0; nf < 4; nf++) {
                int cl = n0 + nf * 8 + 2 * tig;
                int cg = kt * 64 + cl;
                float s0 = sacc[mf][nf][0] * 0.125f + pbias;
                float s1 = sacc[mf][nf][1] * 0.125f + pbias;
                float s2 = sacc[mf][nf][2] * 0.125f + pbias;
                float s3 = sacc[mf][nf][3] * 0.125f + pbias;
                float p0 = __fdividef(1.f, 1.f + __expf(-s0));
                float p1 = __fdividef(1.f, 1.f + __expf(-s1));
                float p2 = __fdividef(1.f, 1.f + __expf(-s2));
                float p3 = __fdividef(1.f, 1.f + __expf(-s3));
                if (diag) {
                    if (cg > rg0)         p0 = 0.f;
                    if (cg + 1 > rg0)     p1 = 0.f;
                    if (cg > rg0 + 8)     p2 = 0.f;
                    if (cg + 1 > rg0 + 8) p3 = 0.f;
                }
                __half2 a;
                a.x = __float2half_rn(p0); a.y = __float2half_rn(p1);
                *(__half2*)&Ps[rl0 * AST + cl] = a;
                a.x = __float2half_rn(p2); a.y = __float2half_rn(p3);
                *(__half2*)&Ps[(rl0 + 8) * AST + cl] = a;
            }
        }
        __syncthreads();

        // ctx += P @ V : p single, v single (1 pass)
#pragma unroll
        for (int ks = 0; ks < 4; ks++) {
            const uint32_t kb = ks * 32 + lkb;
            uint32_t v0h[4], v1h[4];
            ldm_x4(v0h, uVh + (n0 + lrow) * (AST * 2) + kb);
            ldm_x4(v1h, uVh + (n0 + 16 + lrow) * (AST * 2) + kb);
#pragma unroll
            for (int mf = 0; mf < 2; mf++) {
                uint32_t ph[4];
                ldm_x4(ph, uP + (m0 + mf * 16 + lrow) * (AST * 2) + kb);
                mma16(cacc[mf][0], ph, v0h[0], v0h[2]);
                mma16(cacc[mf][1], ph, v0h[1], v0h[3]);
                mma16(cacc[mf][2], ph, v1h[0], v1h[2]);
                mma16(cacc[mf][3], ph, v1h[1], v1h[3]);
            }
        }
    }

    // epilogue: a = half(ctx * u), layout [b, s, h*64 + d]
#pragma unroll
    for (int mf = 0; mf < 2; mf++) {
#pragma unroll
        for (int nf = 0; nf < 4; nf++) {
            int row = qt * 128 + m0 + mf * 16 + gid;
            int col = h * 64 + n0 + nf * 8 + 2 * tig;
            size_t o0i = (size_t)(b * SEQ + row) * DMODEL + col;
            size_t o1i = (size_t)(b * SEQ + row + 8) * DMODEL + col;
            float2 u0 = *(const float2*)(u + o0i);
            float2 u1 = *(const float2*)(u + o1i);
            __half2 a0, a1;
            a0.x = __float2half_rn(cacc[mf][nf][0] * u0.x);
            a0.y = __float2half_rn(cacc[mf][nf][1] * u0.y);
            a1.x = __float2half_rn(cacc[mf][nf][2] * u1.x);
            a1.y = __float2half_rn(cacc[mf][nf][3] * u1.y);
            *(__half2*)(aout + o0i) = a0;
            *(__half2*)(aout + o1i) = a1;
        }
    }
}

// ---------------------------------------------------------------------------
extern "C" void kernel_launch(void* const* d_in, const int* in_sizes, int n_in,
                              void* d_out, int out_size)
{
    const float* x      = (const float*)d_in[0];
    // d_in[1] = attention_mask (causal tril) — applied analytically, unused
    const float* ln_g   = (const float*)d_in[2];
    const float* ln_b   = (const float*)d_in[3];
    const float* w_qkv  = (const float*)d_in[4];
    const float* b_qkv  = (const float*)d_in[5];
    const float* w_gate = (const float*)d_in[6];
    const float* b_gate = (const float*)d_in[7];
    const float* w_out  = (const float*)d_in[8];
    const float* b_out  = (const float*)d_in[9];
    const float* rpb    = (const float*)d_in[10];
    float* out = (float*)d_out;

    __half *xn, *wqh, *wql, *wgh, *wgl, *woh, *wol, *a;
    __half *qkvh, *qkvl;
    float *u;
    cudaGetSymbolAddress((void**)&xn,  g_xn);
    cudaGetSymbolAddress((void**)&wqh, g_wqh);
    cudaGetSymbolAddress((void**)&wql, g_wql);
    cudaGetSymbolAddress((void**)&wgh, g_wgh);
    cudaGetSymbolAddress((void**)&wgl, g_wgl);
    cudaGetSymbolAddress((void**)&woh, g_woh);
    cudaGetSymbolAddress((void**)&wol, g_wol);
    cudaGetSymbolAddress((void**)&qkvh, g_qkvh);
    cudaGetSymbolAddress((void**)&qkvl, g_qkvl);
    cudaGetSymbolAddress((void**)&u,   g_u);
    cudaGetSymbolAddress((void**)&a,   g_a);

    cudaFuncSetAttribute(attn_kernel, cudaFuncAttributeMaxDynamicSharedMemorySize, ATTN_SMEM_B);
    cudaFuncSetAttribute(tgemm<0>, cudaFuncAttributeMaxDynamicSharedMemorySize, G_SMEM);
    cudaFuncSetAttribute(tgemm<1>, cudaFuncAttributeMaxDynamicSharedMemorySize, G_SMEM);

    wsplit_kernel<<<dim3(N_QKV / 32, DMODEL / 32), dim3(32, 8)>>>(w_qkv, wqh, wql, DMODEL, N_QKV);
    wsplit_kernel<<<dim3(DMODEL / 32, DMODEL / 32), dim3(32, 8)>>>(w_gate, wgh, wgl, DMODEL, DMODEL);
    wsplit_kernel<<<dim3(DMODEL / 32, DMODEL / 32), dim3(32, 8)>>>(w_out, woh, wol, DMODEL, DMODEL);

    ln_half_kernel<<<R_TOT, 256>>>(x, ln_g, ln_b, xn);

    // fused qkv + gate GEMM (N = 4096)
    tgemm<1><<<dim3((N_QKV + DMODEL) / 128, R_TOT / 128), 256, G_SMEM>>>(
        xn, wqh, wql, wgh, wgl, b_qkv, b_gate, nullptr, u, qkvh, qkvl);

    attn_kernel<<<dim3(SEQ / 128, 2 * NHEAD), 256, ATTN_SMEM_B>>>(qkvh, qkvl, rpb, u, a);

    // out projection (+ residual)
    tgemm<0><<<dim3(DMODEL / 128, R_TOT / 128), 256, G_SMEM>>>(
        a, woh, wol, nullptr, nullptr, b_out, nullptr, x, out, nullptr, nullptr);
}

// round 10
// speedup vs baseline: 4.1538x; 1.1688x over previous
#include <cuda_runtime.h>
#include <cuda_fp16.h>
#include <cstdint>

#define R_TOT 4096
#define DMODEL 1024
#define N_QKV 3072
#define SEQ 2048
#define NHEAD 16

// ------------------------------ scratch (device globals) -------------------
__device__ __half g_xn[R_TOT * DMODEL];                       // activations, single fp16
__device__ __half g_wqh[N_QKV * DMODEL], g_wql[N_QKV * DMODEL];
__device__ __half g_wgh[DMODEL * DMODEL];
__device__ __half g_woh[DMODEL * DMODEL];
__device__ __half g_qkv[(size_t)R_TOT * N_QKV];               // q,k,v single fp16
__device__ float g_u[R_TOT * DMODEL];
__device__ __half g_a[R_TOT * DMODEL];                        // ctx*u, single fp16

// ------------------------------ helpers ------------------------------------
__device__ __forceinline__ void h_split(float x, __half& h, __half& l) {
    h = __float2half_rn(x);
    l = __float2half_rn(x - __half2float(h));
}
__device__ __forceinline__ void mma16(float d[4], const uint32_t a[4], uint32_t b0, uint32_t b1) {
    asm volatile("mma.sync.aligned.m16n8k16.row.col.f32.f16.f16.f32 "
        "{%0,%1,%2,%3},{%4,%5,%6,%7},{%8,%9},{%0,%1,%2,%3};"
        : "+f"(d[0]), "+f"(d[1]), "+f"(d[2]), "+f"(d[3])
        : "r"(a[0]), "r"(a[1]), "r"(a[2]), "r"(a[3]), "r"(b0), "r"(b1));
}
__device__ __forceinline__ void ldm_x4(uint32_t r[4], uint32_t addr) {
    asm volatile("ldmatrix.sync.aligned.m8n8.x4.shared.b16 {%0,%1,%2,%3}, [%4];"
        : "=r"(r[0]), "=r"(r[1]), "=r"(r[2]), "=r"(r[3]) : "r"(addr));
}
__device__ __forceinline__ uint32_t smem_u32(const void* p) {
    return (uint32_t)__cvta_generic_to_shared(p);
}
#define CP16(dst, src) \
    asm volatile("cp.async.cg.shared.global [%0], [%1], 16;" \
        :: "r"(dst), "l"(__cvta_generic_to_global(src)) : "memory")
#define CP_COMMIT() asm volatile("cp.async.commit_group;" ::: "memory")
#define CP_WAIT0()  asm volatile("cp.async.wait_group 0;" ::: "memory")

// ------------------------------ LayerNorm -> single fp16 -------------------
__global__ __launch_bounds__(256) void ln_half_kernel(
    const float* __restrict__ x, const float* __restrict__ gamma,
    const float* __restrict__ beta, __half* __restrict__ xn)
{
    int row = blockIdx.x;
    int t = threadIdx.x;
    const float4* xr = (const float4*)(x + (size_t)row * DMODEL);
    float4 v = xr[t];
    float s  = v.x + v.y + v.z + v.w;
    float sq = v.x*v.x + v.y*v.y + v.z*v.z + v.w*v.w;
#pragma unroll
    for (int o = 16; o; o >>= 1) {
        s  += __shfl_xor_sync(0xffffffffu, s,  o);
        sq += __shfl_xor_sync(0xffffffffu, sq, o);
    }
    __shared__ float ss[8], sqq[8];
    int w = t >> 5, l = t & 31;
    if (l == 0) { ss[w] = s; sqq[w] = sq; }
    __syncthreads();
    if (w == 0) {
        s  = (l < 8) ? ss[l]  : 0.f;
        sq = (l < 8) ? sqq[l] : 0.f;
#pragma unroll
        for (int o = 4; o; o >>= 1) {
            s  += __shfl_xor_sync(0xffffffffu, s,  o);
            sq += __shfl_xor_sync(0xffffffffu, sq, o);
        }
        if (l == 0) { ss[0] = s; sqq[0] = sq; }
    }
    __syncthreads();
    float mean = ss[0] * (1.f / DMODEL);
    float var  = sqq[0] * (1.f / DMODEL) - mean * mean;
    float rstd = rsqrtf(var + 1e-5f);
    float4 g  = ((const float4*)gamma)[t];
    float4 bb = ((const float4*)beta)[t];
    __half2 p0, p1;
    p0.x = __float2half_rn((v.x - mean) * rstd * g.x + bb.x);
    p0.y = __float2half_rn((v.y - mean) * rstd * g.y + bb.y);
    p1.x = __float2half_rn((v.z - mean) * rstd * g.z + bb.z);
    p1.y = __float2half_rn((v.w - mean) * rstd * g.w + bb.w);
    uint2 o;
    o.x = *(uint32_t*)&p0; o.y = *(uint32_t*)&p1;
    *(uint2*)(xn + (size_t)row * DMODEL + t * 4) = o;
}

// --------------------- weight transpose + fp16 split (hi/lo) ----------------
__global__ void wsplit_kernel(const float* __restrict__ w,
                              __half* __restrict__ th,
                              __half* __restrict__ tl, int K, int N)
{
    __shared__ float t[32][33];
    int n0 = blockIdx.x * 32, k0 = blockIdx.y * 32;
    int tx = threadIdx.x, ty = threadIdx.y;
#pragma unroll
    for (int j = ty; j < 32; j += 8)
        t[j][tx] = w[(size_t)(k0 + j) * N + n0 + tx];
    __syncthreads();
#pragma unroll
    for (int j = ty; j < 32; j += 8) {
        float v = t[tx][j];
        __half h, l;
        h_split(v, h, l);
        th[(size_t)(n0 + j) * K + k0 + tx] = h;
        if (tl) tl[(size_t)(n0 + j) * K + k0 + tx] = l;
    }
}

// --------------------- weight transpose, hi only ----------------------------
__global__ void whalf_kernel(const float* __restrict__ w,
                             __half* __restrict__ th, int K, int N)
{
    __shared__ float t[32][33];
    int n0 = blockIdx.x * 32, k0 = blockIdx.y * 32;
    int tx = threadIdx.x, ty = threadIdx.y;
#pragma unroll
    for (int j = ty; j < 32; j += 8)
        t[j][tx] = w[(size_t)(k0 + j) * N + n0 + tx];
    __syncthreads();
#pragma unroll
    for (int j = ty; j < 32; j += 8)
        th[(size_t)(n0 + j) * K + k0 + tx] = __float2half_rn(t[tx][j]);
}

// ---------------------------------------------------------------------------
// fp16 GEMM core: A single; B 2-pass (hi/lo) or 1-pass, block-uniform.
// Block 128x128, 8 warps, warp tile 32x64. K = 1024 fixed. cp.async, BK=32.
// FUSED=1: nBase<3072 -> 2-pass, qkv single-fp16 out; else 1-pass SiLU -> u fp32
// FUSED=0: 1-pass, +resid -> fp32 out
// stage = A(10240) Bh(10240) Bl(10240) = 30720 B, x2 stages
// ---------------------------------------------------------------------------
#define G_STAGE 30720u
#define G_SMEM  (2 * 30720)

template<int FUSED>
__global__ __launch_bounds__(256) void tgemm(
    const __half* __restrict__ A,
    const __half* __restrict__ BqH, const __half* __restrict__ BqL,
    const __half* __restrict__ BgH,
    const float* __restrict__ bias_q, const float* __restrict__ bias_g,
    const float* __restrict__ resid,
    float* __restrict__ Cf, __half* __restrict__ Ch)
{
    extern __shared__ char gsm[];
    const uint32_t base = smem_u32(gsm);
    const int K = DMODEL;

    const int tid  = threadIdx.x;
    const int lane = tid & 31;
    const int gid  = lane >> 2, tig = lane & 3;
    const int wid  = tid >> 5;
    const int wm   = (wid & 3) * 32;
    const int wn   = (wid >> 2) * 64;
    const int mBase = blockIdx.y * 128, nBase = blockIdx.x * 128;
    const int lrow = lane & 15;
    const uint32_t lkb = (lane >> 4) * 16;

    const bool isQ = FUSED && (nBase < N_QKV);
    const bool twoPass = isQ;
    const __half* Bh = FUSED ? (isQ ? BqH + (size_t)nBase * K
                                    : BgH + (size_t)(nBase - N_QKV) * K)
                             : BqH + (size_t)nBase * K;
    const __half* Bl = isQ ? BqL + (size_t)nBase * K : BqH;
    const float* bias = (FUSED && !isQ) ? bias_g : bias_q;
    const int biasOff = FUSED ? (isQ ? nBase : nBase - N_QKV) : nBase;

    float acc[2][8][4];
#pragma unroll
    for (int i = 0; i < 2; i++)
#pragma unroll
        for (int j = 0; j < 8; j++)
#pragma unroll
            for (int l = 0; l < 4; l++) acc[i][j][l] = 0.f;

    auto ld_stage = [&](int c, int s) {
        const uint32_t sb = base + (uint32_t)s * G_STAGE;
        const int kt = c * 32;
#pragma unroll
        for (int it = 0; it < 2; it++) {
            int idx = it * 256 + tid;
            int row = idx >> 2, seg = idx & 3;
            uint32_t d = sb + row * 80 + seg * 16;
            size_t aoff = (size_t)(mBase + row) * K + kt + seg * 8;
            size_t boff = (size_t)row * K + kt + seg * 8;
            CP16(d,         A  + aoff);
            CP16(d + 10240, Bh + boff);
            if (twoPass) CP16(d + 20480, Bl + boff);
        }
    };

    ld_stage(0, 0); CP_COMMIT();
    const int NC = K / 32;
    for (int c = 0; c < NC; c++) {
        CP_WAIT0(); __syncthreads();
        if (c + 1 < NC) { ld_stage(c + 1, (c + 1) & 1); CP_COMMIT(); }
        const uint32_t sb = base + (uint32_t)(c & 1) * G_STAGE;
#pragma unroll
        for (int ks = 0; ks < 2; ks++) {
            const uint32_t kb = ks * 32 + lkb;
            uint32_t ar[2][4], bh[4][4];
#pragma unroll
            for (int mf = 0; mf < 2; mf++)
                ldm_x4(ar[mf], sb + (wm + mf * 16 + lrow) * 80 + kb);
#pragma unroll
            for (int p = 0; p < 4; p++)
                ldm_x4(bh[p], sb + 10240 + (wn + p * 16 + lrow) * 80 + kb);
#pragma unroll
            for (int nf = 0; nf < 8; nf++)
#pragma unroll
                for (int mf = 0; mf < 2; mf++)
                    mma16(acc[mf][nf], ar[mf], bh[nf >> 1][nf & 1], bh[nf >> 1][(nf & 1) + 2]);
            if (twoPass) {
                uint32_t bl[4][4];
#pragma unroll
                for (int p = 0; p < 4; p++)
                    ldm_x4(bl[p], sb + 20480 + (wn + p * 16 + lrow) * 80 + kb);
#pragma unroll
                for (int nf = 0; nf < 8; nf++)
#pragma unroll
                    for (int mf = 0; mf < 2; mf++)
                        mma16(acc[mf][nf], ar[mf], bl[nf >> 1][nf & 1], bl[nf >> 1][(nf & 1) + 2]);
            }
        }
    }

    // epilogue
#pragma unroll
    for (int mf = 0; mf < 2; mf++) {
#pragma unroll
        for (int nf = 0; nf < 8; nf++) {
            int row0 = mBase + wm + mf * 16 + gid;
            int colL = biasOff + wn + nf * 8 + 2 * tig;
            float bx = bias[colL], by = bias[colL + 1];
            float v0 = acc[mf][nf][0] + bx;
            float v1 = acc[mf][nf][1] + by;
            float v2 = acc[mf][nf][2] + bx;
            float v3 = acc[mf][nf][3] + by;
            if (FUSED && isQ) {
                __half2 a;
                a.x = __float2half_rn(v0); a.y = __float2half_rn(v1);
                *(__half2*)(Ch + (size_t)row0 * N_QKV + colL) = a;
                a.x = __float2half_rn(v2); a.y = __float2half_rn(v3);
                *(__half2*)(Ch + (size_t)(row0 + 8) * N_QKV + colL) = a;
            } else if (FUSED) {   // gate region: SiLU -> u fp32
                v0 = v0 / (1.f + __expf(-v0));
                v1 = v1 / (1.f + __expf(-v1));
                v2 = v2 / (1.f + __expf(-v2));
                v3 = v3 / (1.f + __expf(-v3));
                float2 o0 = {v0, v1}, o1 = {v2, v3};
                *(float2*)(Cf + (size_t)row0 * DMODEL + colL) = o0;
                *(float2*)(Cf + (size_t)(row0 + 8) * DMODEL + colL) = o1;
            } else {              // out-proj: +resid -> fp32
                const float* r0 = resid + (size_t)row0 * DMODEL + colL;
                const float* r1 = resid + (size_t)(row0 + 8) * DMODEL + colL;
                v0 += r0[0]; v1 += r0[1]; v2 += r1[0]; v3 += r1[1];
                float2 o0 = {v0, v1}, o1 = {v2, v3};
                *(float2*)(Cf + (size_t)row0 * DMODEL + colL) = o0;
                *(float2*)(Cf + (size_t)(row0 + 8) * DMODEL + colL) = o1;
            }
        }
    }
}

// ---------------------------------------------------------------------------
// Fused causal sigmoid attention, all-single fp16, 128-q-row tiles.
// QK 1-pass, PV 1-pass. Epilogue: ctx * u -> fp16 `a`.
// smem: Q 128 + P 128 + K 64 + V 64 rows of AST halfs = 55296 B
// ---------------------------------------------------------------------------
#define AST 72
#define ATTN_SMEM_B ((2 * 128 + 2 * 64) * AST * 2)

__global__ __launch_bounds__(256) void attn_kernel(
    const __half* __restrict__ qkv, const float* __restrict__ rpb,
    const float* __restrict__ u, __half* __restrict__ aout)
{
    extern __shared__ __half smb[];
    __half* Qs = smb;
    __half* Ps = Qs + 128 * AST;
    __half* Ks = Ps + 128 * AST;
    __half* Vs = Ks + 64 * AST;
    const uint32_t uQ = smem_u32(Qs), uP = smem_u32(Ps);
    const uint32_t uK = smem_u32(Ks), uV = smem_u32(Vs);

    const int qt = 15 - (int)blockIdx.x;     // big tiles first
    const int bh = blockIdx.y;
    const int b = bh >> 4, h = bh & 15;
    const float pbias = rpb[h];
    const int tid  = threadIdx.x;
    const int lane = tid & 31;
    const int gid  = lane >> 2, tig = lane & 3;
    const int wid  = tid >> 5;
    const int m0   = (wid & 3) * 32;
    const int n0   = (wid >> 2) * 32;
    const int lrow = lane & 15;
    const uint32_t lkb = (lane >> 4) * 16;

    const size_t base = (size_t)(b * SEQ) * N_QKV + h * 64;
    const __half* qb = qkv + base;
    const __half* kb = qkv + base + DMODEL;
    const __half* vb = qkv + base + 2 * DMODEL;

    // Q load: 128 rows x 64 cols
#pragma unroll
    for (int it = 0; it < 4; it++) {
        int idx = it * 256 + tid;
        int row = idx >> 3, seg = idx & 7;
        size_t off = (size_t)(qt * 128 + row) * N_QKV + seg * 8;
        *(uint4*)&Qs[row * AST + seg * 8] = *(const uint4*)(qb + off);
    }

    float cacc[2][4][4];
#pragma unroll
    for (int i = 0; i < 2; i++)
#pragma unroll
        for (int j = 0; j < 4; j++)
#pragma unroll
            for (int l = 0; l < 4; l++) cacc[i][j][l] = 0.f;

    const int krow = tid >> 2;
    const int kc16 = (tid & 3) * 16;
    const int vkp = tid & 31;
    const int vd0 = (tid >> 5) * 8;

    const int nkt = 2 * qt + 2;
    for (int kt = 0; kt < nkt; kt++) {
        uint4 kr0, kr1, va0, va1;
        {
            size_t off = (size_t)(kt * 64 + krow) * N_QKV + kc16;
            kr0 = *(const uint4*)(kb + off);
            kr1 = *(const uint4*)(kb + off + 8);
            size_t voff0 = (size_t)(kt * 64 + 2 * vkp) * N_QKV + vd0;
            va0 = *(const uint4*)(vb + voff0);
            va1 = *(const uint4*)(vb + voff0 + N_QKV);
        }
        __syncthreads();   // prev iter's reads of K/V/P done
        {
            *(uint4*)&Ks[krow * AST + kc16]     = kr0;
            *(uint4*)&Ks[krow * AST + kc16 + 8] = kr1;
            const uint32_t* a0w = (const uint32_t*)&va0;
            const uint32_t* a1w = (const uint32_t*)&va1;
#pragma unroll
            for (int i = 0; i < 4; i++) {
                uint32_t h_lo = __byte_perm(a0w[i], a1w[i], 0x5410);
                uint32_t h_hi = __byte_perm(a0w[i], a1w[i], 0x7632);
                int d = vd0 + 2 * i;
                *(uint32_t*)&Vs[d * AST + 2 * vkp]       = h_lo;
                *(uint32_t*)&Vs[(d + 1) * AST + 2 * vkp] = h_hi;
            }
        }
        __syncthreads();

        // S = Q @ K^T : 1 pass
        float sacc[2][4][4];
#pragma unroll
        for (int i = 0; i < 2; i++)
#pragma unroll
            for (int j = 0; j < 4; j++)
#pragma unroll
                for (int l = 0; l < 4; l++) sacc[i][j][l] = 0.f;
#pragma unroll
        for (int ks = 0; ks < 4; ks++) {
            const uint32_t kbo = ks * 32 + lkb;
            uint32_t k0[4], k1[4];
            ldm_x4(k0, uK + (n0 + lrow) * (AST * 2) + kbo);
            ldm_x4(k1, uK + (n0 + 16 + lrow) * (AST * 2) + kbo);
#pragma unroll
            for (int mf = 0; mf < 2; mf++) {
                uint32_t qh[4];
                ldm_x4(qh, uQ + (m0 + mf * 16 + lrow) * (AST * 2) + kbo);
                mma16(sacc[mf][0], qh, k0[0], k0[2]);
                mma16(sacc[mf][1], qh, k0[1], k0[3]);
                mma16(sacc[mf][2], qh, k1[0], k1[2]);
                mma16(sacc[mf][3], qh, k1[1], k1[3]);
            }
        }

        // sigmoid + causal mask -> P (fp16, [m][kseq])
        const bool diag = (kt >= 2 * qt);
#pragma unroll
        for (int mf = 0; mf < 2; mf++) {
            int rl0 = m0 + mf * 16 + gid;
            int rg0 = qt * 128 + rl0;
#pragma unroll
            for (int nf = 0; nf < 4; nf++) {
                int cl = n0 + nf * 8 + 2 * tig;
                int cg = kt * 64 + cl;
                float s0 = sacc[mf][nf][0] * 0.125f + pbias;
                float s1 = sacc[mf][nf][1] * 0.125f + pbias;
                float s2 = sacc[mf][nf][2] * 0.125f + pbias;
                float s3 = sacc[mf][nf][3] * 0.125f + pbias;
                float p0 = __fdividef(1.f, 1.f + __expf(-s0));
                float p1 = __fdividef(1.f, 1.f + __expf(-s1));
                float p2 = __fdividef(1.f, 1.f + __expf(-s2));
                float p3 = __fdividef(1.f, 1.f + __expf(-s3));
                if (diag) {
                    if (cg > rg0)         p0 = 0.f;
                    if (cg + 1 > rg0)     p1 = 0.f;
                    if (cg > rg0 + 8)     p2 = 0.f;
                    if (cg + 1 > rg0 + 8) p3 = 0.f;
                }
                __half2 a;
                a.x = __float2half_rn(p0); a.y = __float2half_rn(p1);
                *(__half2*)&Ps[rl0 * AST + cl] = a;
                a.x = __float2half_rn(p2); a.y = __float2half_rn(p3);
                *(__half2*)&Ps[(rl0 + 8) * AST + cl] = a;
            }
        }
        __syncthreads();

        // ctx += P @ V : 1 pass
#pragma unroll
        for (int ks = 0; ks < 4; ks++) {
            const uint32_t kbo = ks * 32 + lkb;
            uint32_t v0[4], v1[4];
            ldm_x4(v0, uV + (n0 + lrow) * (AST * 2) + kbo);
            ldm_x4(v1, uV + (n0 + 16 + lrow) * (AST * 2) + kbo);
#pragma unroll
            for (int mf = 0; mf < 2; mf++) {
                uint32_t ph[4];
                ldm_x4(ph, uP + (m0 + mf * 16 + lrow) * (AST * 2) + kbo);
                mma16(cacc[mf][0], ph, v0[0], v0[2]);
                mma16(cacc[mf][1], ph, v0[1], v0[3]);
                mma16(cacc[mf][2], ph, v1[0], v1[2]);
                mma16(cacc[mf][3], ph, v1[1], v1[3]);
            }
        }
    }

    // epilogue: a = half(ctx * u), layout [b, s, h*64 + d]
#pragma unroll
    for (int mf = 0; mf < 2; mf++) {
#pragma unroll
        for (int nf = 0; nf < 4; nf++) {
            int row = qt * 128 + m0 + mf * 16 + gid;
            int col = h * 64 + n0 + nf * 8 + 2 * tig;
            size_t o0i = (size_t)(b * SEQ + row) * DMODEL + col;
            size_t o1i = (size_t)(b * SEQ + row + 8) * DMODEL + col;
            float2 u0 = *(const float2*)(u + o0i);
            float2 u1 = *(const float2*)(u + o1i);
            __half2 a0, a1;
            a0.x = __float2half_rn(cacc[mf][nf][0] * u0.x);
            a0.y = __float2half_rn(cacc[mf][nf][1] * u0.y);
            a1.x = __float2half_rn(cacc[mf][nf][2] * u1.x);
            a1.y = __float2half_rn(cacc[mf][nf][3] * u1.y);
            *(__half2*)(aout + o0i) = a0;
            *(__half2*)(aout + o1i) = a1;
        }
    }
}

// ---------------------------------------------------------------------------
extern "C" void kernel_launch(void* const* d_in, const int* in_sizes, int n_in,
                              void* d_out, int out_size)
{
    const float* x      = (const float*)d_in[0];
    // d_in[1] = attention_mask (causal tril) — applied analytically, unused
    const float* ln_g   = (const float*)d_in[2];
    const float* ln_b   = (const float*)d_in[3];
    const float* w_qkv  = (const float*)d_in[4];
    const float* b_qkv  = (const float*)d_in[5];
    const float* w_gate = (const float*)d_in[6];
    const float* b_gate = (const float*)d_in[7];
    const float* w_out  = (const float*)d_in[8];
    const float* b_out  = (const float*)d_in[9];
    const float* rpb    = (const float*)d_in[10];
    float* out = (float*)d_out;

    __half *xn, *wqh, *wql, *wgh, *woh, *a, *qkv;
    float *u;
    cudaGetSymbolAddress((void**)&xn,  g_xn);
    cudaGetSymbolAddress((void**)&wqh, g_wqh);
    cudaGetSymbolAddress((void**)&wql, g_wql);
    cudaGetSymbolAddress((void**)&wgh, g_wgh);
    cudaGetSymbolAddress((void**)&woh, g_woh);
    cudaGetSymbolAddress((void**)&qkv, g_qkv);
    cudaGetSymbolAddress((void**)&u,   g_u);
    cudaGetSymbolAddress((void**)&a,   g_a);

    cudaFuncSetAttribute(attn_kernel, cudaFuncAttributeMaxDynamicSharedMemorySize, ATTN_SMEM_B);
    cudaFuncSetAttribute(tgemm<0>, cudaFuncAttributeMaxDynamicSharedMemorySize, G_SMEM);
    cudaFuncSetAttribute(tgemm<1>, cudaFuncAttributeMaxDynamicSharedMemorySize, G_SMEM);

    wsplit_kernel<<<dim3(N_QKV / 32, DMODEL / 32), dim3(32, 8)>>>(w_qkv, wqh, wql, DMODEL, N_QKV);
    whalf_kernel<<<dim3(DMODEL / 32, DMODEL / 32), dim3(32, 8)>>>(w_gate, wgh, DMODEL, DMODEL);
    whalf_kernel<<<dim3(DMODEL / 32, DMODEL / 32), dim3(32, 8)>>>(w_out, woh, DMODEL, DMODEL);

    ln_half_kernel<<<R_TOT, 256>>>(x, ln_g, ln_b, xn);

    // fused qkv + gate GEMM (N = 4096)
    tgemm<1><<<dim3((N_QKV + DMODEL) / 128, R_TOT / 128), 256, G_SMEM>>>(
        xn, wqh, wql, wgh, b_qkv, b_gate, nullptr, u, qkv);

    attn_kernel<<<dim3(SEQ / 128, 2 * NHEAD), 256, ATTN_SMEM_B>>>(qkv, rpb, u, a);

    // out projection (+ residual), 1-pass
    tgemm<0><<<dim3(DMODEL / 128, R_TOT / 128), 256, G_SMEM>>>(
        a, woh, nullptr, nullptr, b_out, nullptr, x, out, nullptr);
}

// round 11
// speedup vs baseline: 5.1176x; 1.2320x over previous
#include <cuda_runtime.h>
#include <cuda_fp16.h>
#include <cstdint>

#define R_TOT 4096
#define DMODEL 1024
#define N_QKV 3072
#define SEQ 2048
#define NHEAD 16

// ------------------------------ scratch (device globals) -------------------
__device__ __half g_xn[R_TOT * DMODEL];                       // activations fp16
__device__ __half g_wq[N_QKV * DMODEL];                       // w_qkv^T fp16
__device__ __half g_wg[DMODEL * DMODEL];                      // w_gate^T fp16
__device__ __half g_wo[DMODEL * DMODEL];                      // w_out^T fp16
__device__ __half g_qkv[(size_t)R_TOT * N_QKV];               // q,k,v fp16
__device__ float g_u[R_TOT * DMODEL];
__device__ __half g_a[R_TOT * DMODEL];                        // ctx*u fp16

// ------------------------------ helpers ------------------------------------
__device__ __forceinline__ void mma16(float d[4], const uint32_t a[4], uint32_t b0, uint32_t b1) {
    asm volatile("mma.sync.aligned.m16n8k16.row.col.f32.f16.f16.f32 "
        "{%0,%1,%2,%3},{%4,%5,%6,%7},{%8,%9},{%0,%1,%2,%3};"
        : "+f"(d[0]), "+f"(d[1]), "+f"(d[2]), "+f"(d[3])
        : "r"(a[0]), "r"(a[1]), "r"(a[2]), "r"(a[3]), "r"(b0), "r"(b1));
}
__device__ __forceinline__ void ldm_x4(uint32_t r[4], uint32_t addr) {
    asm volatile("ldmatrix.sync.aligned.m8n8.x4.shared.b16 {%0,%1,%2,%3}, [%4];"
        : "=r"(r[0]), "=r"(r[1]), "=r"(r[2]), "=r"(r[3]) : "r"(addr));
}
__device__ __forceinline__ uint32_t smem_u32(const void* p) {
    return (uint32_t)__cvta_generic_to_shared(p);
}
#define CP16(dst, src) \
    asm volatile("cp.async.cg.shared.global [%0], [%1], 16;" \
        :: "r"(dst), "l"(__cvta_generic_to_global(src)) : "memory")
#define CP_COMMIT() asm volatile("cp.async.commit_group;" ::: "memory")
#define CP_WAIT0()  asm volatile("cp.async.wait_group 0;" ::: "memory")

// ------------------------------ LayerNorm -> fp16 --------------------------
__global__ __launch_bounds__(256) void ln_half_kernel(
    const float* __restrict__ x, const float* __restrict__ gamma,
    const float* __restrict__ beta, __half* __restrict__ xn)
{
    int row = blockIdx.x;
    int t = threadIdx.x;
    const float4* xr = (const float4*)(x + (size_t)row * DMODEL);
    float4 v = xr[t];
    float s  = v.x + v.y + v.z + v.w;
    float sq = v.x*v.x + v.y*v.y + v.z*v.z + v.w*v.w;
#pragma unroll
    for (int o = 16; o; o >>= 1) {
        s  += __shfl_xor_sync(0xffffffffu, s,  o);
        sq += __shfl_xor_sync(0xffffffffu, sq, o);
    }
    __shared__ float ss[8], sqq[8];
    int w = t >> 5, l = t & 31;
    if (l == 0) { ss[w] = s; sqq[w] = sq; }
    __syncthreads();
    if (w == 0) {
        s  = (l < 8) ? ss[l]  : 0.f;
        sq = (l < 8) ? sqq[l] : 0.f;
#pragma unroll
        for (int o = 4; o; o >>= 1) {
            s  += __shfl_xor_sync(0xffffffffu, s,  o);
            sq += __shfl_xor_sync(0xffffffffu, sq, o);
        }
        if (l == 0) { ss[0] = s; sqq[0] = sq; }
    }
    __syncthreads();
    float mean = ss[0] * (1.f / DMODEL);
    float var  = sqq[0] * (1.f / DMODEL) - mean * mean;
    float rstd = rsqrtf(var + 1e-5f);
    float4 g  = ((const float4*)gamma)[t];
    float4 bb = ((const float4*)beta)[t];
    __half2 p0, p1;
    p0.x = __float2half_rn((v.x - mean) * rstd * g.x + bb.x);
    p0.y = __float2half_rn((v.y - mean) * rstd * g.y + bb.y);
    p1.x = __float2half_rn((v.z - mean) * rstd * g.z + bb.z);
    p1.y = __float2half_rn((v.w - mean) * rstd * g.w + bb.w);
    uint2 o;
    o.x = *(uint32_t*)&p0; o.y = *(uint32_t*)&p1;
    *(uint2*)(xn + (size_t)row * DMODEL + t * 4) = o;
}

// --------------------- weight transpose, fp16 -------------------------------
__global__ void whalf_kernel(const float* __restrict__ w,
                             __half* __restrict__ th, int K, int N)
{
    __shared__ float t[32][33];
    int n0 = blockIdx.x * 32, k0 = blockIdx.y * 32;
    int tx = threadIdx.x, ty = threadIdx.y;
#pragma unroll
    for (int j = ty; j < 32; j += 8)
        t[j][tx] = w[(size_t)(k0 + j) * N + n0 + tx];
    __syncthreads();
#pragma unroll
    for (int j = ty; j < 32; j += 8)
        th[(size_t)(n0 + j) * K + k0 + tx] = __float2half_rn(t[tx][j]);
}

// ---------------------------------------------------------------------------
// fp16 GEMM, 1-pass. Block 128x128, 8 warps, warp tile 32x64. K=1024 fixed.
// cp.async double-buffer, BK=32. stage = A(10240) B(10240) = 20480 B, x2.
// FUSED=1: nBase<3072 -> qkv fp16 out; else SiLU -> u fp32
// FUSED=0: +resid -> fp32 out
// ---------------------------------------------------------------------------
#define G_STAGE 20480u
#define G_SMEM  (2 * 20480)

template<int FUSED>
__global__ __launch_bounds__(256) void tgemm(
    const __half* __restrict__ A,
    const __half* __restrict__ Bq, const __half* __restrict__ Bg,
    const float* __restrict__ bias_q, const float* __restrict__ bias_g,
    const float* __restrict__ resid,
    float* __restrict__ Cf, __half* __restrict__ Ch)
{
    extern __shared__ char gsm[];
    const uint32_t base = smem_u32(gsm);
    const int K = DMODEL;

    const int tid  = threadIdx.x;
    const int lane = tid & 31;
    const int gid  = lane >> 2, tig = lane & 3;
    const int wid  = tid >> 5;
    const int wm   = (wid & 3) * 32;
    const int wn   = (wid >> 2) * 64;
    const int mBase = blockIdx.y * 128, nBase = blockIdx.x * 128;
    const int lrow = lane & 15;
    const uint32_t lkb = (lane >> 4) * 16;

    const bool isQ = FUSED && (nBase < N_QKV);
    const __half* Bm = FUSED ? (isQ ? Bq + (size_t)nBase * K
                                    : Bg + (size_t)(nBase - N_QKV) * K)
                             : Bq + (size_t)nBase * K;
    const float* bias = (FUSED && !isQ) ? bias_g : bias_q;
    const int biasOff = FUSED ? (isQ ? nBase : nBase - N_QKV) : nBase;

    float acc[2][8][4];
#pragma unroll
    for (int i = 0; i < 2; i++)
#pragma unroll
        for (int j = 0; j < 8; j++)
#pragma unroll
            for (int l = 0; l < 4; l++) acc[i][j][l] = 0.f;

    auto ld_stage = [&](int c, int s) {
        const uint32_t sb = base + (uint32_t)s * G_STAGE;
        const int kt = c * 32;
#pragma unroll
        for (int it = 0; it < 2; it++) {
            int idx = it * 256 + tid;
            int row = idx >> 2, seg = idx & 3;
            uint32_t d = sb + row * 80 + seg * 16;
            CP16(d,         A  + (size_t)(mBase + row) * K + kt + seg * 8);
            CP16(d + 10240, Bm + (size_t)row * K + kt + seg * 8);
        }
    };

    ld_stage(0, 0); CP_COMMIT();
    const int NC = K / 32;
    for (int c = 0; c < NC; c++) {
        CP_WAIT0(); __syncthreads();
        if (c + 1 < NC) { ld_stage(c + 1, (c + 1) & 1); CP_COMMIT(); }
        const uint32_t sb = base + (uint32_t)(c & 1) * G_STAGE;
#pragma unroll
        for (int ks = 0; ks < 2; ks++) {
            const uint32_t kb = ks * 32 + lkb;
            uint32_t ar[2][4], bh[4][4];
#pragma unroll
            for (int mf = 0; mf < 2; mf++)
                ldm_x4(ar[mf], sb + (wm + mf * 16 + lrow) * 80 + kb);
#pragma unroll
            for (int p = 0; p < 4; p++)
                ldm_x4(bh[p], sb + 10240 + (wn + p * 16 + lrow) * 80 + kb);
#pragma unroll
            for (int nf = 0; nf < 8; nf++)
#pragma unroll
                for (int mf = 0; mf < 2; mf++)
                    mma16(acc[mf][nf], ar[mf], bh[nf >> 1][nf & 1], bh[nf >> 1][(nf & 1) + 2]);
        }
    }

    // epilogue
#pragma unroll
    for (int mf = 0; mf < 2; mf++) {
#pragma unroll
        for (int nf = 0; nf < 8; nf++) {
            int row0 = mBase + wm + mf * 16 + gid;
            int colL = biasOff + wn + nf * 8 + 2 * tig;
            float bx = bias[colL], by = bias[colL + 1];
            float v0 = acc[mf][nf][0] + bx;
            float v1 = acc[mf][nf][1] + by;
            float v2 = acc[mf][nf][2] + bx;
            float v3 = acc[mf][nf][3] + by;
            if (FUSED && isQ) {
                __half2 a;
                a.x = __float2half_rn(v0); a.y = __float2half_rn(v1);
                *(__half2*)(Ch + (size_t)row0 * N_QKV + colL) = a;
                a.x = __float2half_rn(v2); a.y = __float2half_rn(v3);
                *(__half2*)(Ch + (size_t)(row0 + 8) * N_QKV + colL) = a;
            } else if (FUSED) {   // gate region: SiLU -> u fp32
                v0 = v0 / (1.f + __expf(-v0));
                v1 = v1 / (1.f + __expf(-v1));
                v2 = v2 / (1.f + __expf(-v2));
                v3 = v3 / (1.f + __expf(-v3));
                float2 o0 = {v0, v1}, o1 = {v2, v3};
                *(float2*)(Cf + (size_t)row0 * DMODEL + colL) = o0;
                *(float2*)(Cf + (size_t)(row0 + 8) * DMODEL + colL) = o1;
            } else {              // out-proj: +resid -> fp32
                const float* r0 = resid + (size_t)row0 * DMODEL + colL;
                const float* r1 = resid + (size_t)(row0 + 8) * DMODEL + colL;
                v0 += r0[0]; v1 += r0[1]; v2 += r1[0]; v3 += r1[1];
                float2 o0 = {v0, v1}, o1 = {v2, v3};
                *(float2*)(Cf + (size_t)row0 * DMODEL + colL) = o0;
                *(float2*)(Cf + (size_t)(row0 + 8) * DMODEL + colL) = o1;
            }
        }
    }
}

// ---------------------------------------------------------------------------
// Fused causal sigmoid attention, fp16, 128-q-row tiles.
// QK 1-pass, PV 1-pass. Epilogue: ctx * u -> fp16 `a`.
// smem: Q 128 + P 128 + K 64 + V 64 rows of AST halfs = 55296 B
// ---------------------------------------------------------------------------
#define AST 72
#define ATTN_SMEM_B ((2 * 128 + 2 * 64) * AST * 2)

__global__ __launch_bounds__(256) void attn_kernel(
    const __half* __restrict__ qkv, const float* __restrict__ rpb,
    const float* __restrict__ u, __half* __restrict__ aout)
{
    extern __shared__ __half smb[];
    __half* Qs = smb;
    __half* Ps = Qs + 128 * AST;
    __half* Ks = Ps + 128 * AST;
    __half* Vs = Ks + 64 * AST;
    const uint32_t uQ = smem_u32(Qs), uP = smem_u32(Ps);
    const uint32_t uK = smem_u32(Ks), uV = smem_u32(Vs);

    const int qt = 15 - (int)blockIdx.x;     // big tiles first
    const int bh = blockIdx.y;
    const int b = bh >> 4, h = bh & 15;
    const float pbias = rpb[h];
    const int tid  = threadIdx.x;
    const int lane = tid & 31;
    const int gid  = lane >> 2, tig = lane & 3;
    const int wid  = tid >> 5;
    const int m0   = (wid & 3) * 32;
    const int n0   = (wid >> 2) * 32;
    const int lrow = lane & 15;
    const uint32_t lkb = (lane >> 4) * 16;

    const size_t base = (size_t)(b * SEQ) * N_QKV + h * 64;
    const __half* qb = qkv + base;
    const __half* kb = qkv + base + DMODEL;
    const __half* vb = qkv + base + 2 * DMODEL;

    // Q load: 128 rows x 64 cols
#pragma unroll
    for (int it = 0; it < 4; it++) {
        int idx = it * 256 + tid;
        int row = idx >> 3, seg = idx & 7;
        size_t off = (size_t)(qt * 128 + row) * N_QKV + seg * 8;
        *(uint4*)&Qs[row * AST + seg * 8] = *(const uint4*)(qb + off);
    }

    float cacc[2][4][4];
#pragma unroll
    for (int i = 0; i < 2; i++)
#pragma unroll
        for (int j = 0; j < 4; j++)
#pragma unroll
            for (int l = 0; l < 4; l++) cacc[i][j][l] = 0.f;

    const int krow = tid >> 2;
    const int kc16 = (tid & 3) * 16;
    const int vkp = tid & 31;
    const int vd0 = (tid >> 5) * 8;

    const int nkt = 2 * qt + 2;
    for (int kt = 0; kt < nkt; kt++) {
        uint4 kr0, kr1, va0, va1;
        {
            size_t off = (size_t)(kt * 64 + krow) * N_QKV + kc16;
            kr0 = *(const uint4*)(kb + off);
            kr1 = *(const uint4*)(kb + off + 8);
            size_t voff0 = (size_t)(kt * 64 + 2 * vkp) * N_QKV + vd0;
            va0 = *(const uint4*)(vb + voff0);
            va1 = *(const uint4*)(vb + voff0 + N_QKV);
        }
        __syncthreads();   // prev iter's reads of K/V/P done
        {
            *(uint4*)&Ks[krow * AST + kc16]     = kr0;
            *(uint4*)&Ks[krow * AST + kc16 + 8] = kr1;
            const uint32_t* a0w = (const uint32_t*)&va0;
            const uint32_t* a1w = (const uint32_t*)&va1;
#pragma unroll
            for (int i = 0; i < 4; i++) {
                uint32_t h_lo = __byte_perm(a0w[i], a1w[i], 0x5410);
                uint32_t h_hi = __byte_perm(a0w[i], a1w[i], 0x7632);
                int d = vd0 + 2 * i;
                *(uint32_t*)&Vs[d * AST + 2 * vkp]       = h_lo;
                *(uint32_t*)&Vs[(d + 1) * AST + 2 * vkp] = h_hi;
            }
        }
        __syncthreads();

        // S = Q @ K^T : 1 pass
        float sacc[2][4][4];
#pragma unroll
        for (int i = 0; i < 2; i++)
#pragma unroll
            for (int j = 0; j < 4; j++)
#pragma unroll
                for (int l = 0; l < 4; l++) sacc[i][j][l] = 0.f;
#pragma unroll
        for (int ks = 0; ks < 4; ks++) {
            const uint32_t kbo = ks * 32 + lkb;
            uint32_t k0[4], k1[4];
            ldm_x4(k0, uK + (n0 + lrow) * (AST * 2) + kbo);
            ldm_x4(k1, uK + (n0 + 16 + lrow) * (AST * 2) + kbo);
#pragma unroll
            for (int mf = 0; mf < 2; mf++) {
                uint32_t qh[4];
                ldm_x4(qh, uQ + (m0 + mf * 16 + lrow) * (AST * 2) + kbo);
                mma16(sacc[mf][0], qh, k0[0], k0[2]);
                mma16(sacc[mf][1], qh, k0[1], k0[3]);
                mma16(sacc[mf][2], qh, k1[0], k1[2]);
                mma16(sacc[mf][3], qh, k1[1], k1[3]);
            }
        }

        // sigmoid + causal mask -> P (fp16, [m][kseq])
        const bool diag = (kt >= 2 * qt);
#pragma unroll
        for (int mf = 0; mf < 2; mf++) {
            int rl0 = m0 + mf * 16 + gid;
            int rg0 = qt * 128 + rl0;
#pragma unroll
            for (int nf = 0; nf < 4; nf++) {
                int cl = n0 + nf * 8 + 2 * tig;
                int cg = kt * 64 + cl;
                float s0 = sacc[mf][nf][0] * 0.125f + pbias;
                float s1 = sacc[mf][nf][1] * 0.125f + pbias;
                float s2 = sacc[mf][nf][2] * 0.125f + pbias;
                float s3 = sacc[mf][nf][3] * 0.125f + pbias;
                float p0 = __fdividef(1.f, 1.f + __expf(-s0));
                float p1 = __fdividef(1.f, 1.f + __expf(-s1));
                float p2 = __fdividef(1.f, 1.f + __expf(-s2));
                float p3 = __fdividef(1.f, 1.f + __expf(-s3));
                if (diag) {
                    if (cg > rg0)         p0 = 0.f;
                    if (cg + 1 > rg0)     p1 = 0.f;
                    if (cg > rg0 + 8)     p2 = 0.f;
                    if (cg + 1 > rg0 + 8) p3 = 0.f;
                }
                __half2 a;
                a.x = __float2half_rn(p0); a.y = __float2half_rn(p1);
                *(__half2*)&Ps[rl0 * AST + cl] = a;
                a.x = __float2half_rn(p2); a.y = __float2half_rn(p3);
                *(__half2*)&Ps[(rl0 + 8) * AST + cl] = a;
            }
        }
        __syncthreads();

        // ctx += P @ V : 1 pass
#pragma unroll
        for (int ks = 0; ks < 4; ks++) {
            const uint32_t kbo = ks * 32 + lkb;
            uint32_t v0[4], v1[4];
            ldm_x4(v0, uV + (n0 + lrow) * (AST * 2) + kbo);
            ldm_x4(v1, uV + (n0 + 16 + lrow) * (AST * 2) + kbo);
#pragma unroll
            for (int mf = 0; mf < 2; mf++) {
                uint32_t ph[4];
                ldm_x4(ph, uP + (m0 + mf * 16 + lrow) * (AST * 2) + kbo);
                mma16(cacc[mf][0], ph, v0[0], v0[2]);
                mma16(cacc[mf][1], ph, v0[1], v0[3]);
                mma16(cacc[mf][2], ph, v1[0], v1[2]);
                mma16(cacc[mf][3], ph, v1[1], v1[3]);
            }
        }
    }

    // epilogue: a = half(ctx * u), layout [b, s, h*64 + d]
#pragma unroll
    for (int mf = 0; mf < 2; mf++) {
#pragma unroll
        for (int nf = 0; nf < 4; nf++) {
            int row = qt * 128 + m0 + mf * 16 + gid;
            int col = h * 64 + n0 + nf * 8 + 2 * tig;
            size_t o0i = (size_t)(b * SEQ + row) * DMODEL + col;
            size_t o1i = (size_t)(b * SEQ + row + 8) * DMODEL + col;
            float2 u0 = *(const float2*)(u + o0i);
            float2 u1 = *(const float2*)(u + o1i);
            __half2 a0, a1;
            a0.x = __float2half_rn(cacc[mf][nf][0] * u0.x);
            a0.y = __float2half_rn(cacc[mf][nf][1] * u0.y);
            a1.x = __float2half_rn(cacc[mf][nf][2] * u1.x);
            a1.y = __float2half_rn(cacc[mf][nf][3] * u1.y);
            *(__half2*)(aout + o0i) = a0;
            *(__half2*)(aout + o1i) = a1;
        }
    }
}

// ---------------------------------------------------------------------------
extern "C" void kernel_launch(void* const* d_in, const int* in_sizes, int n_in,
                              void* d_out, int out_size)
{
    const float* x      = (const float*)d_in[0];
    // d_in[1] = attention_mask (causal tril) — applied analytically, unused
    const float* ln_g   = (const float*)d_in[2];
    const float* ln_b   = (const float*)d_in[3];
    const float* w_qkv  = (const float*)d_in[4];
    const float* b_qkv  = (const float*)d_in[5];
    const float* w_gate = (const float*)d_in[6];
    const float* b_gate = (const float*)d_in[7];
    const float* w_out  = (const float*)d_in[8];
    const float* b_out  = (const float*)d_in[9];
    const float* rpb    = (const float*)d_in[10];
    float* out = (float*)d_out;

    __half *xn, *wq, *wg, *wo, *a, *qkv;
    float *u;
    cudaGetSymbolAddress((void**)&xn,  g_xn);
    cudaGetSymbolAddress((void**)&wq,  g_wq);
    cudaGetSymbolAddress((void**)&wg,  g_wg);
    cudaGetSymbolAddress((void**)&wo,  g_wo);
    cudaGetSymbolAddress((void**)&qkv, g_qkv);
    cudaGetSymbolAddress((void**)&u,   g_u);
    cudaGetSymbolAddress((void**)&a,   g_a);

    cudaFuncSetAttribute(attn_kernel, cudaFuncAttributeMaxDynamicSharedMemorySize, ATTN_SMEM_B);
    cudaFuncSetAttribute(tgemm<0>, cudaFuncAttributeMaxDynamicSharedMemorySize, G_SMEM);
    cudaFuncSetAttribute(tgemm<1>, cudaFuncAttributeMaxDynamicSharedMemorySize, G_SMEM);

    whalf_kernel<<<dim3(N_QKV / 32, DMODEL / 32), dim3(32, 8)>>>(w_qkv, wq, DMODEL, N_QKV);
    whalf_kernel<<<dim3(DMODEL / 32, DMODEL / 32), dim3(32, 8)>>>(w_gate, wg, DMODEL, DMODEL);
    whalf_kernel<<<dim3(DMODEL / 32, DMODEL / 32), dim3(32, 8)>>>(w_out, wo, DMODEL, DMODEL);

    ln_half_kernel<<<R_TOT, 256>>>(x, ln_g, ln_b, xn);

    // fused qkv + gate GEMM (N = 4096), 1-pass
    tgemm<1><<<dim3((N_QKV + DMODEL) / 128, R_TOT / 128), 256, G_SMEM>>>(
        xn, wq, wg, b_qkv, b_gate, nullptr, u, qkv);

    attn_kernel<<<dim3(SEQ / 128, 2 * NHEAD), 256, ATTN_SMEM_B>>>(qkv, rpb, u, a);

    // out projection (+ residual), 1-pass
    tgemm<0><<<dim3(DMODEL / 128, R_TOT / 128), 256, G_SMEM>>>(
        a, wo, nullptr, b_out, nullptr, x, out, nullptr);
}